// round 1
// baseline (speedup 1.0000x reference)
#include <cuda_runtime.h>
#include <math.h>

#define BB 32
#define LC 1024
#define LQ 128
#define DD 256

// ---------------- scratch (no allocations allowed) ----------------
__device__ float g_E[(size_t)BB * LC * LQ];        // exp(S)  (16 MB)
__device__ float g_T[(size_t)BB * LQ * DD];        // Sc^T @ C (4 MB)
__device__ float g_cdot[BB * LC];
__device__ float g_qdotb[BB * LQ];
__device__ float g_rowinv[BB * LC];
__device__ float g_colinv[BB * LQ];

// ---------------- k_dots: cdot[b,c]=C.w1 ; qdotb[b,q]=Q.w2+bias ----------------
__global__ void k_dots(const float* __restrict__ C, const float* __restrict__ Q,
                       const float* __restrict__ Ww, const float* __restrict__ Wb) {
    int warp = (blockIdx.x * blockDim.x + threadIdx.x) >> 5;
    int lane = threadIdx.x & 31;
    const int NC = BB * LC;
    const int NQ = BB * LQ;
    if (warp < NC) {
        const float4* row = (const float4*)(C + (size_t)warp * DD);
        const float4* w   = (const float4*)(Ww);           // w1
        float s = 0.f;
#pragma unroll
        for (int i = 0; i < 2; i++) {
            float4 v = row[lane + i * 32];
            float4 wv = w[lane + i * 32];
            s += v.x * wv.x + v.y * wv.y + v.z * wv.z + v.w * wv.w;
        }
#pragma unroll
        for (int o = 16; o; o >>= 1) s += __shfl_xor_sync(0xFFFFFFFFu, s, o);
        if (lane == 0) g_cdot[warp] = s;
    } else if (warp < NC + NQ) {
        int r = warp - NC;
        const float4* row = (const float4*)(Q + (size_t)r * DD);
        const float4* w   = (const float4*)(Ww + DD);      // w2
        float s = 0.f;
#pragma unroll
        for (int i = 0; i < 2; i++) {
            float4 v = row[lane + i * 32];
            float4 wv = w[lane + i * 32];
            s += v.x * wv.x + v.y * wv.y + v.z * wv.z + v.w * wv.w;
        }
#pragma unroll
        for (int o = 16; o; o >>= 1) s += __shfl_xor_sync(0xFFFFFFFFu, s, o);
        if (lane == 0) g_qdotb[r] = s + Wb[0];
    }
}

// ---------------- k1: E[b,c,q] = exp( (C.w3).Q^T + cdot + qdotb ) ----------------
// block: 128 c-rows x 128 q, 256 threads, 8x8 per thread, KC=16
__global__ __launch_bounds__(256) void k1_S(const float* __restrict__ C,
                                            const float* __restrict__ Qm,
                                            const float* __restrict__ Ww) {
    __shared__ float w3s[DD];
    __shared__ float As[16][132];
    __shared__ float Bs[16][132];
    const int tid = threadIdx.x;
    const int b = blockIdx.y;
    const int c0 = blockIdx.x * 128;
    w3s[tid] = Ww[2 * DD + tid];
    __syncthreads();

    const float* Cb = C + ((size_t)b * LC + c0) * DD;
    const float* Qb = Qm + (size_t)b * LQ * DD;
    const int tx = tid & 15, ty = tid >> 4;
    float acc[8][8];
#pragma unroll
    for (int i = 0; i < 8; i++)
#pragma unroll
        for (int j = 0; j < 8; j++) acc[i][j] = 0.f;

    for (int k0 = 0; k0 < DD; k0 += 16) {
#pragma unroll
        for (int it = 0; it < 2; it++) {
            int slot = it * 256 + tid;
            int row = slot >> 2, kv = slot & 3;
            float4 v = *(const float4*)(Cb + (size_t)row * DD + k0 + kv * 4);
            As[kv * 4 + 0][row] = v.x * w3s[k0 + kv * 4 + 0];
            As[kv * 4 + 1][row] = v.y * w3s[k0 + kv * 4 + 1];
            As[kv * 4 + 2][row] = v.z * w3s[k0 + kv * 4 + 2];
            As[kv * 4 + 3][row] = v.w * w3s[k0 + kv * 4 + 3];
            float4 q = *(const float4*)(Qb + (size_t)row * DD + k0 + kv * 4);
            Bs[kv * 4 + 0][row] = q.x;
            Bs[kv * 4 + 1][row] = q.y;
            Bs[kv * 4 + 2][row] = q.z;
            Bs[kv * 4 + 3][row] = q.w;
        }
        __syncthreads();
#pragma unroll
        for (int kk = 0; kk < 16; kk++) {
            float a[8], bb[8];
            *(float4*)(a)     = *(float4*)&As[kk][ty * 8];
            *(float4*)(a + 4) = *(float4*)&As[kk][ty * 8 + 4];
            *(float4*)(bb)     = *(float4*)&Bs[kk][tx * 8];
            *(float4*)(bb + 4) = *(float4*)&Bs[kk][tx * 8 + 4];
#pragma unroll
            for (int i = 0; i < 8; i++)
#pragma unroll
                for (int j = 0; j < 8; j++) acc[i][j] = fmaf(a[i], bb[j], acc[i][j]);
        }
        __syncthreads();
    }

    float cd[8], qd[8];
#pragma unroll
    for (int i = 0; i < 8; i++) cd[i] = g_cdot[b * LC + c0 + ty * 8 + i];
#pragma unroll
    for (int j = 0; j < 8; j++) qd[j] = g_qdotb[b * LQ + tx * 8 + j];
    float* Eb = g_E + ((size_t)b * LC + c0) * LQ;
#pragma unroll
    for (int i = 0; i < 8; i++) {
        int row = ty * 8 + i;
#pragma unroll
        for (int jv = 0; jv < 2; jv++) {
            float4 v;
            v.x = expf(acc[i][jv * 4 + 0] + cd[i] + qd[jv * 4 + 0]);
            v.y = expf(acc[i][jv * 4 + 1] + cd[i] + qd[jv * 4 + 1]);
            v.z = expf(acc[i][jv * 4 + 2] + cd[i] + qd[jv * 4 + 2]);
            v.w = expf(acc[i][jv * 4 + 3] + cd[i] + qd[jv * 4 + 3]);
            *(float4*)&Eb[(size_t)row * LQ + tx * 8 + jv * 4] = v;
        }
    }
}

// ---------------- rowsum: 1/sum_q(qmask*E) per (b,c) ----------------
__global__ void k_rowsum(const int* __restrict__ qmask) {
    int warp = (blockIdx.x * 256 + threadIdx.x) >> 5;   // row over B*LC
    int lane = threadIdx.x & 31;
    int b = warp >> 10;
    float4 e = ((const float4*)(g_E + (size_t)warp * LQ))[lane];
    int4 m = ((const int4*)(qmask + b * LQ))[lane];
    float s = (m.x ? e.x : 0.f) + (m.y ? e.y : 0.f) + (m.z ? e.z : 0.f) + (m.w ? e.w : 0.f);
#pragma unroll
    for (int o = 16; o; o >>= 1) s += __shfl_xor_sync(0xFFFFFFFFu, s, o);
    if (lane == 0) g_rowinv[warp] = 1.f / s;
}

// ---------------- colsum: 1/sum_c(cmask*E) per (b,q) ----------------
__global__ void k_colsum(const int* __restrict__ cmask) {
    __shared__ float cm[LC];
    __shared__ float part[256];
    int b = blockIdx.x, tid = threadIdx.x;
    for (int i = tid; i < LC; i += 256) cm[i] = (float)cmask[b * LC + i];
    __syncthreads();
    int q = tid & 127, h = tid >> 7;
    const float* Eb = g_E + (size_t)b * LC * LQ;
    float s = 0.f;
    for (int c = h * 512; c < h * 512 + 512; c++) s += Eb[(size_t)c * LQ + q] * cm[c];
    part[tid] = s;
    __syncthreads();
    if (h == 0) g_colinv[b * LQ + q] = 1.f / (part[q] + part[128 + q]);
}

// ---------------- k2: T[b,q,d] = colinv[q] * sum_k cmask[k]*E[k,q]*C[k,d] ----------------
// block: 64 q x 64 d, 256 threads, 4x4 per thread, K=1024 in KC=16 chunks
__global__ __launch_bounds__(256) void k2_T(const float* __restrict__ C,
                                            const int* __restrict__ cmask) {
    __shared__ float cm[LC];
    __shared__ float As[16][68];
    __shared__ float Bs[16][68];
    const int b = blockIdx.y, tid = threadIdx.x;
    const int q0 = (blockIdx.x >> 2) * 64;
    const int d0 = (blockIdx.x & 3) * 64;
    for (int i = tid; i < LC; i += 256) cm[i] = (float)cmask[b * LC + i];
    __syncthreads();

    const float* Eb = g_E + (size_t)b * LC * LQ;
    const float* Cb = C + (size_t)b * LC * DD;
    const int tx = tid & 15, ty = tid >> 4;
    const int lk = tid >> 4, xv = tid & 15;
    float acc[4][4];
#pragma unroll
    for (int i = 0; i < 4; i++)
#pragma unroll
        for (int j = 0; j < 4; j++) acc[i][j] = 0.f;

    for (int k0 = 0; k0 < LC; k0 += 16) {
        float cf = cm[k0 + lk];
        float4 e = *(const float4*)(Eb + (size_t)(k0 + lk) * LQ + q0 + xv * 4);
        As[lk][xv * 4 + 0] = e.x * cf;
        As[lk][xv * 4 + 1] = e.y * cf;
        As[lk][xv * 4 + 2] = e.z * cf;
        As[lk][xv * 4 + 3] = e.w * cf;
        float4 cv = *(const float4*)(Cb + (size_t)(k0 + lk) * DD + d0 + xv * 4);
        Bs[lk][xv * 4 + 0] = cv.x;
        Bs[lk][xv * 4 + 1] = cv.y;
        Bs[lk][xv * 4 + 2] = cv.z;
        Bs[lk][xv * 4 + 3] = cv.w;
        __syncthreads();
#pragma unroll
        for (int k = 0; k < 16; k++) {
            float a[4], bb[4];
            *(float4*)a = *(float4*)&As[k][ty * 4];
            *(float4*)bb = *(float4*)&Bs[k][tx * 4];
#pragma unroll
            for (int i = 0; i < 4; i++)
#pragma unroll
                for (int j = 0; j < 4; j++) acc[i][j] = fmaf(a[i], bb[j], acc[i][j]);
        }
        __syncthreads();
    }
#pragma unroll
    for (int i = 0; i < 4; i++) {
        int qg = q0 + ty * 4 + i;
        float ci = g_colinv[b * LQ + qg];
        float4 v = {acc[i][0] * ci, acc[i][1] * ci, acc[i][2] * ci, acc[i][3] * ci};
        *(float4*)&g_T[((size_t)b * LQ + qg) * DD + d0 + tx * 4] = v;
    }
}

// ---------------- k3: A/Bm rows + fused epilogue ----------------
// grid.x: mt(16) * 8 ; dte<4 -> [Q] part (writes C, A, C*A), else [T] part (writes C*Bm)
__global__ __launch_bounds__(256) void k3_final(const float* __restrict__ C,
                                                const float* __restrict__ Qm,
                                                const int* __restrict__ qmask,
                                                float* __restrict__ out) {
    __shared__ float qmf[LQ];
    __shared__ float ri[64];
    __shared__ float As[16][68];
    __shared__ float Bs[16][68];
    const int b = blockIdx.y, tid = threadIdx.x;
    const int mt = blockIdx.x >> 3;
    const int dte = blockIdx.x & 7;
    const bool Apart = dte < 4;
    const int d0 = (dte & 3) * 64;
    const int c0 = mt * 64;
    if (tid < LQ) qmf[tid] = (float)qmask[b * LQ + tid];
    if (tid < 64) ri[tid] = g_rowinv[b * LC + c0 + tid];
    __syncthreads();

    const float* Eb = g_E + ((size_t)b * LC + c0) * LQ;
    const float* Bsrc = Apart ? (Qm + (size_t)b * LQ * DD) : (g_T + (size_t)b * LQ * DD);
    const int tx = tid & 15, ty = tid >> 4;
    float acc[4][4];
#pragma unroll
    for (int i = 0; i < 4; i++)
#pragma unroll
        for (int j = 0; j < 4; j++) acc[i][j] = 0.f;

    for (int k0 = 0; k0 < LQ; k0 += 16) {
        {   // A tile: Sq[m,k] = E * qmask * rowinv, stored transposed
            int m = tid >> 2, kv = tid & 3;
            float r = ri[m];
            float4 e = *(const float4*)(Eb + (size_t)m * LQ + k0 + kv * 4);
            As[kv * 4 + 0][m] = e.x * qmf[k0 + kv * 4 + 0] * r;
            As[kv * 4 + 1][m] = e.y * qmf[k0 + kv * 4 + 1] * r;
            As[kv * 4 + 2][m] = e.z * qmf[k0 + kv * 4 + 2] * r;
            As[kv * 4 + 3][m] = e.w * qmf[k0 + kv * 4 + 3] * r;
        }
        {   // B tile: Q or T rows
            int lk = tid >> 4, dv = tid & 15;
            float4 v = *(const float4*)(Bsrc + (size_t)(k0 + lk) * DD + d0 + dv * 4);
            Bs[lk][dv * 4 + 0] = v.x;
            Bs[lk][dv * 4 + 1] = v.y;
            Bs[lk][dv * 4 + 2] = v.z;
            Bs[lk][dv * 4 + 3] = v.w;
        }
        __syncthreads();
#pragma unroll
        for (int k = 0; k < 16; k++) {
            float a[4], bb[4];
            *(float4*)a = *(float4*)&As[k][ty * 4];
            *(float4*)bb = *(float4*)&Bs[k][tx * 4];
#pragma unroll
            for (int i = 0; i < 4; i++)
#pragma unroll
                for (int j = 0; j < 4; j++) acc[i][j] = fmaf(a[i], bb[j], acc[i][j]);
        }
        __syncthreads();
    }

#pragma unroll
    for (int i = 0; i < 4; i++) {
        int cg = c0 + ty * 4 + i;
        float4 Cv = *(const float4*)(C + ((size_t)b * LC + cg) * DD + d0 + tx * 4);
        float* ob = out + ((size_t)b * LC + cg) * (4 * DD);
        float4 av = {acc[i][0], acc[i][1], acc[i][2], acc[i][3]};
        float4 ca = {Cv.x * av.x, Cv.y * av.y, Cv.z * av.z, Cv.w * av.w};
        if (Apart) {
            *(float4*)(ob + d0 + tx * 4) = Cv;                  // seg0: C
            *(float4*)(ob + DD + d0 + tx * 4) = av;             // seg1: A
            *(float4*)(ob + 2 * DD + d0 + tx * 4) = ca;         // seg2: C*A
        } else {
            *(float4*)(ob + 3 * DD + d0 + tx * 4) = ca;         // seg3: C*Bm
        }
    }
}

extern "C" void kernel_launch(void* const* d_in, const int* in_sizes, int n_in,
                              void* d_out, int out_size) {
    const float* C     = (const float*)d_in[0];
    const float* Q     = (const float*)d_in[1];
    const int*   cmask = (const int*)d_in[2];
    const int*   qmask = (const int*)d_in[3];
    const float* Ww    = (const float*)d_in[4];
    const float* Wb    = (const float*)d_in[5];
    float* out = (float*)d_out;

    k_dots<<<4608, 256>>>(C, Q, Ww, Wb);                 // 36864 warps
    k1_S<<<dim3(8, BB), 256>>>(C, Q, Ww);
    k_rowsum<<<4096, 256>>>(qmask);                      // 32768 warps
    k_colsum<<<BB, 256>>>(cmask);
    k2_T<<<dim3(8, BB), 256>>>(C, cmask);
    k3_final<<<dim3(128, BB), 256>>>(C, Q, qmask, out);
}

// round 3
// speedup vs baseline: 1.6762x; 1.6762x over previous
#include <cuda_runtime.h>
#include <cuda_bf16.h>
#include <cstdint>
#include <math.h>

#define BB 32
#define LC 1024
#define LQ 128
#define DD 256
#define STR 136            // smem tile row stride (bf16 elems); 272B rows -> ldmatrix conflict-free
#define STRB 272
#define TILEB (128 * STRB) // 34816 B per 128x128 bf16 tile
#define SMEM_SZ (4 * TILEB)

// ---------------- scratch ----------------
__device__ float g_E[(size_t)BB * LC * LQ];          // exp(S) fp32 (for sums)
__device__ float g_Tp[(size_t)BB * 4 * LQ * DD];     // k2 split-K partials
__device__ float g_cdot[BB * LC];
__device__ float g_qdotb[BB * LQ];
__device__ float g_rowinv[BB * LC];
__device__ float g_colinv[BB * LQ];
__device__ float g_colpart[BB * 16 * LQ];
// bf16 hi/lo operand arrays
__device__ __nv_bfloat16 g_eh[(size_t)BB * LC * LQ], g_el[(size_t)BB * LC * LQ];   // E
__device__ __nv_bfloat16 g_ch[(size_t)BB * LC * DD], g_cl[(size_t)BB * LC * DD];   // C*w3
__device__ __nv_bfloat16 g_cbh[(size_t)BB * LC * DD], g_cbl[(size_t)BB * LC * DD]; // raw C
__device__ __nv_bfloat16 g_qh[(size_t)BB * LQ * DD], g_ql[(size_t)BB * LQ * DD];   // raw Q
__device__ __nv_bfloat16 g_th[(size_t)BB * LQ * DD], g_tl[(size_t)BB * LQ * DD];   // T

// ---------------- warp-mma helpers (sm_80 baseline; no 'a' features) ----------------
__device__ __forceinline__ uint32_t smem_u32(const void* p) {
    uint32_t a;
    asm("{ .reg .u64 t; cvta.to.shared.u64 t, %1; cvt.u32.u64 %0, t; }" : "=r"(a) : "l"(p));
    return a;
}
__device__ __forceinline__ void ldsm4(uint32_t a, uint32_t* r) {
    asm volatile("ldmatrix.sync.aligned.m8n8.x4.shared.b16 {%0,%1,%2,%3}, [%4];"
                 : "=r"(r[0]), "=r"(r[1]), "=r"(r[2]), "=r"(r[3]) : "r"(a));
}
__device__ __forceinline__ void ldsm4t(uint32_t a, uint32_t* r) {
    asm volatile("ldmatrix.sync.aligned.m8n8.x4.trans.shared.b16 {%0,%1,%2,%3}, [%4];"
                 : "=r"(r[0]), "=r"(r[1]), "=r"(r[2]), "=r"(r[3]) : "r"(a));
}
__device__ __forceinline__ void mmabf(float* c, const uint32_t* a, const uint32_t* b) {
    asm volatile(
        "mma.sync.aligned.m16n8k16.row.col.f32.bf16.bf16.f32 "
        "{%0,%1,%2,%3}, {%4,%5,%6,%7}, {%8,%9}, {%0,%1,%2,%3};"
        : "+f"(c[0]), "+f"(c[1]), "+f"(c[2]), "+f"(c[3])
        : "r"(a[0]), "r"(a[1]), "r"(a[2]), "r"(a[3]), "r"(b[0]), "r"(b[1]));
}
__device__ __forceinline__ void split2(float a, float b, uint32_t& h, uint32_t& l) {
    __nv_bfloat16 ha = __float2bfloat16(a), hb = __float2bfloat16(b);
    __nv_bfloat162 H; H.x = ha; H.y = hb; h = *(uint32_t*)&H;
    __nv_bfloat162 L;
    L.x = __float2bfloat16(a - __bfloat162float(ha));
    L.y = __float2bfloat16(b - __bfloat162float(hb));
    l = *(uint32_t*)&L;
}

// ---------------- k_dots ----------------
__global__ void k_dots(const float* __restrict__ C, const float* __restrict__ Q,
                       const float* __restrict__ Ww, const float* __restrict__ Wb) {
    int warp = (blockIdx.x * blockDim.x + threadIdx.x) >> 5;
    int lane = threadIdx.x & 31;
    const int NC = BB * LC, NQ = BB * LQ;
    if (warp < NC) {
        const float4* row = (const float4*)(C + (size_t)warp * DD);
        const float4* w = (const float4*)(Ww);
        float s = 0.f;
#pragma unroll
        for (int i = 0; i < 2; i++) {
            float4 v = row[lane + i * 32], wv = w[lane + i * 32];
            s += v.x * wv.x + v.y * wv.y + v.z * wv.z + v.w * wv.w;
        }
#pragma unroll
        for (int o = 16; o; o >>= 1) s += __shfl_xor_sync(0xFFFFFFFFu, s, o);
        if (lane == 0) g_cdot[warp] = s;
    } else if (warp < NC + NQ) {
        int r = warp - NC;
        const float4* row = (const float4*)(Q + (size_t)r * DD);
        const float4* w = (const float4*)(Ww + DD);
        float s = 0.f;
#pragma unroll
        for (int i = 0; i < 2; i++) {
            float4 v = row[lane + i * 32], wv = w[lane + i * 32];
            s += v.x * wv.x + v.y * wv.y + v.z * wv.z + v.w * wv.w;
        }
#pragma unroll
        for (int o = 16; o; o >>= 1) s += __shfl_xor_sync(0xFFFFFFFFu, s, o);
        if (lane == 0) g_qdotb[r] = s + Wb[0];
    }
}

// ---------------- preps ----------------
__global__ void k_prep_CQ(const float* __restrict__ C, const float* __restrict__ Ww) {
    size_t i = (size_t)blockIdx.x * 256 + threadIdx.x;    // 2M quads
    size_t e0 = i * 4;
    int d = (int)(e0 & (DD - 1));
    float4 v = *(const float4*)(C + e0);
    float4 w = *(const float4*)(Ww + 2 * DD + d);
    uint2 h, l;
    split2(v.x, v.y, h.x, l.x); split2(v.z, v.w, h.y, l.y);
    *(uint2*)(g_cbh + e0) = h; *(uint2*)(g_cbl + e0) = l;
    split2(v.x * w.x, v.y * w.y, h.x, l.x); split2(v.z * w.z, v.w * w.w, h.y, l.y);
    *(uint2*)(g_ch + e0) = h; *(uint2*)(g_cl + e0) = l;
}
__global__ void k_prep_Q(const float* __restrict__ Q) {
    size_t i = (size_t)blockIdx.x * 256 + threadIdx.x;    // 256K quads
    size_t e0 = i * 4;
    float4 v = *(const float4*)(Q + e0);
    uint2 h, l;
    split2(v.x, v.y, h.x, l.x); split2(v.z, v.w, h.y, l.y);
    *(uint2*)(g_qh + e0) = h; *(uint2*)(g_ql + e0) = l;
}

// ---------------- k1: E = exp((C.w3)Q^T + cdot + qdotb) via mma ----------------
// block: 128c x 128q, K=256 (2 chunks). A=CW3 [c][d] row-major, B=Q [q][d] (col-major KxN)
__global__ __launch_bounds__(256, 1) void k1_mma() {
    extern __shared__ char sm[];
    const uint32_t smb = smem_u32(sm);
    const uint32_t sAh = smb, sAl = smb + TILEB, sBh = smb + 2 * TILEB, sBl = smb + 3 * TILEB;
    const int tid = threadIdx.x, lane = tid & 31, wid = tid >> 5;
    const int wm = wid & 1, wn = wid >> 1;
    const int b = blockIdx.y, c0 = blockIdx.x * 128;

    float acc[4][4][4];
#pragma unroll
    for (int i = 0; i < 4; i++)
#pragma unroll
        for (int j = 0; j < 4; j++)
#pragma unroll
            for (int k = 0; k < 4; k++) acc[i][j][k] = 0.f;

    for (int kc = 0; kc < 2; kc++) {
        const uint4* Ash = (const uint4*)(g_ch + ((size_t)(b * LC + c0)) * DD + kc * 128);
        const uint4* Asl = (const uint4*)(g_cl + ((size_t)(b * LC + c0)) * DD + kc * 128);
        const uint4* Bsh = (const uint4*)(g_qh + ((size_t)b * LQ) * DD + kc * 128);
        const uint4* Bsl = (const uint4*)(g_ql + ((size_t)b * LQ) * DD + kc * 128);
        if (kc) __syncthreads();
#pragma unroll
        for (int i = 0; i < 8; i++) {
            int idx = i * 256 + tid, row = idx >> 4, cq = idx & 15;
            *(uint4*)(sm + (sAh - smb) + row * STRB + cq * 16) = Ash[row * 32 + cq];
            *(uint4*)(sm + (sAl - smb) + row * STRB + cq * 16) = Asl[row * 32 + cq];
            *(uint4*)(sm + (sBh - smb) + row * STRB + cq * 16) = Bsh[row * 32 + cq];
            *(uint4*)(sm + (sBl - smb) + row * STRB + cq * 16) = Bsl[row * 32 + cq];
        }
        __syncthreads();
#pragma unroll
        for (int ks = 0; ks < 8; ks++) {
            uint32_t ah[4][4], al[4][4], bh[4][2], bl[4][2];
            // A row-major: row=m, lanes: (lane&15)=m, (lane>>4)*8 = k-half
            uint32_t aro = (uint32_t)(lane & 15) * STRB + (ks * 16 + (lane >> 4) * 8) * 2;
#pragma unroll
            for (int mf = 0; mf < 4; mf++) {
                uint32_t ra = (uint32_t)(wm * 64 + mf * 16) * STRB + aro;
                ldsm4(sAh + ra, ah[mf]);
                ldsm4(sAl + ra, al[mf]);
            }
            // B from [n=q rows][k=d cols], non-trans: row=n, col=k
            uint32_t bro = (uint32_t)((lane & 7) + ((lane >> 4) * 8)) * STRB +
                           (ks * 16 + ((lane >> 3) & 1) * 8) * 2;
#pragma unroll
            for (int np = 0; np < 2; np++) {
                uint32_t r4[4];
                uint32_t rb = (uint32_t)(wn * 32 + np * 16) * STRB + bro;
                ldsm4(sBh + rb, r4);
                bh[np * 2][0] = r4[0]; bh[np * 2][1] = r4[1];
                bh[np * 2 + 1][0] = r4[2]; bh[np * 2 + 1][1] = r4[3];
                ldsm4(sBl + rb, r4);
                bl[np * 2][0] = r4[0]; bl[np * 2][1] = r4[1];
                bl[np * 2 + 1][0] = r4[2]; bl[np * 2 + 1][1] = r4[3];
            }
#pragma unroll
            for (int mf = 0; mf < 4; mf++)
#pragma unroll
                for (int nf = 0; nf < 4; nf++) {
                    mmabf(acc[mf][nf], ah[mf], bh[nf]);
                    mmabf(acc[mf][nf], al[mf], bh[nf]);
                    mmabf(acc[mf][nf], ah[mf], bl[nf]);
                }
        }
    }
    // epilogue: add dots, exp, emit fp32 + bf16 hi/lo
    const int g = lane >> 2, tig = lane & 3;
#pragma unroll
    for (int mf = 0; mf < 4; mf++) {
        int c = c0 + wm * 64 + mf * 16 + g;
        float cd0 = g_cdot[b * LC + c], cd1 = g_cdot[b * LC + c + 8];
        size_t r0 = ((size_t)b * LC + c) * LQ, r1 = r0 + 8 * LQ;
#pragma unroll
        for (int nf = 0; nf < 4; nf++) {
            int q = wn * 32 + nf * 8 + tig * 2;
            float qd0 = g_qdotb[b * LQ + q], qd1 = g_qdotb[b * LQ + q + 1];
            float e00 = expf(acc[mf][nf][0] + cd0 + qd0);
            float e01 = expf(acc[mf][nf][1] + cd0 + qd1);
            float e10 = expf(acc[mf][nf][2] + cd1 + qd0);
            float e11 = expf(acc[mf][nf][3] + cd1 + qd1);
            *(float2*)(g_E + r0 + q) = make_float2(e00, e01);
            *(float2*)(g_E + r1 + q) = make_float2(e10, e11);
            uint32_t h, l;
            split2(e00, e01, h, l);
            *(uint32_t*)(g_eh + r0 + q) = h; *(uint32_t*)(g_el + r0 + q) = l;
            split2(e10, e11, h, l);
            *(uint32_t*)(g_eh + r1 + q) = h; *(uint32_t*)(g_el + r1 + q) = l;
        }
    }
}

// ---------------- sums ----------------
__global__ void k_rowsum(const int* __restrict__ qmask) {
    int warp = (blockIdx.x * 256 + threadIdx.x) >> 5;
    int lane = threadIdx.x & 31;
    int b = warp >> 10;
    float4 e = ((const float4*)(g_E + (size_t)warp * LQ))[lane];
    int4 m = ((const int4*)(qmask + b * LQ))[lane];
    float s = (m.x ? e.x : 0.f) + (m.y ? e.y : 0.f) + (m.z ? e.z : 0.f) + (m.w ? e.w : 0.f);
#pragma unroll
    for (int o = 16; o; o >>= 1) s += __shfl_xor_sync(0xFFFFFFFFu, s, o);
    if (lane == 0) g_rowinv[warp] = 1.f / s;
}
__global__ void k_colsumP(const int* __restrict__ cmask) {
    __shared__ float cm[64];
    __shared__ float part[256];
    int b = blockIdx.y, cc = blockIdx.x, tid = threadIdx.x;
    if (tid < 64) cm[tid] = (float)cmask[b * LC + cc * 64 + tid];
    __syncthreads();
    int q = tid & 127, h = tid >> 7;
    const float* Eb = g_E + (size_t)b * LC * LQ + (size_t)(cc * 64 + h * 32) * LQ;
    float s = 0.f;
#pragma unroll 4
    for (int c = 0; c < 32; c++) s += Eb[(size_t)c * LQ + q] * cm[h * 32 + c];
    part[tid] = s;
    __syncthreads();
    if (h == 0) g_colpart[(b * 16 + cc) * LQ + q] = part[q] + part[128 + q];
}
__global__ void k_colsum2() {
    int b = blockIdx.x, q = threadIdx.x;
    float s = 0.f;
#pragma unroll
    for (int i = 0; i < 16; i++) s += g_colpart[(b * 16 + i) * LQ + q];
    g_colinv[b * LQ + q] = 1.f / s;
}

// ---------------- k2: Tp[ksp] = (cmask*E)^T @ C (split-K partials) ----------------
// block: 128q x 128d, K-slice 256c (2 chunks). A = E^T via trans-ldmatrix, B = C via trans.
__global__ __launch_bounds__(256, 1) void k2_mma(const int* __restrict__ cmask) {
    extern __shared__ char sm[];
    const uint32_t smb = smem_u32(sm);
    const uint32_t sAh = smb, sAl = smb + TILEB, sBh = smb + 2 * TILEB, sBl = smb + 3 * TILEB;
    const int tid = threadIdx.x, lane = tid & 31, wid = tid >> 5;
    const int wm = wid & 1, wn = wid >> 1;
    const int b = blockIdx.y;
    const int dt = blockIdx.x & 1, ksp = blockIdx.x >> 1;
    const int d0 = dt * 128;

    float acc[4][4][4];
#pragma unroll
    for (int i = 0; i < 4; i++)
#pragma unroll
        for (int j = 0; j < 4; j++)
#pragma unroll
            for (int k = 0; k < 4; k++) acc[i][j][k] = 0.f;

    for (int kc = 0; kc < 2; kc++) {
        int cb = ksp * 256 + kc * 128;
        const uint4* Ash = (const uint4*)(g_eh + ((size_t)(b * LC + cb)) * LQ);
        const uint4* Asl = (const uint4*)(g_el + ((size_t)(b * LC + cb)) * LQ);
        const uint4* Bsh = (const uint4*)(g_cbh + ((size_t)(b * LC + cb)) * DD + d0);
        const uint4* Bsl = (const uint4*)(g_cbl + ((size_t)(b * LC + cb)) * DD + d0);
        if (kc) __syncthreads();
        const uint4 zz = make_uint4(0, 0, 0, 0);
#pragma unroll
        for (int i = 0; i < 8; i++) {
            int idx = i * 256 + tid, row = idx >> 4, cq = idx & 15;
            int m = cmask[b * LC + cb + row];
            *(uint4*)(sm + (sAh - smb) + row * STRB + cq * 16) = m ? Ash[row * 16 + cq] : zz;
            *(uint4*)(sm + (sAl - smb) + row * STRB + cq * 16) = m ? Asl[row * 16 + cq] : zz;
            *(uint4*)(sm + (sBh - smb) + row * STRB + cq * 16) = Bsh[row * 32 + cq];
            *(uint4*)(sm + (sBl - smb) + row * STRB + cq * 16) = Bsl[row * 32 + cq];
        }
        __syncthreads();
#pragma unroll
        for (int ks = 0; ks < 8; ks++) {
            uint32_t ah[4][4], al[4][4], bh[4][2], bl[4][2];
            // A from [c=k rows][q=m cols] via trans:
            // lanes0-7:(k-lo,m-lo) 8-15:(k-lo,m-hi) 16-23:(k-hi,m-lo) 24-31:(k-hi,m-hi)
            uint32_t aro = (uint32_t)(ks * 16 + ((lane >> 4) * 8) + (lane & 7)) * STRB +
                           (((lane >> 3) & 1) * 8) * 2;
#pragma unroll
            for (int mf = 0; mf < 4; mf++) {
                uint32_t ra = aro + (uint32_t)(wm * 64 + mf * 16) * 2;
                ldsm4t(sAh + ra, ah[mf]);
                ldsm4t(sAl + ra, al[mf]);
            }
            // B from [c=k rows][d=n cols] via trans: row = k0..15, col-half by lane>>4
            uint32_t bro = (uint32_t)(ks * 16 + (lane & 15)) * STRB + ((lane >> 4) * 8) * 2;
#pragma unroll
            for (int np = 0; np < 2; np++) {
                uint32_t r4[4];
                uint32_t rb = bro + (uint32_t)(wn * 32 + np * 16) * 2;
                ldsm4t(sBh + rb, r4);
                bh[np * 2][0] = r4[0]; bh[np * 2][1] = r4[1];
                bh[np * 2 + 1][0] = r4[2]; bh[np * 2 + 1][1] = r4[3];
                ldsm4t(sBl + rb, r4);
                bl[np * 2][0] = r4[0]; bl[np * 2][1] = r4[1];
                bl[np * 2 + 1][0] = r4[2]; bl[np * 2 + 1][1] = r4[3];
            }
#pragma unroll
            for (int mf = 0; mf < 4; mf++)
#pragma unroll
                for (int nf = 0; nf < 4; nf++) {
                    mmabf(acc[mf][nf], ah[mf], bh[nf]);
                    mmabf(acc[mf][nf], al[mf], bh[nf]);
                    mmabf(acc[mf][nf], ah[mf], bl[nf]);
                }
        }
    }
    const int g = lane >> 2, tig = lane & 3;
    float* Tp = g_Tp + ((size_t)(b * 4 + ksp) * LQ) * DD;
#pragma unroll
    for (int mf = 0; mf < 4; mf++) {
        int q = wm * 64 + mf * 16 + g;
#pragma unroll
        for (int nf = 0; nf < 4; nf++) {
            int d = d0 + wn * 32 + nf * 8 + tig * 2;
            *(float2*)(Tp + (size_t)q * DD + d) = make_float2(acc[mf][nf][0], acc[mf][nf][1]);
            *(float2*)(Tp + (size_t)(q + 8) * DD + d) = make_float2(acc[mf][nf][2], acc[mf][nf][3]);
        }
    }
}

// ---------------- reduce partials -> T bf16 hi/lo ----------------
__global__ void k_t_reduce() {
    size_t i = (size_t)blockIdx.x * 256 + threadIdx.x;   // 262144 quads
    size_t e0 = i * 4;
    int b = (int)(e0 >> 15);
    int q = (int)((e0 >> 8) & 127);
    float ci = g_colinv[b * LQ + q];
    size_t base = ((size_t)(b * 4) * LQ + q) * DD + (e0 & 255);
    float4 s = *(const float4*)(g_Tp + base);
    float4 s1 = *(const float4*)(g_Tp + base + (size_t)LQ * DD);
    float4 s2 = *(const float4*)(g_Tp + base + 2 * (size_t)LQ * DD);
    float4 s3 = *(const float4*)(g_Tp + base + 3 * (size_t)LQ * DD);
    s.x = (s.x + s1.x + s2.x + s3.x) * ci;
    s.y = (s.y + s1.y + s2.y + s3.y) * ci;
    s.z = (s.z + s1.z + s2.z + s3.z) * ci;
    s.w = (s.w + s1.w + s2.w + s3.w) * ci;
    uint2 h, l;
    split2(s.x, s.y, h.x, l.x); split2(s.z, s.w, h.y, l.y);
    *(uint2*)(g_th + e0) = h; *(uint2*)(g_tl + e0) = l;
}

// ---------------- k3: A = Sq@Q, Bm = Sq@T, fused epilogue ----------------
// block: 128c x 128d; A = E [c][q] (qmaskE; rowinv in epilogue), B = Q or T [q][d] (qmask rows)
__global__ __launch_bounds__(256, 1) void k3_mma(const float* __restrict__ Cp,
                                                 const int* __restrict__ qmask,
                                                 float* __restrict__ out) {
    extern __shared__ char sm[];
    const uint32_t smb = smem_u32(sm);
    const uint32_t sAh = smb, sAl = smb + TILEB, sBh = smb + 2 * TILEB, sBl = smb + 3 * TILEB;
    const int tid = threadIdx.x, lane = tid & 31, wid = tid >> 5;
    const int wm = wid & 1, wn = wid >> 1;
    const int b = blockIdx.y;
    const int ct = blockIdx.x >> 2, dt = (blockIdx.x >> 1) & 1, part = blockIdx.x & 1;
    const int c0 = ct * 128, d0 = dt * 128;

    const uint4* Ash = (const uint4*)(g_eh + ((size_t)(b * LC + c0)) * LQ);
    const uint4* Asl = (const uint4*)(g_el + ((size_t)(b * LC + c0)) * LQ);
    const uint4* Bsh = (const uint4*)((part ? g_th : g_qh) + ((size_t)b * LQ) * DD + d0);
    const uint4* Bsl = (const uint4*)((part ? g_tl : g_ql) + ((size_t)b * LQ) * DD + d0);
    const uint4 zz = make_uint4(0, 0, 0, 0);
#pragma unroll
    for (int i = 0; i < 8; i++) {
        int idx = i * 256 + tid, row = idx >> 4, cq = idx & 15;
        int m = qmask[b * LQ + row];   // B rows are q
        *(uint4*)(sm + (sAh - smb) + row * STRB + cq * 16) = Ash[row * 16 + cq];
        *(uint4*)(sm + (sAl - smb) + row * STRB + cq * 16) = Asl[row * 16 + cq];
        *(uint4*)(sm + (sBh - smb) + row * STRB + cq * 16) = m ? Bsh[row * 32 + cq] : zz;
        *(uint4*)(sm + (sBl - smb) + row * STRB + cq * 16) = m ? Bsl[row * 32 + cq] : zz;
    }
    __syncthreads();

    float acc[4][4][4];
#pragma unroll
    for (int i = 0; i < 4; i++)
#pragma unroll
        for (int j = 0; j < 4; j++)
#pragma unroll
            for (int k = 0; k < 4; k++) acc[i][j][k] = 0.f;

#pragma unroll
    for (int ks = 0; ks < 8; ks++) {
        uint32_t ah[4][4], al[4][4], bh[4][2], bl[4][2];
        // A row-major [c][q]
        uint32_t aro = (uint32_t)(lane & 15) * STRB + (ks * 16 + (lane >> 4) * 8) * 2;
#pragma unroll
        for (int mf = 0; mf < 4; mf++) {
            uint32_t ra = (uint32_t)(wm * 64 + mf * 16) * STRB + aro;
            ldsm4(sAh + ra, ah[mf]);
            ldsm4(sAl + ra, al[mf]);
        }
        // B row-major [q=k][d=n] -> trans
        uint32_t bro = (uint32_t)(ks * 16 + (lane & 15)) * STRB + ((lane >> 4) * 8) * 2;
#pragma unroll
        for (int np = 0; np < 2; np++) {
            uint32_t r4[4];
            uint32_t rb = bro + (uint32_t)(wn * 32 + np * 16) * 2;
            ldsm4t(sBh + rb, r4);
            bh[np * 2][0] = r4[0]; bh[np * 2][1] = r4[1];
            bh[np * 2 + 1][0] = r4[2]; bh[np * 2 + 1][1] = r4[3];
            ldsm4t(sBl + rb, r4);
            bl[np * 2][0] = r4[0]; bl[np * 2][1] = r4[1];
            bl[np * 2 + 1][0] = r4[2]; bl[np * 2 + 1][1] = r4[3];
        }
#pragma unroll
        for (int mf = 0; mf < 4; mf++)
#pragma unroll
            for (int nf = 0; nf < 4; nf++) {
                mmabf(acc[mf][nf], ah[mf], bh[nf]);
                mmabf(acc[mf][nf], al[mf], bh[nf]);
                mmabf(acc[mf][nf], ah[mf], bl[nf]);
            }
    }

    const int g = lane >> 2, tig = lane & 3;
#pragma unroll
    for (int mf = 0; mf < 4; mf++) {
        int c = c0 + wm * 64 + mf * 16 + g;
        float r0 = g_rowinv[b * LC + c], r1 = g_rowinv[b * LC + c + 8];
        const float* C0 = Cp + ((size_t)(b * LC + c)) * DD;
        const float* C1 = C0 + 8 * DD;
        float* o0 = out + ((size_t)(b * LC + c)) * (4 * DD);
        float* o1 = o0 + (size_t)8 * 4 * DD;
#pragma unroll
        for (int nf = 0; nf < 4; nf++) {
            int d = d0 + wn * 32 + nf * 8 + tig * 2;
            float2 cv0 = *(const float2*)(C0 + d);
            float2 cv1 = *(const float2*)(C1 + d);
            float a00 = acc[mf][nf][0] * r0, a01 = acc[mf][nf][1] * r0;
            float a10 = acc[mf][nf][2] * r1, a11 = acc[mf][nf][3] * r1;
            if (part == 0) {
                *(float2*)(o0 + d) = cv0;
                *(float2*)(o1 + d) = cv1;
                *(float2*)(o0 + DD + d) = make_float2(a00, a01);
                *(float2*)(o1 + DD + d) = make_float2(a10, a11);
                *(float2*)(o0 + 2 * DD + d) = make_float2(cv0.x * a00, cv0.y * a01);
                *(float2*)(o1 + 2 * DD + d) = make_float2(cv1.x * a10, cv1.y * a11);
            } else {
                *(float2*)(o0 + 3 * DD + d) = make_float2(cv0.x * a00, cv0.y * a01);
                *(float2*)(o1 + 3 * DD + d) = make_float2(cv1.x * a10, cv1.y * a11);
            }
        }
    }
}

extern "C" void kernel_launch(void* const* d_in, const int* in_sizes, int n_in,
                              void* d_out, int out_size) {
    const float* C = (const float*)d_in[0];
    const float* Q = (const float*)d_in[1];
    const int* cmask = (const int*)d_in[2];
    const int* qmask = (const int*)d_in[3];
    const float* Ww = (const float*)d_in[4];
    const float* Wb = (const float*)d_in[5];
    float* out = (float*)d_out;

    static bool attr_set = false;
    if (!attr_set) {
        cudaFuncSetAttribute(k1_mma, cudaFuncAttributeMaxDynamicSharedMemorySize, SMEM_SZ);
        cudaFuncSetAttribute(k2_mma, cudaFuncAttributeMaxDynamicSharedMemorySize, SMEM_SZ);
        cudaFuncSetAttribute(k3_mma, cudaFuncAttributeMaxDynamicSharedMemorySize, SMEM_SZ);
        attr_set = true;
    }

    k_prep_CQ<<<8192, 256>>>(C, Ww);
    k_prep_Q<<<1024, 256>>>(Q);
    k_dots<<<4608, 256>>>(C, Q, Ww, Wb);
    k1_mma<<<dim3(8, BB), 256, SMEM_SZ>>>();
    k_rowsum<<<4096, 256>>>(qmask);
    k_colsumP<<<dim3(16, BB), 256>>>(cmask);
    k_colsum2<<<BB, LQ>>>();
    k2_mma<<<dim3(8, BB), 256, SMEM_SZ>>>(cmask);
    k_t_reduce<<<1024, 256>>>();
    k3_mma<<<dim3(32, BB), 256, SMEM_SZ>>>(C, qmask, out);
}

// round 4
// speedup vs baseline: 2.9051x; 1.7332x over previous
#include <cuda_runtime.h>
#include <cuda_fp16.h>
#include <cstdint>
#include <math.h>

#define BB 32
#define LC 1024
#define LQ 128
#define DD 256
#define STRB 272                 // smem row stride bytes (128 fp16 = 256B + 16 pad)
#define TILEB (128 * STRB)       // 34816 B per 128x128 fp16 tile

// smem layouts
#define SM_K1 (2 * TILEB + 512 + 512 + 2048 + 2048)
#define SM_K2 (2 * TILEB)
#define SM_K3 (3 * TILEB)

// ---------------- scratch ----------------
__device__ float g_Tp[(size_t)BB * 4 * LQ * DD];     // k2 split-K partials (fp32)
__device__ float g_cdot[BB * LC];
__device__ float g_qdotb[BB * LQ];
__device__ float g_rowinv[BB * LC];
__device__ float g_colinv[BB * LQ];
__device__ float g_colpart[BB * 8 * LQ];
// fp16 operands (single precision level — no lo arrays)
__device__ __half g_eh[(size_t)BB * LC * LQ];        // E
__device__ __half g_ch[(size_t)BB * LC * DD];        // C*w3
__device__ __half g_cbh[(size_t)BB * LC * DD];       // raw C
__device__ __half g_qh[(size_t)BB * LQ * DD];        // raw Q
__device__ __half g_th[(size_t)BB * LQ * DD];        // T

// ---------------- helpers ----------------
__device__ __forceinline__ uint32_t smem_u32(const void* p) {
    uint32_t a;
    asm("{ .reg .u64 t; cvta.to.shared.u64 t, %1; cvt.u32.u64 %0, t; }" : "=r"(a) : "l"(p));
    return a;
}
__device__ __forceinline__ void ldsm4(uint32_t a, uint32_t* r) {
    asm volatile("ldmatrix.sync.aligned.m8n8.x4.shared.b16 {%0,%1,%2,%3}, [%4];"
                 : "=r"(r[0]), "=r"(r[1]), "=r"(r[2]), "=r"(r[3]) : "r"(a));
}
__device__ __forceinline__ void ldsm4t(uint32_t a, uint32_t* r) {
    asm volatile("ldmatrix.sync.aligned.m8n8.x4.trans.shared.b16 {%0,%1,%2,%3}, [%4];"
                 : "=r"(r[0]), "=r"(r[1]), "=r"(r[2]), "=r"(r[3]) : "r"(a));
}
__device__ __forceinline__ void mmah(float* c, const uint32_t* a, const uint32_t* b) {
    asm volatile(
        "mma.sync.aligned.m16n8k16.row.col.f32.f16.f16.f32 "
        "{%0,%1,%2,%3}, {%4,%5,%6,%7}, {%8,%9}, {%0,%1,%2,%3};"
        : "+f"(c[0]), "+f"(c[1]), "+f"(c[2]), "+f"(c[3])
        : "r"(a[0]), "r"(a[1]), "r"(a[2]), "r"(a[3]), "r"(b[0]), "r"(b[1]));
}
__device__ __forceinline__ uint32_t h2pk(float a, float b) {
    __half2 t;
    t.x = __float2half_rn(a);
    t.y = __float2half_rn(b);
    return *(uint32_t*)&t;
}

// ---------------- prepC: cdot + C hi + (C*w3) hi ----------------
__global__ void k_prepC(const float* __restrict__ C, const float* __restrict__ Ww) {
    int warp = blockIdx.x * 8 + (threadIdx.x >> 5);   // over BB*LC rows
    int lane = threadIdx.x & 31;
    const float* row = C + (size_t)warp * DD;
    int d0 = lane * 4;
    float4 v1 = *(const float4*)(row + d0);
    float4 v2 = *(const float4*)(row + 128 + d0);
    float4 w1a = *(const float4*)(Ww + d0);
    float4 w1b = *(const float4*)(Ww + 128 + d0);
    float s = v1.x * w1a.x + v1.y * w1a.y + v1.z * w1a.z + v1.w * w1a.w
            + v2.x * w1b.x + v2.y * w1b.y + v2.z * w1b.z + v2.w * w1b.w;
#pragma unroll
    for (int o = 16; o; o >>= 1) s += __shfl_xor_sync(0xFFFFFFFFu, s, o);
    if (lane == 0) g_cdot[warp] = s;
    // raw C hi
    uint2 u;
    u.x = h2pk(v1.x, v1.y); u.y = h2pk(v1.z, v1.w);
    *(uint2*)(g_cbh + (size_t)warp * DD + d0) = u;
    u.x = h2pk(v2.x, v2.y); u.y = h2pk(v2.z, v2.w);
    *(uint2*)(g_cbh + (size_t)warp * DD + 128 + d0) = u;
    // C*w3 hi
    float4 w3a = *(const float4*)(Ww + 2 * DD + d0);
    float4 w3b = *(const float4*)(Ww + 2 * DD + 128 + d0);
    u.x = h2pk(v1.x * w3a.x, v1.y * w3a.y); u.y = h2pk(v1.z * w3a.z, v1.w * w3a.w);
    *(uint2*)(g_ch + (size_t)warp * DD + d0) = u;
    u.x = h2pk(v2.x * w3b.x, v2.y * w3b.y); u.y = h2pk(v2.z * w3b.z, v2.w * w3b.w);
    *(uint2*)(g_ch + (size_t)warp * DD + 128 + d0) = u;
}

// ---------------- prepQ: qdot+bias + Q hi ----------------
__global__ void k_prepQ(const float* __restrict__ Q, const float* __restrict__ Ww,
                        const float* __restrict__ Wb) {
    int warp = blockIdx.x * 8 + (threadIdx.x >> 5);   // over BB*LQ rows
    int lane = threadIdx.x & 31;
    const float* row = Q + (size_t)warp * DD;
    int d0 = lane * 4;
    float4 v1 = *(const float4*)(row + d0);
    float4 v2 = *(const float4*)(row + 128 + d0);
    float4 w2a = *(const float4*)(Ww + DD + d0);
    float4 w2b = *(const float4*)(Ww + DD + 128 + d0);
    float s = v1.x * w2a.x + v1.y * w2a.y + v1.z * w2a.z + v1.w * w2a.w
            + v2.x * w2b.x + v2.y * w2b.y + v2.z * w2b.z + v2.w * w2b.w;
#pragma unroll
    for (int o = 16; o; o >>= 1) s += __shfl_xor_sync(0xFFFFFFFFu, s, o);
    if (lane == 0) g_qdotb[warp] = s + Wb[0];
    uint2 u;
    u.x = h2pk(v1.x, v1.y); u.y = h2pk(v1.z, v1.w);
    *(uint2*)(g_qh + (size_t)warp * DD + d0) = u;
    u.x = h2pk(v2.x, v2.y); u.y = h2pk(v2.z, v2.w);
    *(uint2*)(g_qh + (size_t)warp * DD + 128 + d0) = u;
}

// ---------------- k1: E=exp((Cw3)Q^T + cdot + qdotb); fused row/col sums ----------------
// 512 thr; warp grid 4m x 4n; warp tile 32x32; K=256 in 2 chunks of 128
__global__ __launch_bounds__(512, 1) void k1_mma(const int* __restrict__ cmask,
                                                 const int* __restrict__ qmask) {
    extern __shared__ char sm[];
    const uint32_t smb = smem_u32(sm);
    const uint32_t sA = smb, sB = smb + TILEB;
    float* qmf = (float*)(sm + 2 * TILEB);
    float* cmf = qmf + 128;
    float* rs = cmf + 128;            // [4 wn][128 rows]
    float* cs = rs + 512;             // [16 wid][32]
    const int tid = threadIdx.x, lane = tid & 31, wid = tid >> 5;
    const int wm = wid & 3, wn = wid >> 2;
    const int b = blockIdx.y, ct = blockIdx.x, c0 = ct * 128;
    const int g = lane >> 2, tig = lane & 3;

    if (tid < 128) qmf[tid] = (float)qmask[b * LQ + tid];
    else if (tid < 256) cmf[tid - 128] = (float)cmask[b * LC + c0 + tid - 128];

    float acc[2][4][4];
#pragma unroll
    for (int i = 0; i < 2; i++)
#pragma unroll
        for (int j = 0; j < 4; j++)
#pragma unroll
            for (int k = 0; k < 4; k++) acc[i][j][k] = 0.f;

    for (int kc = 0; kc < 2; kc++) {
        const uint4* As = (const uint4*)(g_ch + ((size_t)(b * LC + c0)) * DD + kc * 128);
        const uint4* Bs = (const uint4*)(g_qh + ((size_t)b * LQ) * DD + kc * 128);
        if (kc) __syncthreads();
#pragma unroll
        for (int i = 0; i < 4; i++) {
            int idx = i * 512 + tid, row = idx >> 4, cq = idx & 15;
            *(uint4*)(sm + row * STRB + cq * 16) = As[row * 32 + cq];
            *(uint4*)(sm + TILEB + row * STRB + cq * 16) = Bs[row * 32 + cq];
        }
        __syncthreads();
#pragma unroll
        for (int ks = 0; ks < 8; ks++) {
            uint32_t ah[2][4], bh[4][2];
            uint32_t aro = (uint32_t)(lane & 15) * STRB + (ks * 16 + (lane >> 4) * 8) * 2;
#pragma unroll
            for (int mf = 0; mf < 2; mf++)
                ldsm4(sA + (uint32_t)(wm * 32 + mf * 16) * STRB + aro, ah[mf]);
            uint32_t bro = (uint32_t)((lane & 7) + ((lane >> 4) * 8)) * STRB +
                           (ks * 16 + ((lane >> 3) & 1) * 8) * 2;
#pragma unroll
            for (int np = 0; np < 2; np++) {
                uint32_t r4[4];
                ldsm4(sB + (uint32_t)(wn * 32 + np * 16) * STRB + bro, r4);
                bh[np * 2][0] = r4[0]; bh[np * 2][1] = r4[1];
                bh[np * 2 + 1][0] = r4[2]; bh[np * 2 + 1][1] = r4[3];
            }
#pragma unroll
            for (int mf = 0; mf < 2; mf++)
#pragma unroll
                for (int nf = 0; nf < 4; nf++) mmah(acc[mf][nf], ah[mf], bh[nf]);
        }
    }

    // epilogue: exp, write eh fp16, accumulate masked row/col partials
    float rpart[2][2] = {{0.f, 0.f}, {0.f, 0.f}};
    float cpart[4][2] = {{0.f, 0.f}, {0.f, 0.f}, {0.f, 0.f}, {0.f, 0.f}};
#pragma unroll
    for (int mf = 0; mf < 2; mf++) {
        int c = c0 + wm * 32 + mf * 16 + g;
        float cd0 = g_cdot[b * LC + c], cd1 = g_cdot[b * LC + c + 8];
        float cm0 = cmf[c - c0], cm1 = cmf[c - c0 + 8];
        size_t r0 = ((size_t)b * LC + c) * LQ, r1 = r0 + 8 * LQ;
#pragma unroll
        for (int nf = 0; nf < 4; nf++) {
            int q = wn * 32 + nf * 8 + tig * 2;
            float qd0 = g_qdotb[b * LQ + q], qd1 = g_qdotb[b * LQ + q + 1];
            float e00 = expf(acc[mf][nf][0] + cd0 + qd0);
            float e01 = expf(acc[mf][nf][1] + cd0 + qd1);
            float e10 = expf(acc[mf][nf][2] + cd1 + qd0);
            float e11 = expf(acc[mf][nf][3] + cd1 + qd1);
            *(uint32_t*)(g_eh + r0 + q) = h2pk(e00, e01);
            *(uint32_t*)(g_eh + r1 + q) = h2pk(e10, e11);
            float qm0 = qmf[q], qm1 = qmf[q + 1];
            rpart[mf][0] += e00 * qm0 + e01 * qm1;
            rpart[mf][1] += e10 * qm0 + e11 * qm1;
            cpart[nf][0] += e00 * cm0 + e10 * cm1;
            cpart[nf][1] += e01 * cm0 + e11 * cm1;
        }
    }
#pragma unroll
    for (int mf = 0; mf < 2; mf++)
#pragma unroll
        for (int rh = 0; rh < 2; rh++) {
            float v = rpart[mf][rh];
            v += __shfl_xor_sync(0xFFFFFFFFu, v, 1);
            v += __shfl_xor_sync(0xFFFFFFFFu, v, 2);
            if (tig == 0) rs[wn * 128 + wm * 32 + mf * 16 + g + rh * 8] = v;
        }
#pragma unroll
    for (int nf = 0; nf < 4; nf++)
#pragma unroll
        for (int j = 0; j < 2; j++) {
            float v = cpart[nf][j];
            v += __shfl_xor_sync(0xFFFFFFFFu, v, 4);
            v += __shfl_xor_sync(0xFFFFFFFFu, v, 8);
            v += __shfl_xor_sync(0xFFFFFFFFu, v, 16);
            if (lane < 4) cs[wid * 32 + nf * 8 + lane * 2 + j] = v;
        }
    __syncthreads();
    if (tid < 128) {
        float s = rs[tid] + rs[128 + tid] + rs[256 + tid] + rs[384 + tid];
        g_rowinv[b * LC + c0 + tid] = 1.f / s;
    } else if (tid < 256) {
        int q = tid - 128, wnq = q >> 5, ql = q & 31;
        float s = cs[(wnq * 4 + 0) * 32 + ql] + cs[(wnq * 4 + 1) * 32 + ql]
                + cs[(wnq * 4 + 2) * 32 + ql] + cs[(wnq * 4 + 3) * 32 + ql];
        g_colpart[(b * 8 + ct) * LQ + q] = s;
    }
}

__global__ void k_colsum2() {
    int b = blockIdx.x, q = threadIdx.x;
    float s = 0.f;
#pragma unroll
    for (int i = 0; i < 8; i++) s += g_colpart[(b * 8 + i) * LQ + q];
    g_colinv[b * LQ + q] = 1.f / s;
}

// ---------------- k2: Tp[ksp] = (cmask*E)^T @ C  (split-K fp32 partials) ----------------
__global__ __launch_bounds__(512, 1) void k2_mma(const int* __restrict__ cmask) {
    extern __shared__ char sm[];
    const uint32_t smb = smem_u32(sm);
    const uint32_t sA = smb, sB = smb + TILEB;
    const int tid = threadIdx.x, lane = tid & 31, wid = tid >> 5;
    const int wm = wid & 3, wn = wid >> 2;
    const int b = blockIdx.y;
    const int dt = blockIdx.x & 1, ksp = blockIdx.x >> 1;
    const int d0 = dt * 128;
    const int g = lane >> 2, tig = lane & 3;

    float acc[2][4][4];
#pragma unroll
    for (int i = 0; i < 2; i++)
#pragma unroll
        for (int j = 0; j < 4; j++)
#pragma unroll
            for (int k = 0; k < 4; k++) acc[i][j][k] = 0.f;

    for (int kc = 0; kc < 2; kc++) {
        int cb = ksp * 256 + kc * 128;
        const uint4* As = (const uint4*)(g_eh + ((size_t)(b * LC + cb)) * LQ);
        const uint4* Bs = (const uint4*)(g_cbh + ((size_t)(b * LC + cb)) * DD + d0);
        if (kc) __syncthreads();
        const uint4 zz = make_uint4(0, 0, 0, 0);
#pragma unroll
        for (int i = 0; i < 4; i++) {
            int idx = i * 512 + tid, row = idx >> 4, cq = idx & 15;
            int m = cmask[b * LC + cb + row];
            *(uint4*)(sm + row * STRB + cq * 16) = m ? As[row * 16 + cq] : zz;
            *(uint4*)(sm + TILEB + row * STRB + cq * 16) = Bs[row * 32 + cq];
        }
        __syncthreads();
#pragma unroll
        for (int ks = 0; ks < 8; ks++) {
            uint32_t ah[2][4], bh[4][2];
            uint32_t aro = (uint32_t)(ks * 16 + ((lane >> 4) * 8) + (lane & 7)) * STRB +
                           (((lane >> 3) & 1) * 8) * 2;
#pragma unroll
            for (int mf = 0; mf < 2; mf++)
                ldsm4t(sA + aro + (uint32_t)(wm * 32 + mf * 16) * 2, ah[mf]);
            uint32_t bro = (uint32_t)(ks * 16 + (lane & 15)) * STRB + ((lane >> 4) * 8) * 2;
#pragma unroll
            for (int np = 0; np < 2; np++) {
                uint32_t r4[4];
                ldsm4t(sB + bro + (uint32_t)(wn * 32 + np * 16) * 2, r4);
                bh[np * 2][0] = r4[0]; bh[np * 2][1] = r4[1];
                bh[np * 2 + 1][0] = r4[2]; bh[np * 2 + 1][1] = r4[3];
            }
#pragma unroll
            for (int mf = 0; mf < 2; mf++)
#pragma unroll
                for (int nf = 0; nf < 4; nf++) mmah(acc[mf][nf], ah[mf], bh[nf]);
        }
    }
    float* Tp = g_Tp + ((size_t)(b * 4 + ksp) * LQ) * DD;
#pragma unroll
    for (int mf = 0; mf < 2; mf++) {
        int q = wm * 32 + mf * 16 + g;
#pragma unroll
        for (int nf = 0; nf < 4; nf++) {
            int d = d0 + wn * 32 + nf * 8 + tig * 2;
            *(float2*)(Tp + (size_t)q * DD + d) = make_float2(acc[mf][nf][0], acc[mf][nf][1]);
            *(float2*)(Tp + (size_t)(q + 8) * DD + d) = make_float2(acc[mf][nf][2], acc[mf][nf][3]);
        }
    }
}

// ---------------- reduce partials -> T fp16 (x colinv) ----------------
__global__ void k_t_reduce() {
    size_t i = (size_t)blockIdx.x * 256 + threadIdx.x;
    size_t e0 = i * 4;
    int b = (int)(e0 >> 15);
    int q = (int)((e0 >> 8) & 127);
    float ci = g_colinv[b * LQ + q];
    size_t base = ((size_t)(b * 4) * LQ + q) * DD + (e0 & 255);
    float4 s = *(const float4*)(g_Tp + base);
    float4 s1 = *(const float4*)(g_Tp + base + (size_t)LQ * DD);
    float4 s2 = *(const float4*)(g_Tp + base + 2 * (size_t)LQ * DD);
    float4 s3 = *(const float4*)(g_Tp + base + 3 * (size_t)LQ * DD);
    uint2 u;
    u.x = h2pk((s.x + s1.x + s2.x + s3.x) * ci, (s.y + s1.y + s2.y + s3.y) * ci);
    u.y = h2pk((s.z + s1.z + s2.z + s3.z) * ci, (s.w + s1.w + s2.w + s3.w) * ci);
    *(uint2*)(g_th + e0) = u;
}

// ---------------- k3: A=Sq@Q and Bm=Sq@T in one block; fused 4-segment epilogue ----------------
__global__ __launch_bounds__(512, 1) void k3_mma(const float* __restrict__ Cp,
                                                 const int* __restrict__ qmask,
                                                 float* __restrict__ out) {
    extern __shared__ char sm[];
    const uint32_t smb = smem_u32(sm);
    const uint32_t sA = smb, sBq = smb + TILEB, sBt = smb + 2 * TILEB;
    const int tid = threadIdx.x, lane = tid & 31, wid = tid >> 5;
    const int wm = wid & 3, wn = wid >> 2;
    const int b = blockIdx.y;
    const int ct = blockIdx.x >> 1, dt = blockIdx.x & 1;
    const int c0 = ct * 128, d0 = dt * 128;
    const int g = lane >> 2, tig = lane & 3;

    const uint4* As = (const uint4*)(g_eh + ((size_t)(b * LC + c0)) * LQ);
    const uint4* Bq = (const uint4*)(g_qh + ((size_t)b * LQ) * DD + d0);
    const uint4* Bt = (const uint4*)(g_th + ((size_t)b * LQ) * DD + d0);
    const uint4 zz = make_uint4(0, 0, 0, 0);
#pragma unroll
    for (int i = 0; i < 4; i++) {
        int idx = i * 512 + tid, row = idx >> 4, cq = idx & 15;
        int m = qmask[b * LQ + row];
        *(uint4*)(sm + row * STRB + cq * 16) = As[row * 16 + cq];
        *(uint4*)(sm + TILEB + row * STRB + cq * 16) = m ? Bq[row * 32 + cq] : zz;
        *(uint4*)(sm + 2 * TILEB + row * STRB + cq * 16) = m ? Bt[row * 32 + cq] : zz;
    }
    __syncthreads();

    float accA[2][4][4], accB[2][4][4];
#pragma unroll
    for (int i = 0; i < 2; i++)
#pragma unroll
        for (int j = 0; j < 4; j++)
#pragma unroll
            for (int k = 0; k < 4; k++) { accA[i][j][k] = 0.f; accB[i][j][k] = 0.f; }

#pragma unroll
    for (int ks = 0; ks < 8; ks++) {
        uint32_t ah[2][4], bq[4][2], bt[4][2];
        uint32_t aro = (uint32_t)(lane & 15) * STRB + (ks * 16 + (lane >> 4) * 8) * 2;
#pragma unroll
        for (int mf = 0; mf < 2; mf++)
            ldsm4(sA + (uint32_t)(wm * 32 + mf * 16) * STRB + aro, ah[mf]);
        uint32_t bro = (uint32_t)(ks * 16 + (lane & 15)) * STRB + ((lane >> 4) * 8) * 2;
#pragma unroll
        for (int np = 0; np < 2; np++) {
            uint32_t r4[4];
            ldsm4t(sBq + bro + (uint32_t)(wn * 32 + np * 16) * 2, r4);
            bq[np * 2][0] = r4[0]; bq[np * 2][1] = r4[1];
            bq[np * 2 + 1][0] = r4[2]; bq[np * 2 + 1][1] = r4[3];
            ldsm4t(sBt + bro + (uint32_t)(wn * 32 + np * 16) * 2, r4);
            bt[np * 2][0] = r4[0]; bt[np * 2][1] = r4[1];
            bt[np * 2 + 1][0] = r4[2]; bt[np * 2 + 1][1] = r4[3];
        }
#pragma unroll
        for (int mf = 0; mf < 2; mf++)
#pragma unroll
            for (int nf = 0; nf < 4; nf++) {
                mmah(accA[mf][nf], ah[mf], bq[nf]);
                mmah(accB[mf][nf], ah[mf], bt[nf]);
            }
    }

#pragma unroll
    for (int mf = 0; mf < 2; mf++) {
        int c = c0 + wm * 32 + mf * 16 + g;
        float r0 = g_rowinv[b * LC + c], r1 = g_rowinv[b * LC + c + 8];
        const float* C0 = Cp + ((size_t)(b * LC + c)) * DD;
        const float* C1 = C0 + 8 * DD;
        float* o0 = out + ((size_t)(b * LC + c)) * (4 * DD);
        float* o1 = o0 + (size_t)8 * 4 * DD;
#pragma unroll
        for (int nf = 0; nf < 4; nf++) {
            int d = d0 + wn * 32 + nf * 8 + tig * 2;
            float2 cv0 = *(const float2*)(C0 + d);
            float2 cv1 = *(const float2*)(C1 + d);
            float a00 = accA[mf][nf][0] * r0, a01 = accA[mf][nf][1] * r0;
            float a10 = accA[mf][nf][2] * r1, a11 = accA[mf][nf][3] * r1;
            float b00 = accB[mf][nf][0] * r0, b01 = accB[mf][nf][1] * r0;
            float b10 = accB[mf][nf][2] * r1, b11 = accB[mf][nf][3] * r1;
            *(float2*)(o0 + d) = cv0;
            *(float2*)(o1 + d) = cv1;
            *(float2*)(o0 + DD + d) = make_float2(a00, a01);
            *(float2*)(o1 + DD + d) = make_float2(a10, a11);
            *(float2*)(o0 + 2 * DD + d) = make_float2(cv0.x * a00, cv0.y * a01);
            *(float2*)(o1 + 2 * DD + d) = make_float2(cv1.x * a10, cv1.y * a11);
            *(float2*)(o0 + 3 * DD + d) = make_float2(cv0.x * b00, cv0.y * b01);
            *(float2*)(o1 + 3 * DD + d) = make_float2(cv1.x * b10, cv1.y * b11);
        }
    }
}

extern "C" void kernel_launch(void* const* d_in, const int* in_sizes, int n_in,
                              void* d_out, int out_size) {
    const float* C = (const float*)d_in[0];
    const float* Q = (const float*)d_in[1];
    const int* cmask = (const int*)d_in[2];
    const int* qmask = (const int*)d_in[3];
    const float* Ww = (const float*)d_in[4];
    const float* Wb = (const float*)d_in[5];
    float* out = (float*)d_out;

    static bool attr_set = false;
    if (!attr_set) {
        cudaFuncSetAttribute(k1_mma, cudaFuncAttributeMaxDynamicSharedMemorySize, SM_K1);
        cudaFuncSetAttribute(k2_mma, cudaFuncAttributeMaxDynamicSharedMemorySize, SM_K2);
        cudaFuncSetAttribute(k3_mma, cudaFuncAttributeMaxDynamicSharedMemorySize, SM_K3);
        attr_set = true;
    }

    k_prepC<<<4096, 256>>>(C, Ww);          // 32768 row-warps
    k_prepQ<<<512, 256>>>(Q, Ww, Wb);       // 4096 row-warps
    k1_mma<<<dim3(8, BB), 512, SM_K1>>>(cmask, qmask);
    k_colsum2<<<BB, LQ>>>();
    k2_mma<<<dim3(8, BB), 512, SM_K2>>>(cmask);
    k_t_reduce<<<1024, 256>>>();
    k3_mma<<<dim3(16, BB), 512, SM_K3>>>(C, qmask, out);
}

// round 5
// speedup vs baseline: 3.1242x; 1.0754x over previous
#include <cuda_runtime.h>
#include <cuda_fp16.h>
#include <cstdint>
#include <math.h>

#define BB 32
#define LC 1024
#define LQ 128
#define DD 256
#define STRB 272                 // smem row stride bytes (128 fp16 = 256B + 16 pad)
#define TILEB (128 * STRB)       // 34816 B per 128x128 fp16 tile

#define SM_K1 (4 * TILEB + 512 + 512 + 2048 + 2048)   // double-buffered A+B
#define SM_K2 (4 * TILEB)
#define SM_K3 (3 * TILEB)

// ---------------- scratch ----------------
__device__ float g_Tp[(size_t)BB * 2 * LQ * DD];     // k2 split-K partials (fp32)
__device__ float g_cdot[BB * LC];
__device__ float g_qdotb[BB * LQ];
__device__ float g_rowinv[BB * LC];
__device__ float g_colpart[BB * 8 * LQ];
__device__ __half g_eh[(size_t)BB * LC * LQ];        // E
__device__ __half g_ch[(size_t)BB * LC * DD];        // C*w3
__device__ __half g_cbh[(size_t)BB * LC * DD];       // raw C
__device__ __half g_qh[(size_t)BB * LQ * DD];        // raw Q
__device__ __half g_th[(size_t)BB * LQ * DD];        // T

// ---------------- helpers ----------------
__device__ __forceinline__ uint32_t smem_u32(const void* p) {
    uint32_t a;
    asm("{ .reg .u64 t; cvta.to.shared.u64 t, %1; cvt.u32.u64 %0, t; }" : "=r"(a) : "l"(p));
    return a;
}
__device__ __forceinline__ void ldsm4(uint32_t a, uint32_t* r) {
    asm volatile("ldmatrix.sync.aligned.m8n8.x4.shared.b16 {%0,%1,%2,%3}, [%4];"
                 : "=r"(r[0]), "=r"(r[1]), "=r"(r[2]), "=r"(r[3]) : "r"(a));
}
__device__ __forceinline__ void ldsm4t(uint32_t a, uint32_t* r) {
    asm volatile("ldmatrix.sync.aligned.m8n8.x4.trans.shared.b16 {%0,%1,%2,%3}, [%4];"
                 : "=r"(r[0]), "=r"(r[1]), "=r"(r[2]), "=r"(r[3]) : "r"(a));
}
__device__ __forceinline__ void mmah(float* c, const uint32_t* a, const uint32_t* b) {
    asm volatile(
        "mma.sync.aligned.m16n8k16.row.col.f32.f16.f16.f32 "
        "{%0,%1,%2,%3}, {%4,%5,%6,%7}, {%8,%9}, {%0,%1,%2,%3};"
        : "+f"(c[0]), "+f"(c[1]), "+f"(c[2]), "+f"(c[3])
        : "r"(a[0]), "r"(a[1]), "r"(a[2]), "r"(a[3]), "r"(b[0]), "r"(b[1]));
}
__device__ __forceinline__ uint32_t h2pk(float a, float b) {
    __half2 t;
    t.x = __float2half_rn(a);
    t.y = __float2half_rn(b);
    return *(uint32_t*)&t;
}
__device__ __forceinline__ void cpa16(uint32_t dst, const void* src) {
    asm volatile("cp.async.cg.shared.global [%0], [%1], 16;" :: "r"(dst), "l"(src));
}
__device__ __forceinline__ void cpa16z(uint32_t dst, const void* src, uint32_t ssize) {
    asm volatile("cp.async.cg.shared.global [%0], [%1], 16, %2;" :: "r"(dst), "l"(src), "r"(ssize));
}
#define CP_COMMIT() asm volatile("cp.async.commit_group;" ::: "memory")
#define CP_WAIT(n) asm volatile("cp.async.wait_group %0;" :: "n"(n) : "memory")

// ---------------- merged prep: C rows + Q rows ----------------
__global__ void k_prep(const float* __restrict__ C, const float* __restrict__ Q,
                       const float* __restrict__ Ww, const float* __restrict__ Wb) {
    int warp = blockIdx.x * 8 + (threadIdx.x >> 5);
    int lane = threadIdx.x & 31;
    int d0 = lane * 4;
    if (warp < BB * LC) {
        const float* row = C + (size_t)warp * DD;
        float4 v1 = *(const float4*)(row + d0);
        float4 v2 = *(const float4*)(row + 128 + d0);
        float4 w1a = *(const float4*)(Ww + d0);
        float4 w1b = *(const float4*)(Ww + 128 + d0);
        float s = v1.x * w1a.x + v1.y * w1a.y + v1.z * w1a.z + v1.w * w1a.w
                + v2.x * w1b.x + v2.y * w1b.y + v2.z * w1b.z + v2.w * w1b.w;
#pragma unroll
        for (int o = 16; o; o >>= 1) s += __shfl_xor_sync(0xFFFFFFFFu, s, o);
        if (lane == 0) g_cdot[warp] = s;
        uint2 u;
        u.x = h2pk(v1.x, v1.y); u.y = h2pk(v1.z, v1.w);
        *(uint2*)(g_cbh + (size_t)warp * DD + d0) = u;
        u.x = h2pk(v2.x, v2.y); u.y = h2pk(v2.z, v2.w);
        *(uint2*)(g_cbh + (size_t)warp * DD + 128 + d0) = u;
        float4 w3a = *(const float4*)(Ww + 2 * DD + d0);
        float4 w3b = *(const float4*)(Ww + 2 * DD + 128 + d0);
        u.x = h2pk(v1.x * w3a.x, v1.y * w3a.y); u.y = h2pk(v1.z * w3a.z, v1.w * w3a.w);
        *(uint2*)(g_ch + (size_t)warp * DD + d0) = u;
        u.x = h2pk(v2.x * w3b.x, v2.y * w3b.y); u.y = h2pk(v2.z * w3b.z, v2.w * w3b.w);
        *(uint2*)(g_ch + (size_t)warp * DD + 128 + d0) = u;
    } else {
        int r = warp - BB * LC;
        const float* row = Q + (size_t)r * DD;
        float4 v1 = *(const float4*)(row + d0);
        float4 v2 = *(const float4*)(row + 128 + d0);
        float4 w2a = *(const float4*)(Ww + DD + d0);
        float4 w2b = *(const float4*)(Ww + DD + 128 + d0);
        float s = v1.x * w2a.x + v1.y * w2a.y + v1.z * w2a.z + v1.w * w2a.w
                + v2.x * w2b.x + v2.y * w2b.y + v2.z * w2b.z + v2.w * w2b.w;
#pragma unroll
        for (int o = 16; o; o >>= 1) s += __shfl_xor_sync(0xFFFFFFFFu, s, o);
        if (lane == 0) g_qdotb[r] = s + Wb[0];
        uint2 u;
        u.x = h2pk(v1.x, v1.y); u.y = h2pk(v1.z, v1.w);
        *(uint2*)(g_qh + (size_t)r * DD + d0) = u;
        u.x = h2pk(v2.x, v2.y); u.y = h2pk(v2.z, v2.w);
        *(uint2*)(g_qh + (size_t)r * DD + 128 + d0) = u;
    }
}

// ---------------- k1: E=exp((Cw3)Q^T + dots); fused row/col sums; cp.async double-buffer ----
__global__ __launch_bounds__(512, 1) void k1_mma(const int* __restrict__ cmask,
                                                 const int* __restrict__ qmask) {
    extern __shared__ char sm[];
    const uint32_t smb = smem_u32(sm);
    float* qmf = (float*)(sm + 4 * TILEB);
    float* cmf = qmf + 128;
    float* rs = cmf + 128;
    float* cs = rs + 512;
    const int tid = threadIdx.x, lane = tid & 31, wid = tid >> 5;
    const int wm = wid & 3, wn = wid >> 2;
    const int b = blockIdx.y, ct = blockIdx.x, c0 = ct * 128;
    const int g = lane >> 2, tig = lane & 3;

    if (tid < 128) qmf[tid] = (float)qmask[b * LQ + tid];
    else if (tid < 256) cmf[tid - 128] = (float)cmask[b * LC + c0 + tid - 128];

    // stage chunk kc into buffer bf
    auto stage = [&](int kc, int bf) {
        uint32_t sa = smb + bf * 2 * TILEB, sb = sa + TILEB;
        const __half* Ag = g_ch + ((size_t)(b * LC + c0)) * DD + kc * 128;
        const __half* Bg = g_qh + ((size_t)b * LQ) * DD + kc * 128;
#pragma unroll
        for (int i = 0; i < 4; i++) {
            int idx = i * 512 + tid, row = idx >> 4, cq = idx & 15;
            cpa16(sa + row * STRB + cq * 16, Ag + (size_t)row * DD + cq * 8);
            cpa16(sb + row * STRB + cq * 16, Bg + (size_t)row * DD + cq * 8);
        }
        CP_COMMIT();
    };

    float acc[2][4][4];
#pragma unroll
    for (int i = 0; i < 2; i++)
#pragma unroll
        for (int j = 0; j < 4; j++)
#pragma unroll
            for (int k = 0; k < 4; k++) acc[i][j][k] = 0.f;

    stage(0, 0);
    stage(1, 1);
#pragma unroll
    for (int kc = 0; kc < 2; kc++) {
        if (kc == 0) CP_WAIT(1); else CP_WAIT(0);
        __syncthreads();
        uint32_t sA = smb + (kc & 1) * 2 * TILEB, sB = sA + TILEB;
#pragma unroll
        for (int ks = 0; ks < 8; ks++) {
            uint32_t ah[2][4], bh[4][2];
            uint32_t aro = (uint32_t)(lane & 15) * STRB + (ks * 16 + (lane >> 4) * 8) * 2;
#pragma unroll
            for (int mf = 0; mf < 2; mf++)
                ldsm4(sA + (uint32_t)(wm * 32 + mf * 16) * STRB + aro, ah[mf]);
            uint32_t bro = (uint32_t)((lane & 7) + ((lane >> 4) * 8)) * STRB +
                           (ks * 16 + ((lane >> 3) & 1) * 8) * 2;
#pragma unroll
            for (int np = 0; np < 2; np++) {
                uint32_t r4[4];
                ldsm4(sB + (uint32_t)(wn * 32 + np * 16) * STRB + bro, r4);
                bh[np * 2][0] = r4[0]; bh[np * 2][1] = r4[1];
                bh[np * 2 + 1][0] = r4[2]; bh[np * 2 + 1][1] = r4[3];
            }
#pragma unroll
            for (int mf = 0; mf < 2; mf++)
#pragma unroll
                for (int nf = 0; nf < 4; nf++) mmah(acc[mf][nf], ah[mf], bh[nf]);
        }
    }

    float rpart[2][2] = {{0.f, 0.f}, {0.f, 0.f}};
    float cpart[4][2] = {{0.f, 0.f}, {0.f, 0.f}, {0.f, 0.f}, {0.f, 0.f}};
#pragma unroll
    for (int mf = 0; mf < 2; mf++) {
        int c = c0 + wm * 32 + mf * 16 + g;
        float cd0 = g_cdot[b * LC + c], cd1 = g_cdot[b * LC + c + 8];
        float cm0 = cmf[c - c0], cm1 = cmf[c - c0 + 8];
        size_t r0 = ((size_t)b * LC + c) * LQ, r1 = r0 + 8 * LQ;
#pragma unroll
        for (int nf = 0; nf < 4; nf++) {
            int q = wn * 32 + nf * 8 + tig * 2;
            float qd0 = g_qdotb[b * LQ + q], qd1 = g_qdotb[b * LQ + q + 1];
            float e00 = expf(acc[mf][nf][0] + cd0 + qd0);
            float e01 = expf(acc[mf][nf][1] + cd0 + qd1);
            float e10 = expf(acc[mf][nf][2] + cd1 + qd0);
            float e11 = expf(acc[mf][nf][3] + cd1 + qd1);
            *(uint32_t*)(g_eh + r0 + q) = h2pk(e00, e01);
            *(uint32_t*)(g_eh + r1 + q) = h2pk(e10, e11);
            float qm0 = qmf[q], qm1 = qmf[q + 1];
            rpart[mf][0] += e00 * qm0 + e01 * qm1;
            rpart[mf][1] += e10 * qm0 + e11 * qm1;
            cpart[nf][0] += e00 * cm0 + e10 * cm1;
            cpart[nf][1] += e01 * cm0 + e11 * cm1;
        }
    }
#pragma unroll
    for (int mf = 0; mf < 2; mf++)
#pragma unroll
        for (int rh = 0; rh < 2; rh++) {
            float v = rpart[mf][rh];
            v += __shfl_xor_sync(0xFFFFFFFFu, v, 1);
            v += __shfl_xor_sync(0xFFFFFFFFu, v, 2);
            if (tig == 0) rs[wn * 128 + wm * 32 + mf * 16 + g + rh * 8] = v;
        }
#pragma unroll
    for (int nf = 0; nf < 4; nf++)
#pragma unroll
        for (int j = 0; j < 2; j++) {
            float v = cpart[nf][j];
            v += __shfl_xor_sync(0xFFFFFFFFu, v, 4);
            v += __shfl_xor_sync(0xFFFFFFFFu, v, 8);
            v += __shfl_xor_sync(0xFFFFFFFFu, v, 16);
            if (lane < 4) cs[wid * 32 + nf * 8 + lane * 2 + j] = v;
        }
    __syncthreads();
    if (tid < 128) {
        float s = rs[tid] + rs[128 + tid] + rs[256 + tid] + rs[384 + tid];
        g_rowinv[b * LC + c0 + tid] = 1.f / s;
    } else if (tid < 256) {
        int q = tid - 128, wnq = q >> 5, ql = q & 31;
        float s = cs[(wnq * 4 + 0) * 32 + ql] + cs[(wnq * 4 + 1) * 32 + ql]
                + cs[(wnq * 4 + 2) * 32 + ql] + cs[(wnq * 4 + 3) * 32 + ql];
        g_colpart[(b * 8 + ct) * LQ + q] = s;
    }
}

// ---------------- k2: Tp[ksp] = (cmask*E)^T @ C, split-K=2, cp.async pipeline ----------------
__global__ __launch_bounds__(512, 1) void k2_mma(const int* __restrict__ cmask) {
    extern __shared__ char sm[];
    const uint32_t smb = smem_u32(sm);
    const int tid = threadIdx.x, lane = tid & 31, wid = tid >> 5;
    const int wm = wid & 3, wn = wid >> 2;
    const int b = blockIdx.y;
    const int dt = blockIdx.x & 1, ksp = blockIdx.x >> 1;
    const int d0 = dt * 128;
    const int g = lane >> 2, tig = lane & 3;

    auto stage = [&](int kc, int bf) {
        uint32_t sa = smb + bf * 2 * TILEB, sb = sa + TILEB;
        int cb = ksp * 512 + kc * 128;
        const __half* Ag = g_eh + ((size_t)(b * LC + cb)) * LQ;
        const __half* Bg = g_cbh + ((size_t)(b * LC + cb)) * DD + d0;
        const int* cm = cmask + b * LC + cb;
#pragma unroll
        for (int i = 0; i < 4; i++) {
            int idx = i * 512 + tid, row = idx >> 4, cq = idx & 15;
            uint32_t ss = cm[row] ? 16u : 0u;
            cpa16z(sa + row * STRB + cq * 16, Ag + (size_t)row * LQ + cq * 8, ss);
            cpa16(sb + row * STRB + cq * 16, Bg + (size_t)row * DD + cq * 8);
        }
        CP_COMMIT();
    };

    float acc[2][4][4];
#pragma unroll
    for (int i = 0; i < 2; i++)
#pragma unroll
        for (int j = 0; j < 4; j++)
#pragma unroll
            for (int k = 0; k < 4; k++) acc[i][j][k] = 0.f;

    stage(0, 0);
    for (int kc = 0; kc < 4; kc++) {
        if (kc + 1 < 4) {
            stage(kc + 1, (kc + 1) & 1);
            CP_WAIT(1);
        } else {
            CP_WAIT(0);
        }
        __syncthreads();
        uint32_t sA = smb + (kc & 1) * 2 * TILEB, sB = sA + TILEB;
#pragma unroll
        for (int ks = 0; ks < 8; ks++) {
            uint32_t ah[2][4], bh[4][2];
            uint32_t aro = (uint32_t)(ks * 16 + ((lane >> 4) * 8) + (lane & 7)) * STRB +
                           (((lane >> 3) & 1) * 8) * 2;
#pragma unroll
            for (int mf = 0; mf < 2; mf++)
                ldsm4t(sA + aro + (uint32_t)(wm * 32 + mf * 16) * 2, ah[mf]);
            uint32_t bro = (uint32_t)(ks * 16 + (lane & 15)) * STRB + ((lane >> 4) * 8) * 2;
#pragma unroll
            for (int np = 0; np < 2; np++) {
                uint32_t r4[4];
                ldsm4t(sB + bro + (uint32_t)(wn * 32 + np * 16) * 2, r4);
                bh[np * 2][0] = r4[0]; bh[np * 2][1] = r4[1];
                bh[np * 2 + 1][0] = r4[2]; bh[np * 2 + 1][1] = r4[3];
            }
#pragma unroll
            for (int mf = 0; mf < 2; mf++)
#pragma unroll
                for (int nf = 0; nf < 4; nf++) mmah(acc[mf][nf], ah[mf], bh[nf]);
        }
        __syncthreads();
    }
    float* Tp = g_Tp + ((size_t)(b * 2 + ksp) * LQ) * DD;
#pragma unroll
    for (int mf = 0; mf < 2; mf++) {
        int q = wm * 32 + mf * 16 + g;
#pragma unroll
        for (int nf = 0; nf < 4; nf++) {
            int d = d0 + wn * 32 + nf * 8 + tig * 2;
            *(float2*)(Tp + (size_t)q * DD + d) = make_float2(acc[mf][nf][0], acc[mf][nf][1]);
            *(float2*)(Tp + (size_t)(q + 8) * DD + d) = make_float2(acc[mf][nf][2], acc[mf][nf][3]);
        }
    }
}

// ---------------- t_reduce: colinv fused; partials -> T fp16 ----------------
__global__ void k_t_reduce() {
    size_t i = (size_t)blockIdx.x * 256 + threadIdx.x;
    size_t e0 = i * 4;
    int b = (int)(e0 >> 15);
    int q = (int)((e0 >> 8) & 127);
    float s = 0.f;
#pragma unroll
    for (int j = 0; j < 8; j++) s += g_colpart[(b * 8 + j) * LQ + q];
    float ci = 1.f / s;
    size_t base = ((size_t)(b * 2) * LQ + q) * DD + (e0 & 255);
    float4 s0 = *(const float4*)(g_Tp + base);
    float4 s1 = *(const float4*)(g_Tp + base + (size_t)LQ * DD);
    uint2 u;
    u.x = h2pk((s0.x + s1.x) * ci, (s0.y + s1.y) * ci);
    u.y = h2pk((s0.z + s1.z) * ci, (s0.w + s1.w) * ci);
    *(uint2*)(g_th + e0) = u;
}

// ---------------- k3: A=Sq@Q and Bm=Sq@T; fused 4-segment epilogue ----------------
__global__ __launch_bounds__(512, 1) void k3_mma(const float* __restrict__ Cp,
                                                 const int* __restrict__ qmask,
                                                 float* __restrict__ out) {
    extern __shared__ char sm[];
    const uint32_t smb = smem_u32(sm);
    const uint32_t sA = smb, sBq = smb + TILEB, sBt = smb + 2 * TILEB;
    const int tid = threadIdx.x, lane = tid & 31, wid = tid >> 5;
    const int wm = wid & 3, wn = wid >> 2;
    const int b = blockIdx.y;
    const int ct = blockIdx.x >> 1, dt = blockIdx.x & 1;
    const int c0 = ct * 128, d0 = dt * 128;
    const int g = lane >> 2, tig = lane & 3;

    {
        const __half* Ag = g_eh + ((size_t)(b * LC + c0)) * LQ;
        const __half* Bqg = g_qh + ((size_t)b * LQ) * DD + d0;
        const __half* Btg = g_th + ((size_t)b * LQ) * DD + d0;
        const int* qm = qmask + b * LQ;
#pragma unroll
        for (int i = 0; i < 4; i++) {
            int idx = i * 512 + tid, row = idx >> 4, cq = idx & 15;
            uint32_t ss = qm[row] ? 16u : 0u;
            cpa16(sA + row * STRB + cq * 16, Ag + (size_t)row * LQ + cq * 8);
            cpa16z(sBq + row * STRB + cq * 16, Bqg + (size_t)row * DD + cq * 8, ss);
            cpa16z(sBt + row * STRB + cq * 16, Btg + (size_t)row * DD + cq * 8, ss);
        }
        CP_COMMIT();
        CP_WAIT(0);
    }
    __syncthreads();

    float accA[2][4][4], accB[2][4][4];
#pragma unroll
    for (int i = 0; i < 2; i++)
#pragma unroll
        for (int j = 0; j < 4; j++)
#pragma unroll
            for (int k = 0; k < 4; k++) { accA[i][j][k] = 0.f; accB[i][j][k] = 0.f; }

#pragma unroll
    for (int ks = 0; ks < 8; ks++) {
        uint32_t ah[2][4], bq[4][2], bt[4][2];
        uint32_t aro = (uint32_t)(lane & 15) * STRB + (ks * 16 + (lane >> 4) * 8) * 2;
#pragma unroll
        for (int mf = 0; mf < 2; mf++)
            ldsm4(sA + (uint32_t)(wm * 32 + mf * 16) * STRB + aro, ah[mf]);
        uint32_t bro = (uint32_t)(ks * 16 + (lane & 15)) * STRB + ((lane >> 4) * 8) * 2;
#pragma unroll
        for (int np = 0; np < 2; np++) {
            uint32_t r4[4];
            ldsm4t(sBq + bro + (uint32_t)(wn * 32 + np * 16) * 2, r4);
            bq[np * 2][0] = r4[0]; bq[np * 2][1] = r4[1];
            bq[np * 2 + 1][0] = r4[2]; bq[np * 2 + 1][1] = r4[3];
            ldsm4t(sBt + bro + (uint32_t)(wn * 32 + np * 16) * 2, r4);
            bt[np * 2][0] = r4[0]; bt[np * 2][1] = r4[1];
            bt[np * 2 + 1][0] = r4[2]; bt[np * 2 + 1][1] = r4[3];
        }
#pragma unroll
        for (int mf = 0; mf < 2; mf++)
#pragma unroll
            for (int nf = 0; nf < 4; nf++) {
                mmah(accA[mf][nf], ah[mf], bq[nf]);
                mmah(accB[mf][nf], ah[mf], bt[nf]);
            }
    }

#pragma unroll
    for (int mf = 0; mf < 2; mf++) {
        int c = c0 + wm * 32 + mf * 16 + g;
        float r0 = g_rowinv[b * LC + c], r1 = g_rowinv[b * LC + c + 8];
        const float* C0 = Cp + ((size_t)(b * LC + c)) * DD;
        const float* C1 = C0 + 8 * DD;
        float* o0 = out + ((size_t)(b * LC + c)) * (4 * DD);
        float* o1 = o0 + (size_t)8 * 4 * DD;
#pragma unroll
        for (int nf = 0; nf < 4; nf++) {
            int d = d0 + wn * 32 + nf * 8 + tig * 2;
            float2 cv0 = *(const float2*)(C0 + d);
            float2 cv1 = *(const float2*)(C1 + d);
            float a00 = accA[mf][nf][0] * r0, a01 = accA[mf][nf][1] * r0;
            float a10 = accA[mf][nf][2] * r1, a11 = accA[mf][nf][3] * r1;
            float b00 = accB[mf][nf][0] * r0, b01 = accB[mf][nf][1] * r0;
            float b10 = accB[mf][nf][2] * r1, b11 = accB[mf][nf][3] * r1;
            *(float2*)(o0 + d) = cv0;
            *(float2*)(o1 + d) = cv1;
            *(float2*)(o0 + DD + d) = make_float2(a00, a01);
            *(float2*)(o1 + DD + d) = make_float2(a10, a11);
            *(float2*)(o0 + 2 * DD + d) = make_float2(cv0.x * a00, cv0.y * a01);
            *(float2*)(o1 + 2 * DD + d) = make_float2(cv1.x * a10, cv1.y * a11);
            *(float2*)(o0 + 3 * DD + d) = make_float2(cv0.x * b00, cv0.y * b01);
            *(float2*)(o1 + 3 * DD + d) = make_float2(cv1.x * b10, cv1.y * b11);
        }
    }
}

extern "C" void kernel_launch(void* const* d_in, const int* in_sizes, int n_in,
                              void* d_out, int out_size) {
    const float* C = (const float*)d_in[0];
    const float* Q = (const float*)d_in[1];
    const int* cmask = (const int*)d_in[2];
    const int* qmask = (const int*)d_in[3];
    const float* Ww = (const float*)d_in[4];
    const float* Wb = (const float*)d_in[5];
    float* out = (float*)d_out;

    static bool attr_set = false;
    if (!attr_set) {
        cudaFuncSetAttribute(k1_mma, cudaFuncAttributeMaxDynamicSharedMemorySize, SM_K1);
        cudaFuncSetAttribute(k2_mma, cudaFuncAttributeMaxDynamicSharedMemorySize, SM_K2);
        cudaFuncSetAttribute(k3_mma, cudaFuncAttributeMaxDynamicSharedMemorySize, SM_K3);
        attr_set = true;
    }

    k_prep<<<4608, 256>>>(C, Q, Ww, Wb);
    k1_mma<<<dim3(8, BB), 512, SM_K1>>>(cmask, qmask);
    k2_mma<<<dim3(4, BB), 512, SM_K2>>>(cmask);
    k_t_reduce<<<1024, 256>>>();
    k3_mma<<<dim3(16, BB), 512, SM_K3>>>(C, qmask, out);
}

// round 6
// speedup vs baseline: 3.4386x; 1.1006x over previous
#include <cuda_runtime.h>
#include <cuda_fp16.h>
#include <cstdint>
#include <math.h>

#define BB 32
#define LC 1024
#define LQ 128
#define DD 256
#define STRB 272                 // smem row stride bytes (128 fp16 = 256B + 16 pad)
#define AT64  (64 * STRB)        // 17408 B : 64-row tile
#define BT128 (128 * STRB)       // 34816 B : 128-row tile
#define K1PAIR (AT64 + BT128)    // 52224
#define SM_K1 (2 * K1PAIR + 2816)
#define SM_K2 (4 * BT128)
#define SM_K3 (AT64 + 2 * BT128)

// ---------------- scratch ----------------
__device__ float g_Tp[(size_t)BB * 2 * LQ * DD];     // k2 split-K partials (fp32)
__device__ float g_cdot[BB * LC];
__device__ float g_qdotb[BB * LQ];
__device__ float g_rowinv[BB * LC];
__device__ float g_colinv[BB * LQ];
__device__ float g_colpart[BB * 16 * LQ];
__device__ __half g_eh[(size_t)BB * LC * LQ];        // E
__device__ __half g_ch[(size_t)BB * LC * DD];        // C*w3
__device__ __half g_cbh[(size_t)BB * LC * DD];       // raw C
__device__ __half g_qh[(size_t)BB * LQ * DD];        // raw Q
__device__ __half g_th[(size_t)BB * LQ * DD];        // T

// ---------------- helpers ----------------
__device__ __forceinline__ uint32_t smem_u32(const void* p) {
    uint32_t a;
    asm("{ .reg .u64 t; cvta.to.shared.u64 t, %1; cvt.u32.u64 %0, t; }" : "=r"(a) : "l"(p));
    return a;
}
__device__ __forceinline__ void ldsm4(uint32_t a, uint32_t* r) {
    asm volatile("ldmatrix.sync.aligned.m8n8.x4.shared.b16 {%0,%1,%2,%3}, [%4];"
                 : "=r"(r[0]), "=r"(r[1]), "=r"(r[2]), "=r"(r[3]) : "r"(a));
}
__device__ __forceinline__ void ldsm4t(uint32_t a, uint32_t* r) {
    asm volatile("ldmatrix.sync.aligned.m8n8.x4.trans.shared.b16 {%0,%1,%2,%3}, [%4];"
                 : "=r"(r[0]), "=r"(r[1]), "=r"(r[2]), "=r"(r[3]) : "r"(a));
}
__device__ __forceinline__ void mmah(float* c, const uint32_t* a, const uint32_t* b) {
    asm volatile(
        "mma.sync.aligned.m16n8k16.row.col.f32.f16.f16.f32 "
        "{%0,%1,%2,%3}, {%4,%5,%6,%7}, {%8,%9}, {%0,%1,%2,%3};"
        : "+f"(c[0]), "+f"(c[1]), "+f"(c[2]), "+f"(c[3])
        : "r"(a[0]), "r"(a[1]), "r"(a[2]), "r"(a[3]), "r"(b[0]), "r"(b[1]));
}
__device__ __forceinline__ uint32_t h2pk(float a, float b) {
    __half2 t;
    t.x = __float2half_rn(a);
    t.y = __float2half_rn(b);
    return *(uint32_t*)&t;
}
__device__ __forceinline__ void cpa16(uint32_t dst, const void* src) {
    asm volatile("cp.async.cg.shared.global [%0], [%1], 16;" :: "r"(dst), "l"(src));
}
__device__ __forceinline__ void cpa16z(uint32_t dst, const void* src, uint32_t ssize) {
    asm volatile("cp.async.cg.shared.global [%0], [%1], 16, %2;" :: "r"(dst), "l"(src), "r"(ssize));
}
#define CP_COMMIT() asm volatile("cp.async.commit_group;" ::: "memory")
#define CP_WAIT(n) asm volatile("cp.async.wait_group %0;" :: "n"(n) : "memory")

// ---------------- merged prep: C rows + Q rows ----------------
__global__ void k_prep(const float* __restrict__ C, const float* __restrict__ Q,
                       const float* __restrict__ Ww, const float* __restrict__ Wb) {
    int warp = blockIdx.x * 8 + (threadIdx.x >> 5);
    int lane = threadIdx.x & 31;
    int d0 = lane * 4;
    if (warp < BB * LC) {
        const float* row = C + (size_t)warp * DD;
        float4 v1 = *(const float4*)(row + d0);
        float4 v2 = *(const float4*)(row + 128 + d0);
        float4 w1a = *(const float4*)(Ww + d0);
        float4 w1b = *(const float4*)(Ww + 128 + d0);
        float s = v1.x * w1a.x + v1.y * w1a.y + v1.z * w1a.z + v1.w * w1a.w
                + v2.x * w1b.x + v2.y * w1b.y + v2.z * w1b.z + v2.w * w1b.w;
#pragma unroll
        for (int o = 16; o; o >>= 1) s += __shfl_xor_sync(0xFFFFFFFFu, s, o);
        if (lane == 0) g_cdot[warp] = s;
        uint2 u;
        u.x = h2pk(v1.x, v1.y); u.y = h2pk(v1.z, v1.w);
        *(uint2*)(g_cbh + (size_t)warp * DD + d0) = u;
        u.x = h2pk(v2.x, v2.y); u.y = h2pk(v2.z, v2.w);
        *(uint2*)(g_cbh + (size_t)warp * DD + 128 + d0) = u;
        float4 w3a = *(const float4*)(Ww + 2 * DD + d0);
        float4 w3b = *(const float4*)(Ww + 2 * DD + 128 + d0);
        u.x = h2pk(v1.x * w3a.x, v1.y * w3a.y); u.y = h2pk(v1.z * w3a.z, v1.w * w3a.w);
        *(uint2*)(g_ch + (size_t)warp * DD + d0) = u;
        u.x = h2pk(v2.x * w3b.x, v2.y * w3b.y); u.y = h2pk(v2.z * w3b.z, v2.w * w3b.w);
        *(uint2*)(g_ch + (size_t)warp * DD + 128 + d0) = u;
    } else {
        int r = warp - BB * LC;
        const float* row = Q + (size_t)r * DD;
        float4 v1 = *(const float4*)(row + d0);
        float4 v2 = *(const float4*)(row + 128 + d0);
        float4 w2a = *(const float4*)(Ww + DD + d0);
        float4 w2b = *(const float4*)(Ww + DD + 128 + d0);
        float s = v1.x * w2a.x + v1.y * w2a.y + v1.z * w2a.z + v1.w * w2a.w
                + v2.x * w2b.x + v2.y * w2b.y + v2.z * w2b.z + v2.w * w2b.w;
#pragma unroll
        for (int o = 16; o; o >>= 1) s += __shfl_xor_sync(0xFFFFFFFFu, s, o);
        if (lane == 0) g_qdotb[r] = s + Wb[0];
        uint2 u;
        u.x = h2pk(v1.x, v1.y); u.y = h2pk(v1.z, v1.w);
        *(uint2*)(g_qh + (size_t)r * DD + d0) = u;
        u.x = h2pk(v2.x, v2.y); u.y = h2pk(v2.z, v2.w);
        *(uint2*)(g_qh + (size_t)r * DD + 128 + d0) = u;
    }
}

// ---------------- k1: 64c x 128q tiles, 256 thr, 2 CTA/SM ----------------
__global__ __launch_bounds__(256, 2) void k1_mma(const int* __restrict__ cmask,
                                                 const int* __restrict__ qmask) {
    extern __shared__ char sm[];
    const uint32_t smb = smem_u32(sm);
    float* qmf = (float*)(sm + 2 * K1PAIR);
    float* cmf = qmf + 128;
    float* rs = cmf + 64;             // [4 wn][64 rows]
    float* cs = rs + 256;             // [8 wid][32]
    const int tid = threadIdx.x, lane = tid & 31, wid = tid >> 5;
    const int wm = wid & 1, wn = wid >> 1;
    const int b = blockIdx.y, ct = blockIdx.x, c0 = ct * 64;
    const int g = lane >> 2, tig = lane & 3;

    if (tid < 128) qmf[tid] = (float)qmask[b * LQ + tid];
    else if (tid < 192) cmf[tid - 128] = (float)cmask[b * LC + c0 + tid - 128];

    auto stage = [&](int kc, int bf) {
        uint32_t sa = smb + bf * K1PAIR, sb = sa + AT64;
        const __half* Ag = g_ch + ((size_t)(b * LC + c0)) * DD + kc * 128;
        const __half* Bg = g_qh + ((size_t)b * LQ) * DD + kc * 128;
#pragma unroll
        for (int i = 0; i < 4; i++) {
            int idx = i * 256 + tid, row = idx >> 4, cq = idx & 15;
            cpa16(sa + row * STRB + cq * 16, Ag + (size_t)row * DD + cq * 8);
        }
#pragma unroll
        for (int i = 0; i < 8; i++) {
            int idx = i * 256 + tid, row = idx >> 4, cq = idx & 15;
            cpa16(sb + row * STRB + cq * 16, Bg + (size_t)row * DD + cq * 8);
        }
        CP_COMMIT();
    };

    float acc[2][4][4];
#pragma unroll
    for (int i = 0; i < 2; i++)
#pragma unroll
        for (int j = 0; j < 4; j++)
#pragma unroll
            for (int k = 0; k < 4; k++) acc[i][j][k] = 0.f;

    stage(0, 0);
    stage(1, 1);
#pragma unroll
    for (int kc = 0; kc < 2; kc++) {
        if (kc == 0) CP_WAIT(1); else CP_WAIT(0);
        __syncthreads();
        uint32_t sA = smb + (kc & 1) * K1PAIR, sB = sA + AT64;
#pragma unroll
        for (int ks = 0; ks < 8; ks++) {
            uint32_t ah[2][4], bh[4][2];
            uint32_t aro = (uint32_t)(lane & 15) * STRB + (ks * 16 + (lane >> 4) * 8) * 2;
#pragma unroll
            for (int mf = 0; mf < 2; mf++)
                ldsm4(sA + (uint32_t)(wm * 32 + mf * 16) * STRB + aro, ah[mf]);
            uint32_t bro = (uint32_t)((lane & 7) + ((lane >> 4) * 8)) * STRB +
                           (ks * 16 + ((lane >> 3) & 1) * 8) * 2;
#pragma unroll
            for (int np = 0; np < 2; np++) {
                uint32_t r4[4];
                ldsm4(sB + (uint32_t)(wn * 32 + np * 16) * STRB + bro, r4);
                bh[np * 2][0] = r4[0]; bh[np * 2][1] = r4[1];
                bh[np * 2 + 1][0] = r4[2]; bh[np * 2 + 1][1] = r4[3];
            }
#pragma unroll
            for (int mf = 0; mf < 2; mf++)
#pragma unroll
                for (int nf = 0; nf < 4; nf++) mmah(acc[mf][nf], ah[mf], bh[nf]);
        }
    }

    float rpart[2][2] = {{0.f, 0.f}, {0.f, 0.f}};
    float cpart[4][2] = {{0.f, 0.f}, {0.f, 0.f}, {0.f, 0.f}, {0.f, 0.f}};
#pragma unroll
    for (int mf = 0; mf < 2; mf++) {
        int c = c0 + wm * 32 + mf * 16 + g;
        float cd0 = g_cdot[b * LC + c], cd1 = g_cdot[b * LC + c + 8];
        float cm0 = cmf[c - c0], cm1 = cmf[c - c0 + 8];
        size_t r0 = ((size_t)b * LC + c) * LQ, r1 = r0 + 8 * LQ;
#pragma unroll
        for (int nf = 0; nf < 4; nf++) {
            int q = wn * 32 + nf * 8 + tig * 2;
            float qd0 = g_qdotb[b * LQ + q], qd1 = g_qdotb[b * LQ + q + 1];
            float e00 = expf(acc[mf][nf][0] + cd0 + qd0);
            float e01 = expf(acc[mf][nf][1] + cd0 + qd1);
            float e10 = expf(acc[mf][nf][2] + cd1 + qd0);
            float e11 = expf(acc[mf][nf][3] + cd1 + qd1);
            *(uint32_t*)(g_eh + r0 + q) = h2pk(e00, e01);
            *(uint32_t*)(g_eh + r1 + q) = h2pk(e10, e11);
            float qm0 = qmf[q], qm1 = qmf[q + 1];
            rpart[mf][0] += e00 * qm0 + e01 * qm1;
            rpart[mf][1] += e10 * qm0 + e11 * qm1;
            cpart[nf][0] += e00 * cm0 + e10 * cm1;
            cpart[nf][1] += e01 * cm0 + e11 * cm1;
        }
    }
#pragma unroll
    for (int mf = 0; mf < 2; mf++)
#pragma unroll
        for (int rh = 0; rh < 2; rh++) {
            float v = rpart[mf][rh];
            v += __shfl_xor_sync(0xFFFFFFFFu, v, 1);
            v += __shfl_xor_sync(0xFFFFFFFFu, v, 2);
            if (tig == 0) rs[wn * 64 + wm * 32 + mf * 16 + g + rh * 8] = v;
        }
#pragma unroll
    for (int nf = 0; nf < 4; nf++)
#pragma unroll
        for (int j = 0; j < 2; j++) {
            float v = cpart[nf][j];
            v += __shfl_xor_sync(0xFFFFFFFFu, v, 4);
            v += __shfl_xor_sync(0xFFFFFFFFu, v, 8);
            v += __shfl_xor_sync(0xFFFFFFFFu, v, 16);
            if (lane < 4) cs[wid * 32 + nf * 8 + lane * 2 + j] = v;
        }
    __syncthreads();
    if (tid < 64) {
        float s = rs[tid] + rs[64 + tid] + rs[128 + tid] + rs[192 + tid];
        g_rowinv[b * LC + c0 + tid] = 1.f / s;
    } else if (tid < 192) {
        int q = tid - 64, wnq = q >> 5, ql = q & 31;
        float s = cs[(wnq * 2 + 0) * 32 + ql] + cs[(wnq * 2 + 1) * 32 + ql];
        g_colpart[(b * 16 + ct) * LQ + q] = s;
    }
}

// ---------------- k2: Tp[ksp] = (cmask*E)^T @ C, split-K=2; colinv by block 0 ----------------
__global__ __launch_bounds__(512, 1) void k2_mma(const int* __restrict__ cmask) {
    extern __shared__ char sm[];
    const uint32_t smb = smem_u32(sm);
    const int tid = threadIdx.x, lane = tid & 31, wid = tid >> 5;
    const int wm = wid & 3, wn = wid >> 2;
    const int b = blockIdx.y;
    const int dt = blockIdx.x & 1, ksp = blockIdx.x >> 1;
    const int d0 = dt * 128;
    const int g = lane >> 2, tig = lane & 3;

    if (blockIdx.x == 0 && tid < 128) {
        float s = 0.f;
#pragma unroll
        for (int j = 0; j < 16; j++) s += g_colpart[(b * 16 + j) * LQ + tid];
        g_colinv[b * LQ + tid] = 1.f / s;
    }

    auto stage = [&](int kc, int bf) {
        uint32_t sa = smb + bf * 2 * BT128, sb = sa + BT128;
        int cb = ksp * 512 + kc * 128;
        const __half* Ag = g_eh + ((size_t)(b * LC + cb)) * LQ;
        const __half* Bg = g_cbh + ((size_t)(b * LC + cb)) * DD + d0;
        const int* cm = cmask + b * LC + cb;
#pragma unroll
        for (int i = 0; i < 4; i++) {
            int idx = i * 512 + tid, row = idx >> 4, cq = idx & 15;
            uint32_t ss = cm[row] ? 16u : 0u;
            cpa16z(sa + row * STRB + cq * 16, Ag + (size_t)row * LQ + cq * 8, ss);
            cpa16(sb + row * STRB + cq * 16, Bg + (size_t)row * DD + cq * 8);
        }
        CP_COMMIT();
    };

    float acc[2][4][4];
#pragma unroll
    for (int i = 0; i < 2; i++)
#pragma unroll
        for (int j = 0; j < 4; j++)
#pragma unroll
            for (int k = 0; k < 4; k++) acc[i][j][k] = 0.f;

    stage(0, 0);
    for (int kc = 0; kc < 4; kc++) {
        if (kc + 1 < 4) {
            stage(kc + 1, (kc + 1) & 1);
            CP_WAIT(1);
        } else {
            CP_WAIT(0);
        }
        __syncthreads();
        uint32_t sA = smb + (kc & 1) * 2 * BT128, sB = sA + BT128;
#pragma unroll
        for (int ks = 0; ks < 8; ks++) {
            uint32_t ah[2][4], bh[4][2];
            uint32_t aro = (uint32_t)(ks * 16 + ((lane >> 4) * 8) + (lane & 7)) * STRB +
                           (((lane >> 3) & 1) * 8) * 2;
#pragma unroll
            for (int mf = 0; mf < 2; mf++)
                ldsm4t(sA + aro + (uint32_t)(wm * 32 + mf * 16) * 2, ah[mf]);
            uint32_t bro = (uint32_t)(ks * 16 + (lane & 15)) * STRB + ((lane >> 4) * 8) * 2;
#pragma unroll
            for (int np = 0; np < 2; np++) {
                uint32_t r4[4];
                ldsm4t(sB + bro + (uint32_t)(wn * 32 + np * 16) * 2, r4);
                bh[np * 2][0] = r4[0]; bh[np * 2][1] = r4[1];
                bh[np * 2 + 1][0] = r4[2]; bh[np * 2 + 1][1] = r4[3];
            }
#pragma unroll
            for (int mf = 0; mf < 2; mf++)
#pragma unroll
                for (int nf = 0; nf < 4; nf++) mmah(acc[mf][nf], ah[mf], bh[nf]);
        }
        __syncthreads();
    }
    float* Tp = g_Tp + ((size_t)(b * 2 + ksp) * LQ) * DD;
#pragma unroll
    for (int mf = 0; mf < 2; mf++) {
        int q = wm * 32 + mf * 16 + g;
#pragma unroll
        for (int nf = 0; nf < 4; nf++) {
            int d = d0 + wn * 32 + nf * 8 + tig * 2;
            *(float2*)(Tp + (size_t)q * DD + d) = make_float2(acc[mf][nf][0], acc[mf][nf][1]);
            *(float2*)(Tp + (size_t)(q + 8) * DD + d) = make_float2(acc[mf][nf][2], acc[mf][nf][3]);
        }
    }
}

// ---------------- t_reduce: partials -> T fp16 (8 elems/thread) ----------------
__global__ void k_t_reduce() {
    size_t i = (size_t)blockIdx.x * 256 + threadIdx.x;   // 131072 threads
    size_t e0 = i * 8;
    int b = (int)(e0 >> 15);
    int q = (int)((e0 >> 8) & 127);
    float ci = g_colinv[b * LQ + q];
    size_t base = ((size_t)(b * 2) * LQ + q) * DD + (e0 & 255);
    float4 a0 = *(const float4*)(g_Tp + base);
    float4 a1 = *(const float4*)(g_Tp + base + (size_t)LQ * DD);
    float4 b0 = *(const float4*)(g_Tp + base + 4);
    float4 b1 = *(const float4*)(g_Tp + base + (size_t)LQ * DD + 4);
    uint4 u;
    u.x = h2pk((a0.x + a1.x) * ci, (a0.y + a1.y) * ci);
    u.y = h2pk((a0.z + a1.z) * ci, (a0.w + a1.w) * ci);
    u.z = h2pk((b0.x + b1.x) * ci, (b0.y + b1.y) * ci);
    u.w = h2pk((b0.z + b1.z) * ci, (b0.w + b1.w) * ci);
    *(uint4*)(g_th + e0) = u;
}

// ---------------- k3: 64c x 128d tiles, 256 thr, 2 CTA/SM; streaming stores ----------------
__global__ __launch_bounds__(256, 2) void k3_mma(const float* __restrict__ Cp,
                                                 const int* __restrict__ qmask,
                                                 float* __restrict__ out) {
    extern __shared__ char sm[];
    const uint32_t smb = smem_u32(sm);
    const uint32_t sA = smb, sBq = smb + AT64, sBt = smb + AT64 + BT128;
    const int tid = threadIdx.x, lane = tid & 31, wid = tid >> 5;
    const int wm = wid & 1, wn = wid >> 1;
    const int b = blockIdx.y;
    const int ct = blockIdx.x >> 1, dt = blockIdx.x & 1;
    const int c0 = ct * 64, d0 = dt * 128;
    const int g = lane >> 2, tig = lane & 3;

    {
        const __half* Ag = g_eh + ((size_t)(b * LC + c0)) * LQ;
        const __half* Bqg = g_qh + ((size_t)b * LQ) * DD + d0;
        const __half* Btg = g_th + ((size_t)b * LQ) * DD + d0;
        const int* qm = qmask + b * LQ;
#pragma unroll
        for (int i = 0; i < 4; i++) {
            int idx = i * 256 + tid, row = idx >> 4, cq = idx & 15;
            cpa16(sA + row * STRB + cq * 16, Ag + (size_t)row * LQ + cq * 8);
        }
#pragma unroll
        for (int i = 0; i < 8; i++) {
            int idx = i * 256 + tid, row = idx >> 4, cq = idx & 15;
            uint32_t ss = qm[row] ? 16u : 0u;
            cpa16z(sBq + row * STRB + cq * 16, Bqg + (size_t)row * DD + cq * 8, ss);
            cpa16z(sBt + row * STRB + cq * 16, Btg + (size_t)row * DD + cq * 8, ss);
        }
        CP_COMMIT();
        CP_WAIT(0);
    }
    __syncthreads();

    float accA[2][4][4], accB[2][4][4];
#pragma unroll
    for (int i = 0; i < 2; i++)
#pragma unroll
        for (int j = 0; j < 4; j++)
#pragma unroll
            for (int k = 0; k < 4; k++) { accA[i][j][k] = 0.f; accB[i][j][k] = 0.f; }

#pragma unroll
    for (int ks = 0; ks < 8; ks++) {
        uint32_t ah[2][4], bq[4][2], bt[4][2];
        uint32_t aro = (uint32_t)(lane & 15) * STRB + (ks * 16 + (lane >> 4) * 8) * 2;
#pragma unroll
        for (int mf = 0; mf < 2; mf++)
            ldsm4(sA + (uint32_t)(wm * 32 + mf * 16) * STRB + aro, ah[mf]);
        uint32_t bro = (uint32_t)(ks * 16 + (lane & 15)) * STRB + ((lane >> 4) * 8) * 2;
#pragma unroll
        for (int np = 0; np < 2; np++) {
            uint32_t r4[4];
            ldsm4t(sBq + bro + (uint32_t)(wn * 32 + np * 16) * 2, r4);
            bq[np * 2][0] = r4[0]; bq[np * 2][1] = r4[1];
            bq[np * 2 + 1][0] = r4[2]; bq[np * 2 + 1][1] = r4[3];
            ldsm4t(sBt + bro + (uint32_t)(wn * 32 + np * 16) * 2, r4);
            bt[np * 2][0] = r4[0]; bt[np * 2][1] = r4[1];
            bt[np * 2 + 1][0] = r4[2]; bt[np * 2 + 1][1] = r4[3];
        }
#pragma unroll
        for (int mf = 0; mf < 2; mf++)
#pragma unroll
            for (int nf = 0; nf < 4; nf++) {
                mmah(accA[mf][nf], ah[mf], bq[nf]);
                mmah(accB[mf][nf], ah[mf], bt[nf]);
            }
    }

#pragma unroll
    for (int mf = 0; mf < 2; mf++) {
        int c = c0 + wm * 32 + mf * 16 + g;
        float r0 = g_rowinv[b * LC + c], r1 = g_rowinv[b * LC + c + 8];
        const float* C0 = Cp + ((size_t)(b * LC + c)) * DD;
        const float* C1 = C0 + 8 * DD;
        float* o0 = out + ((size_t)(b * LC + c)) * (4 * DD);
        float* o1 = o0 + (size_t)8 * 4 * DD;
#pragma unroll
        for (int nf = 0; nf < 4; nf++) {
            int d = d0 + wn * 32 + nf * 8 + tig * 2;
            float2 cv0 = *(const float2*)(C0 + d);
            float2 cv1 = *(const float2*)(C1 + d);
            float a00 = accA[mf][nf][0] * r0, a01 = accA[mf][nf][1] * r0;
            float a10 = accA[mf][nf][2] * r1, a11 = accA[mf][nf][3] * r1;
            float b00 = accB[mf][nf][0] * r0, b01 = accB[mf][nf][1] * r0;
            float b10 = accB[mf][nf][2] * r1, b11 = accB[mf][nf][3] * r1;
            __stcs((float2*)(o0 + d), cv0);
            __stcs((float2*)(o1 + d), cv1);
            __stcs((float2*)(o0 + DD + d), make_float2(a00, a01));
            __stcs((float2*)(o1 + DD + d), make_float2(a10, a11));
            __stcs((float2*)(o0 + 2 * DD + d), make_float2(cv0.x * a00, cv0.y * a01));
            __stcs((float2*)(o1 + 2 * DD + d), make_float2(cv1.x * a10, cv1.y * a11));
            __stcs((float2*)(o0 + 3 * DD + d), make_float2(cv0.x * b00, cv0.y * b01));
            __stcs((float2*)(o1 + 3 * DD + d), make_float2(cv1.x * b10, cv1.y * b11));
        }
    }
}

extern "C" void kernel_launch(void* const* d_in, const int* in_sizes, int n_in,
                              void* d_out, int out_size) {
    const float* C = (const float*)d_in[0];
    const float* Q = (const float*)d_in[1];
    const int* cmask = (const int*)d_in[2];
    const int* qmask = (const int*)d_in[3];
    const float* Ww = (const float*)d_in[4];
    const float* Wb = (const float*)d_in[5];
    float* out = (float*)d_out;

    static bool attr_set = false;
    if (!attr_set) {
        cudaFuncSetAttribute(k1_mma, cudaFuncAttributeMaxDynamicSharedMemorySize, SM_K1);
        cudaFuncSetAttribute(k2_mma, cudaFuncAttributeMaxDynamicSharedMemorySize, SM_K2);
        cudaFuncSetAttribute(k3_mma, cudaFuncAttributeMaxDynamicSharedMemorySize, SM_K3);
        attr_set = true;
    }

    k_prep<<<4608, 256>>>(C, Q, Ww, Wb);
    k1_mma<<<dim3(16, BB), 256, SM_K1>>>(cmask, qmask);
    k2_mma<<<dim3(4, BB), 512, SM_K2>>>(cmask);
    k_t_reduce<<<512, 256>>>();
    k3_mma<<<dim3(32, BB), 256, SM_K3>>>(C, qmask, out);
}

// round 7
// speedup vs baseline: 3.4633x; 1.0072x over previous
#include <cuda_runtime.h>
#include <cuda_fp16.h>
#include <cstdint>
#include <math.h>

#define BB 32
#define LC 1024
#define LQ 128
#define DD 256
#define STRB 272                 // 128-col fp16 tile row stride (256B + 16 pad)
#define STRB2 144                // 64-col fp16 tile row stride (128B + 16 pad)
#define AT64  (64 * STRB)        // 17408 B : 64-row x 128-col tile
#define BT128 (128 * STRB)       // 34816 B : 128-row x 128-col tile
#define BT64d (128 * STRB2)      // 18432 B : 128-row x 64-col tile
#define K1PAIR (AT64 + BT128)    // 52224
#define K2PAIR (BT128 + BT64d)   // 53248
#define SM_K1 (2 * K1PAIR + 2816)
#define SM_K2 (2 * K2PAIR)
#define SM_K3 (AT64 + 2 * BT128)

// ---------------- scratch ----------------
__device__ float g_Tp[(size_t)BB * 2 * LQ * DD];     // k2 split-K partials (fp32)
__device__ float g_cdot[BB * LC];
__device__ float g_qdotb[BB * LQ];
__device__ float g_rowinv[BB * LC];
__device__ float g_colpart[BB * 16 * LQ];
__device__ int   g_cnt[BB * 4];
__device__ __half g_eh[(size_t)BB * LC * LQ];        // E
__device__ __half g_ch[(size_t)BB * LC * DD];        // C*w3
__device__ __half g_cbh[(size_t)BB * LC * DD];       // raw C
__device__ __half g_qh[(size_t)BB * LQ * DD];        // raw Q
__device__ __half g_th[(size_t)BB * LQ * DD];        // T

// ---------------- helpers ----------------
__device__ __forceinline__ uint32_t smem_u32(const void* p) {
    uint32_t a;
    asm("{ .reg .u64 t; cvta.to.shared.u64 t, %1; cvt.u32.u64 %0, t; }" : "=r"(a) : "l"(p));
    return a;
}
__device__ __forceinline__ void ldsm4(uint32_t a, uint32_t* r) {
    asm volatile("ldmatrix.sync.aligned.m8n8.x4.shared.b16 {%0,%1,%2,%3}, [%4];"
                 : "=r"(r[0]), "=r"(r[1]), "=r"(r[2]), "=r"(r[3]) : "r"(a));
}
__device__ __forceinline__ void ldsm4t(uint32_t a, uint32_t* r) {
    asm volatile("ldmatrix.sync.aligned.m8n8.x4.trans.shared.b16 {%0,%1,%2,%3}, [%4];"
                 : "=r"(r[0]), "=r"(r[1]), "=r"(r[2]), "=r"(r[3]) : "r"(a));
}
__device__ __forceinline__ void mmah(float* c, const uint32_t* a, const uint32_t* b) {
    asm volatile(
        "mma.sync.aligned.m16n8k16.row.col.f32.f16.f16.f32 "
        "{%0,%1,%2,%3}, {%4,%5,%6,%7}, {%8,%9}, {%0,%1,%2,%3};"
        : "+f"(c[0]), "+f"(c[1]), "+f"(c[2]), "+f"(c[3])
        : "r"(a[0]), "r"(a[1]), "r"(a[2]), "r"(a[3]), "r"(b[0]), "r"(b[1]));
}
__device__ __forceinline__ uint32_t h2pk(float a, float b) {
    __half2 t;
    t.x = __float2half_rn(a);
    t.y = __float2half_rn(b);
    return *(uint32_t*)&t;
}
__device__ __forceinline__ void cpa16(uint32_t dst, const void* src) {
    asm volatile("cp.async.cg.shared.global [%0], [%1], 16;" :: "r"(dst), "l"(src));
}
__device__ __forceinline__ void cpa16z(uint32_t dst, const void* src, uint32_t ssize) {
    asm volatile("cp.async.cg.shared.global [%0], [%1], 16, %2;" :: "r"(dst), "l"(src), "r"(ssize));
}
#define CP_COMMIT() asm volatile("cp.async.commit_group;" ::: "memory")
#define CP_WAIT(n) asm volatile("cp.async.wait_group %0;" :: "n"(n) : "memory")

// ---------------- merged prep: C rows + Q rows (+ counter reset) ----------------
__global__ void k_prep(const float* __restrict__ C, const float* __restrict__ Q,
                       const float* __restrict__ Ww, const float* __restrict__ Wb) {
    if (blockIdx.x == 0 && threadIdx.x < BB * 4) g_cnt[threadIdx.x] = 0;
    int warp = blockIdx.x * 8 + (threadIdx.x >> 5);
    int lane = threadIdx.x & 31;
    int d0 = lane * 4;
    if (warp < BB * LC) {
        const float* row = C + (size_t)warp * DD;
        float4 v1 = *(const float4*)(row + d0);
        float4 v2 = *(const float4*)(row + 128 + d0);
        float4 w1a = *(const float4*)(Ww + d0);
        float4 w1b = *(const float4*)(Ww + 128 + d0);
        float s = v1.x * w1a.x + v1.y * w1a.y + v1.z * w1a.z + v1.w * w1a.w
                + v2.x * w1b.x + v2.y * w1b.y + v2.z * w1b.z + v2.w * w1b.w;
#pragma unroll
        for (int o = 16; o; o >>= 1) s += __shfl_xor_sync(0xFFFFFFFFu, s, o);
        if (lane == 0) g_cdot[warp] = s;
        uint2 u;
        u.x = h2pk(v1.x, v1.y); u.y = h2pk(v1.z, v1.w);
        *(uint2*)(g_cbh + (size_t)warp * DD + d0) = u;
        u.x = h2pk(v2.x, v2.y); u.y = h2pk(v2.z, v2.w);
        *(uint2*)(g_cbh + (size_t)warp * DD + 128 + d0) = u;
        float4 w3a = *(const float4*)(Ww + 2 * DD + d0);
        float4 w3b = *(const float4*)(Ww + 2 * DD + 128 + d0);
        u.x = h2pk(v1.x * w3a.x, v1.y * w3a.y); u.y = h2pk(v1.z * w3a.z, v1.w * w3a.w);
        *(uint2*)(g_ch + (size_t)warp * DD + d0) = u;
        u.x = h2pk(v2.x * w3b.x, v2.y * w3b.y); u.y = h2pk(v2.z * w3b.z, v2.w * w3b.w);
        *(uint2*)(g_ch + (size_t)warp * DD + 128 + d0) = u;
    } else {
        int r = warp - BB * LC;
        const float* row = Q + (size_t)r * DD;
        float4 v1 = *(const float4*)(row + d0);
        float4 v2 = *(const float4*)(row + 128 + d0);
        float4 w2a = *(const float4*)(Ww + DD + d0);
        float4 w2b = *(const float4*)(Ww + DD + 128 + d0);
        float s = v1.x * w2a.x + v1.y * w2a.y + v1.z * w2a.z + v1.w * w2a.w
                + v2.x * w2b.x + v2.y * w2b.y + v2.z * w2b.z + v2.w * w2b.w;
#pragma unroll
        for (int o = 16; o; o >>= 1) s += __shfl_xor_sync(0xFFFFFFFFu, s, o);
        if (lane == 0) g_qdotb[r] = s + Wb[0];
        uint2 u;
        u.x = h2pk(v1.x, v1.y); u.y = h2pk(v1.z, v1.w);
        *(uint2*)(g_qh + (size_t)r * DD + d0) = u;
        u.x = h2pk(v2.x, v2.y); u.y = h2pk(v2.z, v2.w);
        *(uint2*)(g_qh + (size_t)r * DD + 128 + d0) = u;
    }
}

// ---------------- k1: 64c x 128q tiles, 256 thr, 2 CTA/SM ----------------
__global__ __launch_bounds__(256, 2) void k1_mma(const int* __restrict__ cmask,
                                                 const int* __restrict__ qmask) {
    extern __shared__ char sm[];
    const uint32_t smb = smem_u32(sm);
    float* qmf = (float*)(sm + 2 * K1PAIR);
    float* cmf = qmf + 128;
    float* rs = cmf + 64;
    float* cs = rs + 256;
    const int tid = threadIdx.x, lane = tid & 31, wid = tid >> 5;
    const int wm = wid & 1, wn = wid >> 1;
    const int b = blockIdx.y, ct = blockIdx.x, c0 = ct * 64;
    const int g = lane >> 2, tig = lane & 3;

    if (tid < 128) qmf[tid] = (float)qmask[b * LQ + tid];
    else if (tid < 192) cmf[tid - 128] = (float)cmask[b * LC + c0 + tid - 128];

    auto stage = [&](int kc, int bf) {
        uint32_t sa = smb + bf * K1PAIR, sb = sa + AT64;
        const __half* Ag = g_ch + ((size_t)(b * LC + c0)) * DD + kc * 128;
        const __half* Bg = g_qh + ((size_t)b * LQ) * DD + kc * 128;
#pragma unroll
        for (int i = 0; i < 4; i++) {
            int idx = i * 256 + tid, row = idx >> 4, cq = idx & 15;
            cpa16(sa + row * STRB + cq * 16, Ag + (size_t)row * DD + cq * 8);
        }
#pragma unroll
        for (int i = 0; i < 8; i++) {
            int idx = i * 256 + tid, row = idx >> 4, cq = idx & 15;
            cpa16(sb + row * STRB + cq * 16, Bg + (size_t)row * DD + cq * 8);
        }
        CP_COMMIT();
    };

    float acc[2][4][4];
#pragma unroll
    for (int i = 0; i < 2; i++)
#pragma unroll
        for (int j = 0; j < 4; j++)
#pragma unroll
            for (int k = 0; k < 4; k++) acc[i][j][k] = 0.f;

    stage(0, 0);
    stage(1, 1);
#pragma unroll
    for (int kc = 0; kc < 2; kc++) {
        if (kc == 0) CP_WAIT(1); else CP_WAIT(0);
        __syncthreads();
        uint32_t sA = smb + (kc & 1) * K1PAIR, sB = sA + AT64;
#pragma unroll
        for (int ks = 0; ks < 8; ks++) {
            uint32_t ah[2][4], bh[4][2];
            uint32_t aro = (uint32_t)(lane & 15) * STRB + (ks * 16 + (lane >> 4) * 8) * 2;
#pragma unroll
            for (int mf = 0; mf < 2; mf++)
                ldsm4(sA + (uint32_t)(wm * 32 + mf * 16) * STRB + aro, ah[mf]);
            uint32_t bro = (uint32_t)((lane & 7) + ((lane >> 4) * 8)) * STRB +
                           (ks * 16 + ((lane >> 3) & 1) * 8) * 2;
#pragma unroll
            for (int np = 0; np < 2; np++) {
                uint32_t r4[4];
                ldsm4(sB + (uint32_t)(wn * 32 + np * 16) * STRB + bro, r4);
                bh[np * 2][0] = r4[0]; bh[np * 2][1] = r4[1];
                bh[np * 2 + 1][0] = r4[2]; bh[np * 2 + 1][1] = r4[3];
            }
#pragma unroll
            for (int mf = 0; mf < 2; mf++)
#pragma unroll
                for (int nf = 0; nf < 4; nf++) mmah(acc[mf][nf], ah[mf], bh[nf]);
        }
    }

    float rpart[2][2] = {{0.f, 0.f}, {0.f, 0.f}};
    float cpart[4][2] = {{0.f, 0.f}, {0.f, 0.f}, {0.f, 0.f}, {0.f, 0.f}};
#pragma unroll
    for (int mf = 0; mf < 2; mf++) {
        int c = c0 + wm * 32 + mf * 16 + g;
        float cd0 = g_cdot[b * LC + c], cd1 = g_cdot[b * LC + c + 8];
        float cm0 = cmf[c - c0], cm1 = cmf[c - c0 + 8];
        size_t r0 = ((size_t)b * LC + c) * LQ, r1 = r0 + 8 * LQ;
#pragma unroll
        for (int nf = 0; nf < 4; nf++) {
            int q = wn * 32 + nf * 8 + tig * 2;
            float qd0 = g_qdotb[b * LQ + q], qd1 = g_qdotb[b * LQ + q + 1];
            float e00 = expf(acc[mf][nf][0] + cd0 + qd0);
            float e01 = expf(acc[mf][nf][1] + cd0 + qd1);
            float e10 = expf(acc[mf][nf][2] + cd1 + qd0);
            float e11 = expf(acc[mf][nf][3] + cd1 + qd1);
            *(uint32_t*)(g_eh + r0 + q) = h2pk(e00, e01);
            *(uint32_t*)(g_eh + r1 + q) = h2pk(e10, e11);
            float qm0 = qmf[q], qm1 = qmf[q + 1];
            rpart[mf][0] += e00 * qm0 + e01 * qm1;
            rpart[mf][1] += e10 * qm0 + e11 * qm1;
            cpart[nf][0] += e00 * cm0 + e10 * cm1;
            cpart[nf][1] += e01 * cm0 + e11 * cm1;
        }
    }
#pragma unroll
    for (int mf = 0; mf < 2; mf++)
#pragma unroll
        for (int rh = 0; rh < 2; rh++) {
            float v = rpart[mf][rh];
            v += __shfl_xor_sync(0xFFFFFFFFu, v, 1);
            v += __shfl_xor_sync(0xFFFFFFFFu, v, 2);
            if (tig == 0) rs[wn * 64 + wm * 32 + mf * 16 + g + rh * 8] = v;
        }
#pragma unroll
    for (int nf = 0; nf < 4; nf++)
#pragma unroll
        for (int j = 0; j < 2; j++) {
            float v = cpart[nf][j];
            v += __shfl_xor_sync(0xFFFFFFFFu, v, 4);
            v += __shfl_xor_sync(0xFFFFFFFFu, v, 8);
            v += __shfl_xor_sync(0xFFFFFFFFu, v, 16);
            if (lane < 4) cs[wid * 32 + nf * 8 + lane * 2 + j] = v;
        }
    __syncthreads();
    if (tid < 64) {
        float s = rs[tid] + rs[64 + tid] + rs[128 + tid] + rs[192 + tid];
        g_rowinv[b * LC + c0 + tid] = 1.f / s;
    } else if (tid < 192) {
        int q = tid - 64, wnq = q >> 5, ql = q & 31;
        float s = cs[(wnq * 2 + 0) * 32 + ql] + cs[(wnq * 2 + 1) * 32 + ql];
        g_colpart[(b * 16 + ct) * LQ + q] = s;
    }
}

// ---------------- k2: 128q x 64d tiles, 256 thr, 2 CTA/SM; last-block reduce -> g_th ------
__global__ __launch_bounds__(256, 2) void k2_mma(const int* __restrict__ cmask) {
    extern __shared__ char sm[];
    const uint32_t smb = smem_u32(sm);
    __shared__ int isLast;
    const int tid = threadIdx.x, lane = tid & 31, wid = tid >> 5;
    const int wm = wid & 3, wn = wid >> 2;
    const int b = blockIdx.y;
    const int dt = blockIdx.x & 3, ksp = blockIdx.x >> 2;
    const int d0 = dt * 64;
    const int g = lane >> 2, tig = lane & 3;

    auto stage = [&](int kc, int bf) {
        uint32_t sa = smb + bf * K2PAIR, sb = sa + BT128;
        int cb = ksp * 512 + kc * 128;
        const __half* Ag = g_eh + ((size_t)(b * LC + cb)) * LQ;
        const __half* Bg = g_cbh + ((size_t)(b * LC + cb)) * DD + d0;
        const int* cm = cmask + b * LC + cb;
#pragma unroll
        for (int i = 0; i < 8; i++) {
            int idx = i * 256 + tid, row = idx >> 4, cq = idx & 15;
            uint32_t ss = cm[row] ? 16u : 0u;
            cpa16z(sa + row * STRB + cq * 16, Ag + (size_t)row * LQ + cq * 8, ss);
        }
#pragma unroll
        for (int i = 0; i < 4; i++) {
            int idx = i * 256 + tid, row = idx >> 3, cq = idx & 7;
            cpa16(sb + row * STRB2 + cq * 16, Bg + (size_t)row * DD + cq * 8);
        }
        CP_COMMIT();
    };

    float acc[2][4][4];
#pragma unroll
    for (int i = 0; i < 2; i++)
#pragma unroll
        for (int j = 0; j < 4; j++)
#pragma unroll
            for (int k = 0; k < 4; k++) acc[i][j][k] = 0.f;

    stage(0, 0);
    for (int kc = 0; kc < 4; kc++) {
        if (kc + 1 < 4) {
            stage(kc + 1, (kc + 1) & 1);
            CP_WAIT(1);
        } else {
            CP_WAIT(0);
        }
        __syncthreads();
        uint32_t sA = smb + (kc & 1) * K2PAIR, sB = sA + BT128;
#pragma unroll
        for (int ks = 0; ks < 8; ks++) {
            uint32_t ah[2][4], bh[4][2];
            uint32_t aro = (uint32_t)(ks * 16 + ((lane >> 4) * 8) + (lane & 7)) * STRB +
                           (((lane >> 3) & 1) * 8) * 2;
#pragma unroll
            for (int mf = 0; mf < 2; mf++)
                ldsm4t(sA + aro + (uint32_t)(wm * 32 + mf * 16) * 2, ah[mf]);
            uint32_t bro = (uint32_t)(ks * 16 + (lane & 15)) * STRB2 + ((lane >> 4) * 8) * 2;
#pragma unroll
            for (int np = 0; np < 2; np++) {
                uint32_t r4[4];
                ldsm4t(sB + bro + (uint32_t)(wn * 32 + np * 16) * 2, r4);
                bh[np * 2][0] = r4[0]; bh[np * 2][1] = r4[1];
                bh[np * 2 + 1][0] = r4[2]; bh[np * 2 + 1][1] = r4[3];
            }
#pragma unroll
            for (int mf = 0; mf < 2; mf++)
#pragma unroll
                for (int nf = 0; nf < 4; nf++) mmah(acc[mf][nf], ah[mf], bh[nf]);
        }
        __syncthreads();
    }
    float* Tp = g_Tp + ((size_t)(b * 2 + ksp) * LQ) * DD;
#pragma unroll
    for (int mf = 0; mf < 2; mf++) {
        int q = wm * 32 + mf * 16 + g;
#pragma unroll
        for (int nf = 0; nf < 4; nf++) {
            int d = d0 + wn * 32 + nf * 8 + tig * 2;
            *(float2*)(Tp + (size_t)q * DD + d) = make_float2(acc[mf][nf][0], acc[mf][nf][1]);
            *(float2*)(Tp + (size_t)(q + 8) * DD + d) = make_float2(acc[mf][nf][2], acc[mf][nf][3]);
        }
    }

    // deterministic last-block reduction for this (b, dt)
    __threadfence();
    if (tid == 0) {
        int old = atomicAdd(&g_cnt[b * 4 + dt], 1);
        isLast = (old == 1);
    }
    __syncthreads();
    if (isLast) {
        float* civ = (float*)sm;   // reuse smem (all MMA work done)
        if (tid < 128) {
            float s = 0.f;
#pragma unroll
            for (int j = 0; j < 16; j++) s += g_colpart[(b * 16 + j) * LQ + tid];
            civ[tid] = 1.f / s;
        }
        __syncthreads();
        const float* P0 = g_Tp + ((size_t)(b * 2 + 0) * LQ) * DD + d0;
        const float* P1 = g_Tp + ((size_t)(b * 2 + 1) * LQ) * DD + d0;
        __half* To = g_th + (size_t)b * LQ * DD + d0;
        for (int i = tid; i < 128 * 16; i += 256) {
            int q = i >> 4, c4 = (i & 15) * 4;
            float4 x0 = *(const float4*)(P0 + (size_t)q * DD + c4);
            float4 x1 = *(const float4*)(P1 + (size_t)q * DD + c4);
            float ci = civ[q];
            uint2 u;
            u.x = h2pk((x0.x + x1.x) * ci, (x0.y + x1.y) * ci);
            u.y = h2pk((x0.z + x1.z) * ci, (x0.w + x1.w) * ci);
            *(uint2*)(To + (size_t)q * DD + c4) = u;
        }
    }
}

// ---------------- k3: 64c x 128d tiles, 256 thr, 2 CTA/SM; streaming stores ----------------
__global__ __launch_bounds__(256, 2) void k3_mma(const float* __restrict__ Cp,
                                                 const int* __restrict__ qmask,
                                                 float* __restrict__ out) {
    extern __shared__ char sm[];
    const uint32_t smb = smem_u32(sm);
    const uint32_t sA = smb, sBq = smb + AT64, sBt = smb + AT64 + BT128;
    const int tid = threadIdx.x, lane = tid & 31, wid = tid >> 5;
    const int wm = wid & 1, wn = wid >> 1;
    const int b = blockIdx.y;
    const int ct = blockIdx.x >> 1, dt = blockIdx.x & 1;
    const int c0 = ct * 64, d0 = dt * 128;
    const int g = lane >> 2, tig = lane & 3;

    {
        const __half* Ag = g_eh + ((size_t)(b * LC + c0)) * LQ;
        const __half* Bqg = g_qh + ((size_t)b * LQ) * DD + d0;
        const __half* Btg = g_th + ((size_t)b * LQ) * DD + d0;
        const int* qm = qmask + b * LQ;
#pragma unroll
        for (int i = 0; i < 4; i++) {
            int idx = i * 256 + tid, row = idx >> 4, cq = idx & 15;
            cpa16(sA + row * STRB + cq * 16, Ag + (size_t)row * LQ + cq * 8);
        }
#pragma unroll
        for (int i = 0; i < 8; i++) {
            int idx = i * 256 + tid, row = idx >> 4, cq = idx & 15;
            uint32_t ss = qm[row] ? 16u : 0u;
            cpa16z(sBq + row * STRB + cq * 16, Bqg + (size_t)row * DD + cq * 8, ss);
            cpa16z(sBt + row * STRB + cq * 16, Btg + (size_t)row * DD + cq * 8, ss);
        }
        CP_COMMIT();
        CP_WAIT(0);
    }
    __syncthreads();

    float accA[2][4][4], accB[2][4][4];
#pragma unroll
    for (int i = 0; i < 2; i++)
#pragma unroll
        for (int j = 0; j < 4; j++)
#pragma unroll
            for (int k = 0; k < 4; k++) { accA[i][j][k] = 0.f; accB[i][j][k] = 0.f; }

#pragma unroll
    for (int ks = 0; ks < 8; ks++) {
        uint32_t ah[2][4], bq[4][2], bt[4][2];
        uint32_t aro = (uint32_t)(lane & 15) * STRB + (ks * 16 + (lane >> 4) * 8) * 2;
#pragma unroll
        for (int mf = 0; mf < 2; mf++)
            ldsm4(sA + (uint32_t)(wm * 32 + mf * 16) * STRB + aro, ah[mf]);
        uint32_t bro = (uint32_t)(ks * 16 + (lane & 15)) * STRB + ((lane >> 4) * 8) * 2;
#pragma unroll
        for (int np = 0; np < 2; np++) {
            uint32_t r4[4];
            ldsm4t(sBq + bro + (uint32_t)(wn * 32 + np * 16) * 2, r4);
            bq[np * 2][0] = r4[0]; bq[np * 2][1] = r4[1];
            bq[np * 2 + 1][0] = r4[2]; bq[np * 2 + 1][1] = r4[3];
            ldsm4t(sBt + bro + (uint32_t)(wn * 32 + np * 16) * 2, r4);
            bt[np * 2][0] = r4[0]; bt[np * 2][1] = r4[1];
            bt[np * 2 + 1][0] = r4[2]; bt[np * 2 + 1][1] = r4[3];
        }
#pragma unroll
        for (int mf = 0; mf < 2; mf++)
#pragma unroll
            for (int nf = 0; nf < 4; nf++) {
                mmah(accA[mf][nf], ah[mf], bq[nf]);
                mmah(accB[mf][nf], ah[mf], bt[nf]);
            }
    }

#pragma unroll
    for (int mf = 0; mf < 2; mf++) {
        int c = c0 + wm * 32 + mf * 16 + g;
        float r0 = g_rowinv[b * LC + c], r1 = g_rowinv[b * LC + c + 8];
        const float* C0 = Cp + ((size_t)(b * LC + c)) * DD;
        const float* C1 = C0 + 8 * DD;
        float* o0 = out + ((size_t)(b * LC + c)) * (4 * DD);
        float* o1 = o0 + (size_t)8 * 4 * DD;
#pragma unroll
        for (int nf = 0; nf < 4; nf++) {
            int d = d0 + wn * 32 + nf * 8 + tig * 2;
            float2 cv0 = *(const float2*)(C0 + d);
            float2 cv1 = *(const float2*)(C1 + d);
            float a00 = accA[mf][nf][0] * r0, a01 = accA[mf][nf][1] * r0;
            float a10 = accA[mf][nf][2] * r1, a11 = accA[mf][nf][3] * r1;
            float b00 = accB[mf][nf][0] * r0, b01 = accB[mf][nf][1] * r0;
            float b10 = accB[mf][nf][2] * r1, b11 = accB[mf][nf][3] * r1;
            __stcs((float2*)(o0 + d), cv0);
            __stcs((float2*)(o1 + d), cv1);
            __stcs((float2*)(o0 + DD + d), make_float2(a00, a01));
            __stcs((float2*)(o1 + DD + d), make_float2(a10, a11));
            __stcs((float2*)(o0 + 2 * DD + d), make_float2(cv0.x * a00, cv0.y * a01));
            __stcs((float2*)(o1 + 2 * DD + d), make_float2(cv1.x * a10, cv1.y * a11));
            __stcs((float2*)(o0 + 3 * DD + d), make_float2(cv0.x * b00, cv0.y * b01));
            __stcs((float2*)(o1 + 3 * DD + d), make_float2(cv1.x * b10, cv1.y * b11));
        }
    }
}

extern "C" void kernel_launch(void* const* d_in, const int* in_sizes, int n_in,
                              void* d_out, int out_size) {
    const float* C = (const float*)d_in[0];
    const float* Q = (const float*)d_in[1];
    const int* cmask = (const int*)d_in[2];
    const int* qmask = (const int*)d_in[3];
    const float* Ww = (const float*)d_in[4];
    const float* Wb = (const float*)d_in[5];
    float* out = (float*)d_out;

    static bool attr_set = false;
    if (!attr_set) {
        cudaFuncSetAttribute(k1_mma, cudaFuncAttributeMaxDynamicSharedMemorySize, SM_K1);
        cudaFuncSetAttribute(k2_mma, cudaFuncAttributeMaxDynamicSharedMemorySize, SM_K2);
        cudaFuncSetAttribute(k3_mma, cudaFuncAttributeMaxDynamicSharedMemorySize, SM_K3);
        attr_set = true;
    }

    k_prep<<<4608, 256>>>(C, Q, Ww, Wb);
    k1_mma<<<dim3(16, BB), 256, SM_K1>>>(cmask, qmask);
    k2_mma<<<dim3(8, BB), 256, SM_K2>>>(cmask);
    k3_mma<<<dim3(32, BB), 256, SM_K3>>>(C, qmask, out);
}

// round 8
// speedup vs baseline: 3.7406x; 1.0801x over previous
#include <cuda_runtime.h>
#include <cuda_fp16.h>
#include <cstdint>
#include <math.h>

#define BB 32
#define LC 1024
#define LQ 128
#define DD 256
#define STRB 272                 // 128-col fp16 tile row stride (256B + 16 pad)
#define STRB2 144                // 64-col fp16 tile row stride (128B + 16 pad)
#define AT64  (64 * STRB)        // 17408 B : 64-row x 128-col tile
#define BT128 (128 * STRB)       // 34816 B : 128-row x 128-col tile
#define BT64d (128 * STRB2)      // 18432 B : 128-row x 64-col tile
#define K1PAIR (AT64 + BT128)    // 52224
#define K2PAIR (BT128 + BT64d)   // 53248
#define SM_K1 (2 * K1PAIR + 2816)
#define SM_K2 (2 * K2PAIR)
#define SM_K3 (AT64 + 2 * BT128) // 87040 (also >= 2*64*132*4 = 67584 epilogue staging)
#define EPST 132                 // epilogue smem row stride (floats)

// ---------------- scratch ----------------
__device__ float g_Tp[(size_t)BB * 2 * LQ * DD];     // k2 split-K partials (fp32)
__device__ float g_cdot[BB * LC];
__device__ float g_qdotb[BB * LQ];
__device__ float g_rowinv[BB * LC];
__device__ float g_colpart[BB * 16 * LQ];
__device__ int   g_cnt[BB * 4];
__device__ __half g_eh[(size_t)BB * LC * LQ];        // E
__device__ __half g_ch[(size_t)BB * LC * DD];        // C*w3
__device__ __half g_cbh[(size_t)BB * LC * DD];       // raw C
__device__ __half g_qh[(size_t)BB * LQ * DD];        // raw Q
__device__ __half g_th[(size_t)BB * LQ * DD];        // T

// ---------------- helpers ----------------
__device__ __forceinline__ uint32_t smem_u32(const void* p) {
    uint32_t a;
    asm("{ .reg .u64 t; cvta.to.shared.u64 t, %1; cvt.u32.u64 %0, t; }" : "=r"(a) : "l"(p));
    return a;
}
__device__ __forceinline__ void ldsm4(uint32_t a, uint32_t* r) {
    asm volatile("ldmatrix.sync.aligned.m8n8.x4.shared.b16 {%0,%1,%2,%3}, [%4];"
                 : "=r"(r[0]), "=r"(r[1]), "=r"(r[2]), "=r"(r[3]) : "r"(a));
}
__device__ __forceinline__ void ldsm4t(uint32_t a, uint32_t* r) {
    asm volatile("ldmatrix.sync.aligned.m8n8.x4.trans.shared.b16 {%0,%1,%2,%3}, [%4];"
                 : "=r"(r[0]), "=r"(r[1]), "=r"(r[2]), "=r"(r[3]) : "r"(a));
}
__device__ __forceinline__ void mmah(float* c, const uint32_t* a, const uint32_t* b) {
    asm volatile(
        "mma.sync.aligned.m16n8k16.row.col.f32.f16.f16.f32 "
        "{%0,%1,%2,%3}, {%4,%5,%6,%7}, {%8,%9}, {%0,%1,%2,%3};"
        : "+f"(c[0]), "+f"(c[1]), "+f"(c[2]), "+f"(c[3])
        : "r"(a[0]), "r"(a[1]), "r"(a[2]), "r"(a[3]), "r"(b[0]), "r"(b[1]));
}
__device__ __forceinline__ uint32_t h2pk(float a, float b) {
    __half2 t;
    t.x = __float2half_rn(a);
    t.y = __float2half_rn(b);
    return *(uint32_t*)&t;
}
__device__ __forceinline__ void cpa16(uint32_t dst, const void* src) {
    asm volatile("cp.async.cg.shared.global [%0], [%1], 16;" :: "r"(dst), "l"(src));
}
__device__ __forceinline__ void cpa16z(uint32_t dst, const void* src, uint32_t ssize) {
    asm volatile("cp.async.cg.shared.global [%0], [%1], 16, %2;" :: "r"(dst), "l"(src), "r"(ssize));
}
#define CP_COMMIT() asm volatile("cp.async.commit_group;" ::: "memory")
#define CP_WAIT(n) asm volatile("cp.async.wait_group %0;" :: "n"(n) : "memory")

// ---------------- merged prep: C rows + Q rows (+ counter reset) ----------------
__global__ void k_prep(const float* __restrict__ C, const float* __restrict__ Q,
                       const float* __restrict__ Ww, const float* __restrict__ Wb) {
    if (blockIdx.x == 0 && threadIdx.x < BB * 4) g_cnt[threadIdx.x] = 0;
    int warp = blockIdx.x * 8 + (threadIdx.x >> 5);
    int lane = threadIdx.x & 31;
    int d0 = lane * 4;
    if (warp < BB * LC) {
        const float* row = C + (size_t)warp * DD;
        float4 v1 = *(const float4*)(row + d0);
        float4 v2 = *(const float4*)(row + 128 + d0);
        float4 w1a = *(const float4*)(Ww + d0);
        float4 w1b = *(const float4*)(Ww + 128 + d0);
        float s = v1.x * w1a.x + v1.y * w1a.y + v1.z * w1a.z + v1.w * w1a.w
                + v2.x * w1b.x + v2.y * w1b.y + v2.z * w1b.z + v2.w * w1b.w;
#pragma unroll
        for (int o = 16; o; o >>= 1) s += __shfl_xor_sync(0xFFFFFFFFu, s, o);
        if (lane == 0) g_cdot[warp] = s;
        uint2 u;
        u.x = h2pk(v1.x, v1.y); u.y = h2pk(v1.z, v1.w);
        *(uint2*)(g_cbh + (size_t)warp * DD + d0) = u;
        u.x = h2pk(v2.x, v2.y); u.y = h2pk(v2.z, v2.w);
        *(uint2*)(g_cbh + (size_t)warp * DD + 128 + d0) = u;
        float4 w3a = *(const float4*)(Ww + 2 * DD + d0);
        float4 w3b = *(const float4*)(Ww + 2 * DD + 128 + d0);
        u.x = h2pk(v1.x * w3a.x, v1.y * w3a.y); u.y = h2pk(v1.z * w3a.z, v1.w * w3a.w);
        *(uint2*)(g_ch + (size_t)warp * DD + d0) = u;
        u.x = h2pk(v2.x * w3b.x, v2.y * w3b.y); u.y = h2pk(v2.z * w3b.z, v2.w * w3b.w);
        *(uint2*)(g_ch + (size_t)warp * DD + 128 + d0) = u;
    } else {
        int r = warp - BB * LC;
        const float* row = Q + (size_t)r * DD;
        float4 v1 = *(const float4*)(row + d0);
        float4 v2 = *(const float4*)(row + 128 + d0);
        float4 w2a = *(const float4*)(Ww + DD + d0);
        float4 w2b = *(const float4*)(Ww + DD + 128 + d0);
        float s = v1.x * w2a.x + v1.y * w2a.y + v1.z * w2a.z + v1.w * w2a.w
                + v2.x * w2b.x + v2.y * w2b.y + v2.z * w2b.z + v2.w * w2b.w;
#pragma unroll
        for (int o = 16; o; o >>= 1) s += __shfl_xor_sync(0xFFFFFFFFu, s, o);
        if (lane == 0) g_qdotb[r] = s + Wb[0];
        uint2 u;
        u.x = h2pk(v1.x, v1.y); u.y = h2pk(v1.z, v1.w);
        *(uint2*)(g_qh + (size_t)r * DD + d0) = u;
        u.x = h2pk(v2.x, v2.y); u.y = h2pk(v2.z, v2.w);
        *(uint2*)(g_qh + (size_t)r * DD + 128 + d0) = u;
    }
}

// ---------------- k1: 64c x 128q tiles, 256 thr, 2 CTA/SM ----------------
__global__ __launch_bounds__(256, 2) void k1_mma(const int* __restrict__ cmask,
                                                 const int* __restrict__ qmask) {
    extern __shared__ char sm[];
    const uint32_t smb = smem_u32(sm);
    float* qmf = (float*)(sm + 2 * K1PAIR);
    float* cmf = qmf + 128;
    float* rs = cmf + 64;
    float* cs = rs + 256;
    const int tid = threadIdx.x, lane = tid & 31, wid = tid >> 5;
    const int wm = wid & 1, wn = wid >> 1;
    const int b = blockIdx.y, ct = blockIdx.x, c0 = ct * 64;
    const int g = lane >> 2, tig = lane & 3;

    if (tid < 128) qmf[tid] = (float)qmask[b * LQ + tid];
    else if (tid < 192) cmf[tid - 128] = (float)cmask[b * LC + c0 + tid - 128];

    auto stage = [&](int kc, int bf) {
        uint32_t sa = smb + bf * K1PAIR, sb = sa + AT64;
        const __half* Ag = g_ch + ((size_t)(b * LC + c0)) * DD + kc * 128;
        const __half* Bg = g_qh + ((size_t)b * LQ) * DD + kc * 128;
#pragma unroll
        for (int i = 0; i < 4; i++) {
            int idx = i * 256 + tid, row = idx >> 4, cq = idx & 15;
            cpa16(sa + row * STRB + cq * 16, Ag + (size_t)row * DD + cq * 8);
        }
#pragma unroll
        for (int i = 0; i < 8; i++) {
            int idx = i * 256 + tid, row = idx >> 4, cq = idx & 15;
            cpa16(sb + row * STRB + cq * 16, Bg + (size_t)row * DD + cq * 8);
        }
        CP_COMMIT();
    };

    float acc[2][4][4];
#pragma unroll
    for (int i = 0; i < 2; i++)
#pragma unroll
        for (int j = 0; j < 4; j++)
#pragma unroll
            for (int k = 0; k < 4; k++) acc[i][j][k] = 0.f;

    stage(0, 0);
    stage(1, 1);
#pragma unroll
    for (int kc = 0; kc < 2; kc++) {
        if (kc == 0) CP_WAIT(1); else CP_WAIT(0);
        __syncthreads();
        uint32_t sA = smb + (kc & 1) * K1PAIR, sB = sA + AT64;
#pragma unroll
        for (int ks = 0; ks < 8; ks++) {
            uint32_t ah[2][4], bh[4][2];
            uint32_t aro = (uint32_t)(lane & 15) * STRB + (ks * 16 + (lane >> 4) * 8) * 2;
#pragma unroll
            for (int mf = 0; mf < 2; mf++)
                ldsm4(sA + (uint32_t)(wm * 32 + mf * 16) * STRB + aro, ah[mf]);
            uint32_t bro = (uint32_t)((lane & 7) + ((lane >> 4) * 8)) * STRB +
                           (ks * 16 + ((lane >> 3) & 1) * 8) * 2;
#pragma unroll
            for (int np = 0; np < 2; np++) {
                uint32_t r4[4];
                ldsm4(sB + (uint32_t)(wn * 32 + np * 16) * STRB + bro, r4);
                bh[np * 2][0] = r4[0]; bh[np * 2][1] = r4[1];
                bh[np * 2 + 1][0] = r4[2]; bh[np * 2 + 1][1] = r4[3];
            }
#pragma unroll
            for (int mf = 0; mf < 2; mf++)
#pragma unroll
                for (int nf = 0; nf < 4; nf++) mmah(acc[mf][nf], ah[mf], bh[nf]);
        }
    }

    float rpart[2][2] = {{0.f, 0.f}, {0.f, 0.f}};
    float cpart[4][2] = {{0.f, 0.f}, {0.f, 0.f}, {0.f, 0.f}, {0.f, 0.f}};
#pragma unroll
    for (int mf = 0; mf < 2; mf++) {
        int c = c0 + wm * 32 + mf * 16 + g;
        float cd0 = g_cdot[b * LC + c], cd1 = g_cdot[b * LC + c + 8];
        float cm0 = cmf[c - c0], cm1 = cmf[c - c0 + 8];
        size_t r0 = ((size_t)b * LC + c) * LQ, r1 = r0 + 8 * LQ;
#pragma unroll
        for (int nf = 0; nf < 4; nf++) {
            int q = wn * 32 + nf * 8 + tig * 2;
            float qd0 = g_qdotb[b * LQ + q], qd1 = g_qdotb[b * LQ + q + 1];
            float e00 = expf(acc[mf][nf][0] + cd0 + qd0);
            float e01 = expf(acc[mf][nf][1] + cd0 + qd1);
            float e10 = expf(acc[mf][nf][2] + cd1 + qd0);
            float e11 = expf(acc[mf][nf][3] + cd1 + qd1);
            *(uint32_t*)(g_eh + r0 + q) = h2pk(e00, e01);
            *(uint32_t*)(g_eh + r1 + q) = h2pk(e10, e11);
            float qm0 = qmf[q], qm1 = qmf[q + 1];
            rpart[mf][0] += e00 * qm0 + e01 * qm1;
            rpart[mf][1] += e10 * qm0 + e11 * qm1;
            cpart[nf][0] += e00 * cm0 + e10 * cm1;
            cpart[nf][1] += e01 * cm0 + e11 * cm1;
        }
    }
#pragma unroll
    for (int mf = 0; mf < 2; mf++)
#pragma unroll
        for (int rh = 0; rh < 2; rh++) {
            float v = rpart[mf][rh];
            v += __shfl_xor_sync(0xFFFFFFFFu, v, 1);
            v += __shfl_xor_sync(0xFFFFFFFFu, v, 2);
            if (tig == 0) rs[wn * 64 + wm * 32 + mf * 16 + g + rh * 8] = v;
        }
#pragma unroll
    for (int nf = 0; nf < 4; nf++)
#pragma unroll
        for (int j = 0; j < 2; j++) {
            float v = cpart[nf][j];
            v += __shfl_xor_sync(0xFFFFFFFFu, v, 4);
            v += __shfl_xor_sync(0xFFFFFFFFu, v, 8);
            v += __shfl_xor_sync(0xFFFFFFFFu, v, 16);
            if (lane < 4) cs[wid * 32 + nf * 8 + lane * 2 + j] = v;
        }
    __syncthreads();
    if (tid < 64) {
        float s = rs[tid] + rs[64 + tid] + rs[128 + tid] + rs[192 + tid];
        g_rowinv[b * LC + c0 + tid] = 1.f / s;
    } else if (tid < 192) {
        int q = tid - 64, wnq = q >> 5, ql = q & 31;
        float s = cs[(wnq * 2 + 0) * 32 + ql] + cs[(wnq * 2 + 1) * 32 + ql];
        g_colpart[(b * 16 + ct) * LQ + q] = s;
    }
}

// ---------------- k2: 128q x 64d tiles, 256 thr, 2 CTA/SM; last-block reduce -> g_th ------
__global__ __launch_bounds__(256, 2) void k2_mma(const int* __restrict__ cmask) {
    extern __shared__ char sm[];
    const uint32_t smb = smem_u32(sm);
    __shared__ int isLast;
    const int tid = threadIdx.x, lane = tid & 31, wid = tid >> 5;
    const int wm = wid & 3, wn = wid >> 2;
    const int b = blockIdx.y;
    const int dt = blockIdx.x & 3, ksp = blockIdx.x >> 2;
    const int d0 = dt * 64;
    const int g = lane >> 2, tig = lane & 3;

    auto stage = [&](int kc, int bf) {
        uint32_t sa = smb + bf * K2PAIR, sb = sa + BT128;
        int cb = ksp * 512 + kc * 128;
        const __half* Ag = g_eh + ((size_t)(b * LC + cb)) * LQ;
        const __half* Bg = g_cbh + ((size_t)(b * LC + cb)) * DD + d0;
        const int* cm = cmask + b * LC + cb;
#pragma unroll
        for (int i = 0; i < 8; i++) {
            int idx = i * 256 + tid, row = idx >> 4, cq = idx & 15;
            uint32_t ss = cm[row] ? 16u : 0u;
            cpa16z(sa + row * STRB + cq * 16, Ag + (size_t)row * LQ + cq * 8, ss);
        }
#pragma unroll
        for (int i = 0; i < 4; i++) {
            int idx = i * 256 + tid, row = idx >> 3, cq = idx & 7;
            cpa16(sb + row * STRB2 + cq * 16, Bg + (size_t)row * DD + cq * 8);
        }
        CP_COMMIT();
    };

    float acc[2][4][4];
#pragma unroll
    for (int i = 0; i < 2; i++)
#pragma unroll
        for (int j = 0; j < 4; j++)
#pragma unroll
            for (int k = 0; k < 4; k++) acc[i][j][k] = 0.f;

    stage(0, 0);
    for (int kc = 0; kc < 4; kc++) {
        if (kc + 1 < 4) {
            stage(kc + 1, (kc + 1) & 1);
            CP_WAIT(1);
        } else {
            CP_WAIT(0);
        }
        __syncthreads();
        uint32_t sA = smb + (kc & 1) * K2PAIR, sB = sA + BT128;
#pragma unroll
        for (int ks = 0; ks < 8; ks++) {
            uint32_t ah[2][4], bh[4][2];
            uint32_t aro = (uint32_t)(ks * 16 + ((lane >> 4) * 8) + (lane & 7)) * STRB +
                           (((lane >> 3) & 1) * 8) * 2;
#pragma unroll
            for (int mf = 0; mf < 2; mf++)
                ldsm4t(sA + aro + (uint32_t)(wm * 32 + mf * 16) * 2, ah[mf]);
            uint32_t bro = (uint32_t)(ks * 16 + (lane & 15)) * STRB2 + ((lane >> 4) * 8) * 2;
#pragma unroll
            for (int np = 0; np < 2; np++) {
                uint32_t r4[4];
                ldsm4t(sB + bro + (uint32_t)(wn * 32 + np * 16) * 2, r4);
                bh[np * 2][0] = r4[0]; bh[np * 2][1] = r4[1];
                bh[np * 2 + 1][0] = r4[2]; bh[np * 2 + 1][1] = r4[3];
            }
#pragma unroll
            for (int mf = 0; mf < 2; mf++)
#pragma unroll
                for (int nf = 0; nf < 4; nf++) mmah(acc[mf][nf], ah[mf], bh[nf]);
        }
        __syncthreads();
    }
    float* Tp = g_Tp + ((size_t)(b * 2 + ksp) * LQ) * DD;
#pragma unroll
    for (int mf = 0; mf < 2; mf++) {
        int q = wm * 32 + mf * 16 + g;
#pragma unroll
        for (int nf = 0; nf < 4; nf++) {
            int d = d0 + wn * 32 + nf * 8 + tig * 2;
            *(float2*)(Tp + (size_t)q * DD + d) = make_float2(acc[mf][nf][0], acc[mf][nf][1]);
            *(float2*)(Tp + (size_t)(q + 8) * DD + d) = make_float2(acc[mf][nf][2], acc[mf][nf][3]);
        }
    }

    // deterministic last-block reduction for this (b, dt)
    __threadfence();
    if (tid == 0) {
        int old = atomicAdd(&g_cnt[b * 4 + dt], 1);
        isLast = (old == 1);
    }
    __syncthreads();
    if (isLast) {
        float* civ = (float*)sm;
        if (tid < 128) {
            float s = 0.f;
#pragma unroll
            for (int j = 0; j < 16; j++) s += g_colpart[(b * 16 + j) * LQ + tid];
            civ[tid] = 1.f / s;
        }
        __syncthreads();
        const float* P0 = g_Tp + ((size_t)(b * 2 + 0) * LQ) * DD + d0;
        const float* P1 = g_Tp + ((size_t)(b * 2 + 1) * LQ) * DD + d0;
        __half* To = g_th + (size_t)b * LQ * DD + d0;
        for (int i = tid; i < 128 * 16; i += 256) {
            int q = i >> 4, c4 = (i & 15) * 4;
            float4 x0 = *(const float4*)(P0 + (size_t)q * DD + c4);
            float4 x1 = *(const float4*)(P1 + (size_t)q * DD + c4);
            float ci = civ[q];
            uint2 u;
            u.x = h2pk((x0.x + x1.x) * ci, (x0.y + x1.y) * ci);
            u.y = h2pk((x0.z + x1.z) * ci, (x0.w + x1.w) * ci);
            *(uint2*)(To + (size_t)q * DD + c4) = u;
        }
    }
}

// ---------------- k3: 64c x 128d tiles; smem-staged coalesced epilogue ----------------
__global__ __launch_bounds__(256, 2) void k3_mma(const float* __restrict__ Cp,
                                                 const int* __restrict__ qmask,
                                                 float* __restrict__ out) {
    extern __shared__ char sm[];
    const uint32_t smb = smem_u32(sm);
    const uint32_t sA = smb, sBq = smb + AT64, sBt = smb + AT64 + BT128;
    const int tid = threadIdx.x, lane = tid & 31, wid = tid >> 5;
    const int wm = wid & 1, wn = wid >> 1;
    const int b = blockIdx.y;
    const int ct = blockIdx.x >> 1, dt = blockIdx.x & 1;
    const int c0 = ct * 64, d0 = dt * 128;
    const int g = lane >> 2, tig = lane & 3;

    {
        const __half* Ag = g_eh + ((size_t)(b * LC + c0)) * LQ;
        const __half* Bqg = g_qh + ((size_t)b * LQ) * DD + d0;
        const __half* Btg = g_th + ((size_t)b * LQ) * DD + d0;
        const int* qm = qmask + b * LQ;
#pragma unroll
        for (int i = 0; i < 4; i++) {
            int idx = i * 256 + tid, row = idx >> 4, cq = idx & 15;
            cpa16(sA + row * STRB + cq * 16, Ag + (size_t)row * LQ + cq * 8);
        }
#pragma unroll
        for (int i = 0; i < 8; i++) {
            int idx = i * 256 + tid, row = idx >> 4, cq = idx & 15;
            uint32_t ss = qm[row] ? 16u : 0u;
            cpa16z(sBq + row * STRB + cq * 16, Bqg + (size_t)row * DD + cq * 8, ss);
            cpa16z(sBt + row * STRB + cq * 16, Btg + (size_t)row * DD + cq * 8, ss);
        }
        CP_COMMIT();
        CP_WAIT(0);
    }
    __syncthreads();

    float accA[2][4][4], accB[2][4][4];
#pragma unroll
    for (int i = 0; i < 2; i++)
#pragma unroll
        for (int j = 0; j < 4; j++)
#pragma unroll
            for (int k = 0; k < 4; k++) { accA[i][j][k] = 0.f; accB[i][j][k] = 0.f; }

#pragma unroll
    for (int ks = 0; ks < 8; ks++) {
        uint32_t ah[2][4], bq[4][2], bt[4][2];
        uint32_t aro = (uint32_t)(lane & 15) * STRB + (ks * 16 + (lane >> 4) * 8) * 2;
#pragma unroll
        for (int mf = 0; mf < 2; mf++)
            ldsm4(sA + (uint32_t)(wm * 32 + mf * 16) * STRB + aro, ah[mf]);
        uint32_t bro = (uint32_t)(ks * 16 + (lane & 15)) * STRB + ((lane >> 4) * 8) * 2;
#pragma unroll
        for (int np = 0; np < 2; np++) {
            uint32_t r4[4];
            ldsm4t(sBq + bro + (uint32_t)(wn * 32 + np * 16) * 2, r4);
            bq[np * 2][0] = r4[0]; bq[np * 2][1] = r4[1];
            bq[np * 2 + 1][0] = r4[2]; bq[np * 2 + 1][1] = r4[3];
            ldsm4t(sBt + bro + (uint32_t)(wn * 32 + np * 16) * 2, r4);
            bt[np * 2][0] = r4[0]; bt[np * 2][1] = r4[1];
            bt[np * 2 + 1][0] = r4[2]; bt[np * 2 + 1][1] = r4[3];
        }
#pragma unroll
        for (int mf = 0; mf < 2; mf++)
#pragma unroll
            for (int nf = 0; nf < 4; nf++) {
                mmah(accA[mf][nf], ah[mf], bq[nf]);
                mmah(accB[mf][nf], ah[mf], bt[nf]);
            }
    }

    // stage scaled accumulators to smem (reuse tile buffers; MMA reads done)
    __syncthreads();
    float* smA = (float*)sm;                 // [64][EPST]
    float* smB = smA + 64 * EPST;            // [64][EPST]
#pragma unroll
    for (int mf = 0; mf < 2; mf++) {
        int r0 = wm * 32 + mf * 16 + g;      // local row
        float ri0 = g_rowinv[b * LC + c0 + r0], ri1 = g_rowinv[b * LC + c0 + r0 + 8];
#pragma unroll
        for (int nf = 0; nf < 4; nf++) {
            int d = wn * 32 + nf * 8 + tig * 2;
            *(float2*)(smA + r0 * EPST + d) = make_float2(accA[mf][nf][0] * ri0, accA[mf][nf][1] * ri0);
            *(float2*)(smA + (r0 + 8) * EPST + d) = make_float2(accA[mf][nf][2] * ri1, accA[mf][nf][3] * ri1);
            *(float2*)(smB + r0 * EPST + d) = make_float2(accB[mf][nf][0] * ri0, accB[mf][nf][1] * ri0);
            *(float2*)(smB + (r0 + 8) * EPST + d) = make_float2(accB[mf][nf][2] * ri1, accB[mf][nf][3] * ri1);
        }
    }
    __syncthreads();

    // coalesced epilogue: warp per row-chunk, lane -> d = lane*4 (512B contiguous)
#pragma unroll
    for (int it = 0; it < 8; it++) {
        int row = it * 8 + wid;              // local c row 0..63
        int d = lane * 4;                    // 0..124
        const float* Crow = Cp + ((size_t)(b * LC + c0 + row)) * DD + d0 + d;
        float4 cv = *(const float4*)Crow;
        float4 av = *(const float4*)(smA + row * EPST + d);
        float4 bv = *(const float4*)(smB + row * EPST + d);
        float* ob = out + ((size_t)(b * LC + c0 + row)) * (4 * DD) + d0 + d;
        __stcs((float4*)(ob), cv);
        __stcs((float4*)(ob + DD), av);
        __stcs((float4*)(ob + 2 * DD), make_float4(cv.x * av.x, cv.y * av.y, cv.z * av.z, cv.w * av.w));
        __stcs((float4*)(ob + 3 * DD), make_float4(cv.x * bv.x, cv.y * bv.y, cv.z * bv.z, cv.w * bv.w));
    }
}

extern "C" void kernel_launch(void* const* d_in, const int* in_sizes, int n_in,
                              void* d_out, int out_size) {
    const float* C = (const float*)d_in[0];
    const float* Q = (const float*)d_in[1];
    const int* cmask = (const int*)d_in[2];
    const int* qmask = (const int*)d_in[3];
    const float* Ww = (const float*)d_in[4];
    const float* Wb = (const float*)d_in[5];
    float* out = (float*)d_out;

    static bool attr_set = false;
    if (!attr_set) {
        cudaFuncSetAttribute(k1_mma, cudaFuncAttributeMaxDynamicSharedMemorySize, SM_K1);
        cudaFuncSetAttribute(k2_mma, cudaFuncAttributeMaxDynamicSharedMemorySize, SM_K2);
        cudaFuncSetAttribute(k3_mma, cudaFuncAttributeMaxDynamicSharedMemorySize, SM_K3);
        attr_set = true;
    }

    k_prep<<<4608, 256>>>(C, Q, Ww, Wb);
    k1_mma<<<dim3(16, BB), 256, SM_K1>>>(cmask, qmask);
    k2_mma<<<dim3(8, BB), 256, SM_K2>>>(cmask);
    k3_mma<<<dim3(32, BB), 256, SM_K3>>>(C, qmask, out);
}

// round 9
// speedup vs baseline: 3.7590x; 1.0049x over previous
#include <cuda_runtime.h>
#include <cuda_fp16.h>
#include <cstdint>
#include <math.h>

#define BB 32
#define LC 1024
#define LQ 128
#define DD 256
#define STRB 272                 // 128-col fp16 tile row stride (256B + 16 pad)
#define STRB2 144                // 64-col fp16 tile row stride (128B + 16 pad)
#define AT64  (64 * STRB)        // 17408 B : 64-row x 128-col tile
#define BT128 (128 * STRB)       // 34816 B : 128-row x 128-col tile
#define BT64d (128 * STRB2)      // 18432 B : 128-row x 64-col tile
#define K1PAIR (AT64 + BT128)    // 52224
#define K2PAIR (BT128 + BT64d)   // 53248
#define SM_K1 (2 * K1PAIR + 2816)
#define SM_K2 (2 * K2PAIR)
#define SM_K3 (2 * BT128 + 2 * AT64)   // 104448: Bq + Bt + E(+smA) + smB annex
#define EPH 136                  // epilogue fp16 staging row stride (halves)

// ---------------- scratch ----------------
__device__ float g_Tp[(size_t)BB * 2 * LQ * DD];     // k2 split-K partials (fp32)
__device__ float g_cdot[BB * LC];
__device__ float g_qdotb[BB * LQ];
__device__ float g_rowinv[BB * LC];
__device__ float g_colpart[BB * 16 * LQ];
__device__ int   g_cnt[BB * 4];
__device__ __half g_eh[(size_t)BB * LC * LQ];        // E
__device__ __half g_cbh[(size_t)BB * LC * DD];       // raw C (k1 A, k2 B)
__device__ __half g_qh[(size_t)BB * LQ * DD];        // raw Q (k3 Bq)
__device__ __half g_qwh[(size_t)BB * LQ * DD];       // w3*Q (k1 B)
__device__ __half g_th[(size_t)BB * LQ * DD];        // T

// ---------------- helpers ----------------
__device__ __forceinline__ uint32_t smem_u32(const void* p) {
    uint32_t a;
    asm("{ .reg .u64 t; cvta.to.shared.u64 t, %1; cvt.u32.u64 %0, t; }" : "=r"(a) : "l"(p));
    return a;
}
__device__ __forceinline__ void ldsm4(uint32_t a, uint32_t* r) {
    asm volatile("ldmatrix.sync.aligned.m8n8.x4.shared.b16 {%0,%1,%2,%3}, [%4];"
                 : "=r"(r[0]), "=r"(r[1]), "=r"(r[2]), "=r"(r[3]) : "r"(a));
}
__device__ __forceinline__ void ldsm4t(uint32_t a, uint32_t* r) {
    asm volatile("ldmatrix.sync.aligned.m8n8.x4.trans.shared.b16 {%0,%1,%2,%3}, [%4];"
                 : "=r"(r[0]), "=r"(r[1]), "=r"(r[2]), "=r"(r[3]) : "r"(a));
}
__device__ __forceinline__ void mmah(float* c, const uint32_t* a, const uint32_t* b) {
    asm volatile(
        "mma.sync.aligned.m16n8k16.row.col.f32.f16.f16.f32 "
        "{%0,%1,%2,%3}, {%4,%5,%6,%7}, {%8,%9}, {%0,%1,%2,%3};"
        : "+f"(c[0]), "+f"(c[1]), "+f"(c[2]), "+f"(c[3])
        : "r"(a[0]), "r"(a[1]), "r"(a[2]), "r"(a[3]), "r"(b[0]), "r"(b[1]));
}
__device__ __forceinline__ uint32_t h2pk(float a, float b) {
    __half2 t;
    t.x = __float2half_rn(a);
    t.y = __float2half_rn(b);
    return *(uint32_t*)&t;
}
__device__ __forceinline__ void cpa16(uint32_t dst, const void* src) {
    asm volatile("cp.async.cg.shared.global [%0], [%1], 16;" :: "r"(dst), "l"(src));
}
__device__ __forceinline__ void cpa16z(uint32_t dst, const void* src, uint32_t ssize) {
    asm volatile("cp.async.cg.shared.global [%0], [%1], 16, %2;" :: "r"(dst), "l"(src), "r"(ssize));
}
#define CP_COMMIT() asm volatile("cp.async.commit_group;" ::: "memory")
#define CP_WAIT(n) asm volatile("cp.async.wait_group %0;" :: "n"(n) : "memory")

// ---------------- merged prep: C rows + Q rows (+ counter reset) ----------------
__global__ void k_prep(const float* __restrict__ C, const float* __restrict__ Q,
                       const float* __restrict__ Ww, const float* __restrict__ Wb) {
    if (blockIdx.x == 0 && threadIdx.x < BB * 4) g_cnt[threadIdx.x] = 0;
    int warp = blockIdx.x * 8 + (threadIdx.x >> 5);
    int lane = threadIdx.x & 31;
    int d0 = lane * 4;
    if (warp < BB * LC) {
        const float* row = C + (size_t)warp * DD;
        float4 v1 = *(const float4*)(row + d0);
        float4 v2 = *(const float4*)(row + 128 + d0);
        float4 w1a = *(const float4*)(Ww + d0);
        float4 w1b = *(const float4*)(Ww + 128 + d0);
        float s = v1.x * w1a.x + v1.y * w1a.y + v1.z * w1a.z + v1.w * w1a.w
                + v2.x * w1b.x + v2.y * w1b.y + v2.z * w1b.z + v2.w * w1b.w;
#pragma unroll
        for (int o = 16; o; o >>= 1) s += __shfl_xor_sync(0xFFFFFFFFu, s, o);
        if (lane == 0) g_cdot[warp] = s;
        uint2 u;
        u.x = h2pk(v1.x, v1.y); u.y = h2pk(v1.z, v1.w);
        *(uint2*)(g_cbh + (size_t)warp * DD + d0) = u;
        u.x = h2pk(v2.x, v2.y); u.y = h2pk(v2.z, v2.w);
        *(uint2*)(g_cbh + (size_t)warp * DD + 128 + d0) = u;
    } else {
        int r = warp - BB * LC;
        const float* row = Q + (size_t)r * DD;
        float4 v1 = *(const float4*)(row + d0);
        float4 v2 = *(const float4*)(row + 128 + d0);
        float4 w2a = *(const float4*)(Ww + DD + d0);
        float4 w2b = *(const float4*)(Ww + DD + 128 + d0);
        float s = v1.x * w2a.x + v1.y * w2a.y + v1.z * w2a.z + v1.w * w2a.w
                + v2.x * w2b.x + v2.y * w2b.y + v2.z * w2b.z + v2.w * w2b.w;
#pragma unroll
        for (int o = 16; o; o >>= 1) s += __shfl_xor_sync(0xFFFFFFFFu, s, o);
        if (lane == 0) g_qdotb[r] = s + Wb[0];
        uint2 u;
        u.x = h2pk(v1.x, v1.y); u.y = h2pk(v1.z, v1.w);
        *(uint2*)(g_qh + (size_t)r * DD + d0) = u;
        u.x = h2pk(v2.x, v2.y); u.y = h2pk(v2.z, v2.w);
        *(uint2*)(g_qh + (size_t)r * DD + 128 + d0) = u;
        // w3 * Q  (S = C . (w3 o Q)^T)
        float4 w3a = *(const float4*)(Ww + 2 * DD + d0);
        float4 w3b = *(const float4*)(Ww + 2 * DD + 128 + d0);
        u.x = h2pk(v1.x * w3a.x, v1.y * w3a.y); u.y = h2pk(v1.z * w3a.z, v1.w * w3a.w);
        *(uint2*)(g_qwh + (size_t)r * DD + d0) = u;
        u.x = h2pk(v2.x * w3b.x, v2.y * w3b.y); u.y = h2pk(v2.z * w3b.z, v2.w * w3b.w);
        *(uint2*)(g_qwh + (size_t)r * DD + 128 + d0) = u;
    }
}

// ---------------- k1: 64c x 128q tiles, 256 thr, 2 CTA/SM ----------------
__global__ __launch_bounds__(256, 2) void k1_mma(const int* __restrict__ cmask,
                                                 const int* __restrict__ qmask) {
    extern __shared__ char sm[];
    const uint32_t smb = smem_u32(sm);
    float* qmf = (float*)(sm + 2 * K1PAIR);
    float* cmf = qmf + 128;
    float* rs = cmf + 64;
    float* cs = rs + 256;
    const int tid = threadIdx.x, lane = tid & 31, wid = tid >> 5;
    const int wm = wid & 1, wn = wid >> 1;
    const int b = blockIdx.y, ct = blockIdx.x, c0 = ct * 64;
    const int g = lane >> 2, tig = lane & 3;

    if (tid < 128) qmf[tid] = (float)qmask[b * LQ + tid];
    else if (tid < 192) cmf[tid - 128] = (float)cmask[b * LC + c0 + tid - 128];

    auto stage = [&](int kc, int bf) {
        uint32_t sa = smb + bf * K1PAIR, sb = sa + AT64;
        const __half* Ag = g_cbh + ((size_t)(b * LC + c0)) * DD + kc * 128;
        const __half* Bg = g_qwh + ((size_t)b * LQ) * DD + kc * 128;
#pragma unroll
        for (int i = 0; i < 4; i++) {
            int idx = i * 256 + tid, row = idx >> 4, cq = idx & 15;
            cpa16(sa + row * STRB + cq * 16, Ag + (size_t)row * DD + cq * 8);
        }
#pragma unroll
        for (int i = 0; i < 8; i++) {
            int idx = i * 256 + tid, row = idx >> 4, cq = idx & 15;
            cpa16(sb + row * STRB + cq * 16, Bg + (size_t)row * DD + cq * 8);
        }
        CP_COMMIT();
    };

    float acc[2][4][4];
#pragma unroll
    for (int i = 0; i < 2; i++)
#pragma unroll
        for (int j = 0; j < 4; j++)
#pragma unroll
            for (int k = 0; k < 4; k++) acc[i][j][k] = 0.f;

    stage(0, 0);
    stage(1, 1);
#pragma unroll
    for (int kc = 0; kc < 2; kc++) {
        if (kc == 0) CP_WAIT(1); else CP_WAIT(0);
        __syncthreads();
        uint32_t sA = smb + (kc & 1) * K1PAIR, sB = sA + AT64;
#pragma unroll
        for (int ks = 0; ks < 8; ks++) {
            uint32_t ah[2][4], bh[4][2];
            uint32_t aro = (uint32_t)(lane & 15) * STRB + (ks * 16 + (lane >> 4) * 8) * 2;
#pragma unroll
            for (int mf = 0; mf < 2; mf++)
                ldsm4(sA + (uint32_t)(wm * 32 + mf * 16) * STRB + aro, ah[mf]);
            uint32_t bro = (uint32_t)((lane & 7) + ((lane >> 4) * 8)) * STRB +
                           (ks * 16 + ((lane >> 3) & 1) * 8) * 2;
#pragma unroll
            for (int np = 0; np < 2; np++) {
                uint32_t r4[4];
                ldsm4(sB + (uint32_t)(wn * 32 + np * 16) * STRB + bro, r4);
                bh[np * 2][0] = r4[0]; bh[np * 2][1] = r4[1];
                bh[np * 2 + 1][0] = r4[2]; bh[np * 2 + 1][1] = r4[3];
            }
#pragma unroll
            for (int mf = 0; mf < 2; mf++)
#pragma unroll
                for (int nf = 0; nf < 4; nf++) mmah(acc[mf][nf], ah[mf], bh[nf]);
        }
    }

    float rpart[2][2] = {{0.f, 0.f}, {0.f, 0.f}};
    float cpart[4][2] = {{0.f, 0.f}, {0.f, 0.f}, {0.f, 0.f}, {0.f, 0.f}};
#pragma unroll
    for (int mf = 0; mf < 2; mf++) {
        int c = c0 + wm * 32 + mf * 16 + g;
        float cd0 = g_cdot[b * LC + c], cd1 = g_cdot[b * LC + c + 8];
        float cm0 = cmf[c - c0], cm1 = cmf[c - c0 + 8];
        size_t r0 = ((size_t)b * LC + c) * LQ, r1 = r0 + 8 * LQ;
#pragma unroll
        for (int nf = 0; nf < 4; nf++) {
            int q = wn * 32 + nf * 8 + tig * 2;
            float qd0 = g_qdotb[b * LQ + q], qd1 = g_qdotb[b * LQ + q + 1];
            float e00 = expf(acc[mf][nf][0] + cd0 + qd0);
            float e01 = expf(acc[mf][nf][1] + cd0 + qd1);
            float e10 = expf(acc[mf][nf][2] + cd1 + qd0);
            float e11 = expf(acc[mf][nf][3] + cd1 + qd1);
            *(uint32_t*)(g_eh + r0 + q) = h2pk(e00, e01);
            *(uint32_t*)(g_eh + r1 + q) = h2pk(e10, e11);
            float qm0 = qmf[q], qm1 = qmf[q + 1];
            rpart[mf][0] += e00 * qm0 + e01 * qm1;
            rpart[mf][1] += e10 * qm0 + e11 * qm1;
            cpart[nf][0] += e00 * cm0 + e10 * cm1;
            cpart[nf][1] += e01 * cm0 + e11 * cm1;
        }
    }
#pragma unroll
    for (int mf = 0; mf < 2; mf++)
#pragma unroll
        for (int rh = 0; rh < 2; rh++) {
            float v = rpart[mf][rh];
            v += __shfl_xor_sync(0xFFFFFFFFu, v, 1);
            v += __shfl_xor_sync(0xFFFFFFFFu, v, 2);
            if (tig == 0) rs[wn * 64 + wm * 32 + mf * 16 + g + rh * 8] = v;
        }
#pragma unroll
    for (int nf = 0; nf < 4; nf++)
#pragma unroll
        for (int j = 0; j < 2; j++) {
            float v = cpart[nf][j];
            v += __shfl_xor_sync(0xFFFFFFFFu, v, 4);
            v += __shfl_xor_sync(0xFFFFFFFFu, v, 8);
            v += __shfl_xor_sync(0xFFFFFFFFu, v, 16);
            if (lane < 4) cs[wid * 32 + nf * 8 + lane * 2 + j] = v;
        }
    __syncthreads();
    if (tid < 64) {
        float s = rs[tid] + rs[64 + tid] + rs[128 + tid] + rs[192 + tid];
        g_rowinv[b * LC + c0 + tid] = 1.f / s;
    } else if (tid < 192) {
        int q = tid - 64, wnq = q >> 5, ql = q & 31;
        float s = cs[(wnq * 2 + 0) * 32 + ql] + cs[(wnq * 2 + 1) * 32 + ql];
        g_colpart[(b * 16 + ct) * LQ + q] = s;
    }
}

// ---------------- k2: 128q x 64d tiles, 256 thr, 2 CTA/SM; last-block reduce -> g_th ------
__global__ __launch_bounds__(256, 2) void k2_mma(const int* __restrict__ cmask) {
    extern __shared__ char sm[];
    const uint32_t smb = smem_u32(sm);
    __shared__ int isLast;
    const int tid = threadIdx.x, lane = tid & 31, wid = tid >> 5;
    const int wm = wid & 3, wn = wid >> 2;
    const int b = blockIdx.y;
    const int dt = blockIdx.x & 3, ksp = blockIdx.x >> 2;
    const int d0 = dt * 64;
    const int g = lane >> 2, tig = lane & 3;

    auto stage = [&](int kc, int bf) {
        uint32_t sa = smb + bf * K2PAIR, sb = sa + BT128;
        int cb = ksp * 512 + kc * 128;
        const __half* Ag = g_eh + ((size_t)(b * LC + cb)) * LQ;
        const __half* Bg = g_cbh + ((size_t)(b * LC + cb)) * DD + d0;
        const int* cm = cmask + b * LC + cb;
#pragma unroll
        for (int i = 0; i < 8; i++) {
            int idx = i * 256 + tid, row = idx >> 4, cq = idx & 15;
            uint32_t ss = cm[row] ? 16u : 0u;
            cpa16z(sa + row * STRB + cq * 16, Ag + (size_t)row * LQ + cq * 8, ss);
        }
#pragma unroll
        for (int i = 0; i < 4; i++) {
            int idx = i * 256 + tid, row = idx >> 3, cq = idx & 7;
            cpa16(sb + row * STRB2 + cq * 16, Bg + (size_t)row * DD + cq * 8);
        }
        CP_COMMIT();
    };

    float acc[2][4][4];
#pragma unroll
    for (int i = 0; i < 2; i++)
#pragma unroll
        for (int j = 0; j < 4; j++)
#pragma unroll
            for (int k = 0; k < 4; k++) acc[i][j][k] = 0.f;

    stage(0, 0);
    for (int kc = 0; kc < 4; kc++) {
        if (kc + 1 < 4) {
            stage(kc + 1, (kc + 1) & 1);
            CP_WAIT(1);
        } else {
            CP_WAIT(0);
        }
        __syncthreads();
        uint32_t sA = smb + (kc & 1) * K2PAIR, sB = sA + BT128;
#pragma unroll
        for (int ks = 0; ks < 8; ks++) {
            uint32_t ah[2][4], bh[4][2];
            uint32_t aro = (uint32_t)(ks * 16 + ((lane >> 4) * 8) + (lane & 7)) * STRB +
                           (((lane >> 3) & 1) * 8) * 2;
#pragma unroll
            for (int mf = 0; mf < 2; mf++)
                ldsm4t(sA + aro + (uint32_t)(wm * 32 + mf * 16) * 2, ah[mf]);
            uint32_t bro = (uint32_t)(ks * 16 + (lane & 15)) * STRB2 + ((lane >> 4) * 8) * 2;
#pragma unroll
            for (int np = 0; np < 2; np++) {
                uint32_t r4[4];
                ldsm4t(sB + bro + (uint32_t)(wn * 32 + np * 16) * 2, r4);
                bh[np * 2][0] = r4[0]; bh[np * 2][1] = r4[1];
                bh[np * 2 + 1][0] = r4[2]; bh[np * 2 + 1][1] = r4[3];
            }
#pragma unroll
            for (int mf = 0; mf < 2; mf++)
#pragma unroll
                for (int nf = 0; nf < 4; nf++) mmah(acc[mf][nf], ah[mf], bh[nf]);
        }
        __syncthreads();
    }
    float* Tp = g_Tp + ((size_t)(b * 2 + ksp) * LQ) * DD;
#pragma unroll
    for (int mf = 0; mf < 2; mf++) {
        int q = wm * 32 + mf * 16 + g;
#pragma unroll
        for (int nf = 0; nf < 4; nf++) {
            int d = d0 + wn * 32 + nf * 8 + tig * 2;
            *(float2*)(Tp + (size_t)q * DD + d) = make_float2(acc[mf][nf][0], acc[mf][nf][1]);
            *(float2*)(Tp + (size_t)(q + 8) * DD + d) = make_float2(acc[mf][nf][2], acc[mf][nf][3]);
        }
    }

    __threadfence();
    if (tid == 0) {
        int old = atomicAdd(&g_cnt[b * 4 + dt], 1);
        isLast = (old == 1);
    }
    __syncthreads();
    if (isLast) {
        float* civ = (float*)sm;
        if (tid < 128) {
            float s = 0.f;
#pragma unroll
            for (int j = 0; j < 16; j++) s += g_colpart[(b * 16 + j) * LQ + tid];
            civ[tid] = 1.f / s;
        }
        __syncthreads();
        const float* P0 = g_Tp + ((size_t)(b * 2 + 0) * LQ) * DD + d0;
        const float* P1 = g_Tp + ((size_t)(b * 2 + 1) * LQ) * DD + d0;
        __half* To = g_th + (size_t)b * LQ * DD + d0;
        for (int i = tid; i < 128 * 16; i += 256) {
            int q = i >> 4, c4 = (i & 15) * 4;
            float4 x0 = *(const float4*)(P0 + (size_t)q * DD + c4);
            float4 x1 = *(const float4*)(P1 + (size_t)q * DD + c4);
            float ci = civ[q];
            uint2 u;
            u.x = h2pk((x0.x + x1.x) * ci, (x0.y + x1.y) * ci);
            u.y = h2pk((x0.z + x1.z) * ci, (x0.w + x1.w) * ci);
            *(uint2*)(To + (size_t)q * DD + c4) = u;
        }
    }
}

// ---------------- k3: B-resident blocks; 4 c-tiles per block; fp16-staged epilogue --------
// grid 256: b = bx>>3, dt = (bx>>2)&1, ctg = bx&3 -> ct in [ctg*4, ctg*4+4)
__global__ __launch_bounds__(256, 2) void k3_mma(const float* __restrict__ Cp,
                                                 const int* __restrict__ qmask,
                                                 float* __restrict__ out) {
    extern __shared__ char sm[];
    const uint32_t smb = smem_u32(sm);
    const uint32_t sBq = smb, sBt = smb + BT128, sE = smb + 2 * BT128;
    char* epA = sm + 2 * BT128;                  // reuses E tile region (fp16 64xEPH)
    char* epB = sm + 2 * BT128 + AT64;           // annex (fp16 64xEPH)
    const int tid = threadIdx.x, lane = tid & 31, wid = tid >> 5;
    const int wm = wid & 1, wn = wid >> 1;
    const int bx = blockIdx.x;
    const int b = bx >> 3, dt = (bx >> 2) & 1, ctg = bx & 3;
    const int d0 = dt * 128;
    const int g = lane >> 2, tig = lane & 3;

    // stage Bq/Bt once (qmask-zeroed rows)
    {
        const __half* Bqg = g_qh + ((size_t)b * LQ) * DD + d0;
        const __half* Btg = g_th + ((size_t)b * LQ) * DD + d0;
        const int* qm = qmask + b * LQ;
#pragma unroll
        for (int i = 0; i < 8; i++) {
            int idx = i * 256 + tid, row = idx >> 4, cq = idx & 15;
            uint32_t ss = qm[row] ? 16u : 0u;
            cpa16z(sBq + row * STRB + cq * 16, Bqg + (size_t)row * DD + cq * 8, ss);
            cpa16z(sBt + row * STRB + cq * 16, Btg + (size_t)row * DD + cq * 8, ss);
        }
        CP_COMMIT();
    }

    for (int t = 0; t < 4; t++) {
        const int ct = ctg * 4 + t, c0 = ct * 64;
        // stage E tile
        {
            const __half* Ag = g_eh + ((size_t)(b * LC + c0)) * LQ;
#pragma unroll
            for (int i = 0; i < 4; i++) {
                int idx = i * 256 + tid, row = idx >> 4, cq = idx & 15;
                cpa16(sE + row * STRB + cq * 16, Ag + (size_t)row * LQ + cq * 8);
            }
            CP_COMMIT();
            CP_WAIT(0);
        }
        __syncthreads();

        float accA[2][4][4], accB[2][4][4];
#pragma unroll
        for (int i = 0; i < 2; i++)
#pragma unroll
            for (int j = 0; j < 4; j++)
#pragma unroll
                for (int k = 0; k < 4; k++) { accA[i][j][k] = 0.f; accB[i][j][k] = 0.f; }

#pragma unroll
        for (int ks = 0; ks < 8; ks++) {
            uint32_t ah[2][4], bq[4][2], bt[4][2];
            uint32_t aro = (uint32_t)(lane & 15) * STRB + (ks * 16 + (lane >> 4) * 8) * 2;
#pragma unroll
            for (int mf = 0; mf < 2; mf++)
                ldsm4(sE + (uint32_t)(wm * 32 + mf * 16) * STRB + aro, ah[mf]);
            uint32_t bro = (uint32_t)(ks * 16 + (lane & 15)) * STRB + ((lane >> 4) * 8) * 2;
#pragma unroll
            for (int np = 0; np < 2; np++) {
                uint32_t r4[4];
                ldsm4t(sBq + bro + (uint32_t)(wn * 32 + np * 16) * 2, r4);
                bq[np * 2][0] = r4[0]; bq[np * 2][1] = r4[1];
                bq[np * 2 + 1][0] = r4[2]; bq[np * 2 + 1][1] = r4[3];
                ldsm4t(sBt + bro + (uint32_t)(wn * 32 + np * 16) * 2, r4);
                bt[np * 2][0] = r4[0]; bt[np * 2][1] = r4[1];
                bt[np * 2 + 1][0] = r4[2]; bt[np * 2 + 1][1] = r4[3];
            }
#pragma unroll
            for (int mf = 0; mf < 2; mf++)
#pragma unroll
                for (int nf = 0; nf < 4; nf++) {
                    mmah(accA[mf][nf], ah[mf], bq[nf]);
                    mmah(accB[mf][nf], ah[mf], bt[nf]);
                }
        }

        // stage scaled accumulators (fp16) — epA reuses E region (E reads done)
        __syncthreads();
#pragma unroll
        for (int mf = 0; mf < 2; mf++) {
            int r0 = wm * 32 + mf * 16 + g;
            float ri0 = g_rowinv[b * LC + c0 + r0], ri1 = g_rowinv[b * LC + c0 + r0 + 8];
#pragma unroll
            for (int nf = 0; nf < 4; nf++) {
                int d = wn * 32 + nf * 8 + tig * 2;
                *(uint32_t*)(epA + (r0 * EPH + d) * 2) = h2pk(accA[mf][nf][0] * ri0, accA[mf][nf][1] * ri0);
                *(uint32_t*)(epA + ((r0 + 8) * EPH + d) * 2) = h2pk(accA[mf][nf][2] * ri1, accA[mf][nf][3] * ri1);
                *(uint32_t*)(epB + (r0 * EPH + d) * 2) = h2pk(accB[mf][nf][0] * ri0, accB[mf][nf][1] * ri0);
                *(uint32_t*)(epB + ((r0 + 8) * EPH + d) * 2) = h2pk(accB[mf][nf][2] * ri1, accB[mf][nf][3] * ri1);
            }
        }
        __syncthreads();

        // coalesced epilogue: warp per row, lane -> d = lane*4
#pragma unroll
        for (int it = 0; it < 8; it++) {
            int row = it * 8 + wid;
            int d = lane * 4;
            uint2 ua = *(uint2*)(epA + (row * EPH + d) * 2);
            uint2 ub = *(uint2*)(epB + (row * EPH + d) * 2);
            float2 a01 = __half22float2(*(__half2*)&ua.x);
            float2 a23 = __half22float2(*(__half2*)&ua.y);
            float2 b01 = __half22float2(*(__half2*)&ub.x);
            float2 b23 = __half22float2(*(__half2*)&ub.y);
            const float* Crow = Cp + ((size_t)(b * LC + c0 + row)) * DD + d0 + d;
            float4 cv = *(const float4*)Crow;
            float* ob = out + ((size_t)(b * LC + c0 + row)) * (4 * DD) + d0 + d;
            __stcs((float4*)(ob), cv);
            __stcs((float4*)(ob + DD), make_float4(a01.x, a01.y, a23.x, a23.y));
            __stcs((float4*)(ob + 2 * DD),
                   make_float4(cv.x * a01.x, cv.y * a01.y, cv.z * a23.x, cv.w * a23.y));
            __stcs((float4*)(ob + 3 * DD),
                   make_float4(cv.x * b01.x, cv.y * b01.y, cv.z * b23.x, cv.w * b23.y));
        }
        __syncthreads();   // before next E stage overwrites epA region
    }
}

extern "C" void kernel_launch(void* const* d_in, const int* in_sizes, int n_in,
                              void* d_out, int out_size) {
    const float* C = (const float*)d_in[0];
    const float* Q = (const float*)d_in[1];
    const int* cmask = (const int*)d_in[2];
    const int* qmask = (const int*)d_in[3];
    const float* Ww = (const float*)d_in[4];
    const float* Wb = (const float*)d_in[5];
    float* out = (float*)d_out;

    static bool attr_set = false;
    if (!attr_set) {
        cudaFuncSetAttribute(k1_mma, cudaFuncAttributeMaxDynamicSharedMemorySize, SM_K1);
        cudaFuncSetAttribute(k2_mma, cudaFuncAttributeMaxDynamicSharedMemorySize, SM_K2);
        cudaFuncSetAttribute(k3_mma, cudaFuncAttributeMaxDynamicSharedMemorySize, SM_K3);
        attr_set = true;
    }

    k_prep<<<4608, 256>>>(C, Q, Ww, Wb);
    k1_mma<<<dim3(16, BB), 256, SM_K1>>>(cmask, qmask);
    k2_mma<<<dim3(8, BB), 256, SM_K2>>>(cmask);
    k3_mma<<<256, 256, SM_K3>>>(C, qmask, out);
}

// round 12
// speedup vs baseline: 3.8298x; 1.0188x over previous
#include <cuda_runtime.h>
#include <cuda_fp16.h>
#include <cstdint>
#include <math.h>

#define BB 32
#define LC 1024
#define LQ 128
#define DD 256
#define STRB 272                 // 128-col fp16 tile row stride (256B + 16 pad)
#define STRB2 144                // 64-col fp16 tile row stride (128B + 16 pad)
#define AT64  (64 * STRB)        // 17408 B : 64-row x 128-col tile
#define BT128 (128 * STRB)       // 34816 B : 128-row x 128-col tile
#define BT64d (128 * STRB2)      // 18432 B : 128-row x 64-col tile
#define K1PAIR (AT64 + BT128)    // 52224
#define K2PAIR (BT128 + BT64d)   // 53248
#define SM_K1 (2 * K1PAIR + 2816)
#define SM_K2 (2 * K2PAIR)
#define SM_K3 (2 * BT128 + 2 * AT64)   // 104448: Bq + Bt + E(/epA) + epB annex
#define EPH 136                  // epilogue fp16 staging row stride (halves)

// ---------------- scratch ----------------
__device__ float g_Tp[(size_t)BB * 2 * LQ * DD];     // k2 split-K partials (fp32)
__device__ float g_cdot[BB * LC];
__device__ float g_qdotb[BB * LQ];
__device__ float g_rowinv[BB * LC];
__device__ float g_colpart[BB * 16 * LQ];
__device__ int   g_cnt[BB * 4];
__device__ __half g_eh[(size_t)BB * LC * LQ];        // E
__device__ __half g_cbh[(size_t)BB * LC * DD];       // raw C (k1 A, k2 B)
__device__ __half g_qh[(size_t)BB * LQ * DD];        // raw Q (k3 Bq)
__device__ __half g_qwh[(size_t)BB * LQ * DD];       // w3*Q (k1 B)
__device__ __half g_th[(size_t)BB * LQ * DD];        // T

// ---------------- helpers ----------------
__device__ __forceinline__ uint32_t smem_u32(const void* p) {
    uint32_t a;
    asm("{ .reg .u64 t; cvta.to.shared.u64 t, %1; cvt.u32.u64 %0, t; }" : "=r"(a) : "l"(p));
    return a;
}
__device__ __forceinline__ void ldsm4(uint32_t a, uint32_t* r) {
    asm volatile("ldmatrix.sync.aligned.m8n8.x4.shared.b16 {%0,%1,%2,%3}, [%4];"
                 : "=r"(r[0]), "=r"(r[1]), "=r"(r[2]), "=r"(r[3]) : "r"(a));
}
__device__ __forceinline__ void ldsm4t(uint32_t a, uint32_t* r) {
    asm volatile("ldmatrix.sync.aligned.m8n8.x4.trans.shared.b16 {%0,%1,%2,%3}, [%4];"
                 : "=r"(r[0]), "=r"(r[1]), "=r"(r[2]), "=r"(r[3]) : "r"(a));
}
__device__ __forceinline__ void mmah(float* c, const uint32_t* a, const uint32_t* b) {
    asm volatile(
        "mma.sync.aligned.m16n8k16.row.col.f32.f16.f16.f32 "
        "{%0,%1,%2,%3}, {%4,%5,%6,%7}, {%8,%9}, {%0,%1,%2,%3};"
        : "+f"(c[0]), "+f"(c[1]), "+f"(c[2]), "+f"(c[3])
        : "r"(a[0]), "r"(a[1]), "r"(a[2]), "r"(a[3]), "r"(b[0]), "r"(b[1]));
}
__device__ __forceinline__ uint32_t h2pk(float a, float b) {
    __half2 t;
    t.x = __float2half_rn(a);
    t.y = __float2half_rn(b);
    return *(uint32_t*)&t;
}
__device__ __forceinline__ void cpa16(uint32_t dst, const void* src) {
    asm volatile("cp.async.cg.shared.global [%0], [%1], 16;" :: "r"(dst), "l"(src));
}
__device__ __forceinline__ void cpa16z(uint32_t dst, const void* src, uint32_t ssize) {
    asm volatile("cp.async.cg.shared.global [%0], [%1], 16, %2;" :: "r"(dst), "l"(src), "r"(ssize));
}
#define CP_COMMIT() asm volatile("cp.async.commit_group;" ::: "memory")
#define CP_WAIT(n) asm volatile("cp.async.wait_group %0;" :: "n"(n) : "memory")

// ---------------- merged prep: C rows + Q rows (+ counter reset) ----------------
__global__ void k_prep(const float* __restrict__ C, const float* __restrict__ Q,
                       const float* __restrict__ Ww, const float* __restrict__ Wb) {
    if (blockIdx.x == 0 && threadIdx.x < BB * 4) g_cnt[threadIdx.x] = 0;
    int warp = blockIdx.x * 8 + (threadIdx.x >> 5);
    int lane = threadIdx.x & 31;
    int d0 = lane * 4;
    if (warp < BB * LC) {
        const float* row = C + (size_t)warp * DD;
        float4 v1 = *(const float4*)(row + d0);
        float4 v2 = *(const float4*)(row + 128 + d0);
        float4 w1a = *(const float4*)(Ww + d0);
        float4 w1b = *(const float4*)(Ww + 128 + d0);
        float s = v1.x * w1a.x + v1.y * w1a.y + v1.z * w1a.z + v1.w * w1a.w
                + v2.x * w1b.x + v2.y * w1b.y + v2.z * w1b.z + v2.w * w1b.w;
#pragma unroll
        for (int o = 16; o; o >>= 1) s += __shfl_xor_sync(0xFFFFFFFFu, s, o);
        if (lane == 0) g_cdot[warp] = s;
        uint2 u;
        u.x = h2pk(v1.x, v1.y); u.y = h2pk(v1.z, v1.w);
        *(uint2*)(g_cbh + (size_t)warp * DD + d0) = u;
        u.x = h2pk(v2.x, v2.y); u.y = h2pk(v2.z, v2.w);
        *(uint2*)(g_cbh + (size_t)warp * DD + 128 + d0) = u;
    } else {
        int r = warp - BB * LC;
        const float* row = Q + (size_t)r * DD;
        float4 v1 = *(const float4*)(row + d0);
        float4 v2 = *(const float4*)(row + 128 + d0);
        float4 w2a = *(const float4*)(Ww + DD + d0);
        float4 w2b = *(const float4*)(Ww + DD + 128 + d0);
        float s = v1.x * w2a.x + v1.y * w2a.y + v1.z * w2a.z + v1.w * w2a.w
                + v2.x * w2b.x + v2.y * w2b.y + v2.z * w2b.z + v2.w * w2b.w;
#pragma unroll
        for (int o = 16; o; o >>= 1) s += __shfl_xor_sync(0xFFFFFFFFu, s, o);
        if (lane == 0) g_qdotb[r] = s + Wb[0];
        uint2 u;
        u.x = h2pk(v1.x, v1.y); u.y = h2pk(v1.z, v1.w);
        *(uint2*)(g_qh + (size_t)r * DD + d0) = u;
        u.x = h2pk(v2.x, v2.y); u.y = h2pk(v2.z, v2.w);
        *(uint2*)(g_qh + (size_t)r * DD + 128 + d0) = u;
        float4 w3a = *(const float4*)(Ww + 2 * DD + d0);
        float4 w3b = *(const float4*)(Ww + 2 * DD + 128 + d0);
        u.x = h2pk(v1.x * w3a.x, v1.y * w3a.y); u.y = h2pk(v1.z * w3a.z, v1.w * w3a.w);
        *(uint2*)(g_qwh + (size_t)r * DD + d0) = u;
        u.x = h2pk(v2.x * w3b.x, v2.y * w3b.y); u.y = h2pk(v2.z * w3b.z, v2.w * w3b.w);
        *(uint2*)(g_qwh + (size_t)r * DD + 128 + d0) = u;
    }
}

// ---------------- k1: 64c x 128q tiles, 256 thr, 2 CTA/SM ----------------
__global__ __launch_bounds__(256, 2) void k1_mma(const int* __restrict__ cmask,
                                                 const int* __restrict__ qmask) {
    extern __shared__ char sm[];
    const uint32_t smb = smem_u32(sm);
    float* qmf = (float*)(sm + 2 * K1PAIR);
    float* cmf = qmf + 128;
    float* rs = cmf + 64;
    float* cs = rs + 256;
    const int tid = threadIdx.x, lane = tid & 31, wid = tid >> 5;
    const int wm = wid & 1, wn = wid >> 1;
    const int b = blockIdx.y, ct = blockIdx.x, c0 = ct * 64;
    const int g = lane >> 2, tig = lane & 3;

    if (tid < 128) qmf[tid] = (float)qmask[b * LQ + tid];
    else if (tid < 192) cmf[tid - 128] = (float)cmask[b * LC + c0 + tid - 128];

    auto stage = [&](int kc, int bf) {
        uint32_t sa = smb + bf * K1PAIR, sb = sa + AT64;
        const __half* Ag = g_cbh + ((size_t)(b * LC + c0)) * DD + kc * 128;
        const __half* Bg = g_qwh + ((size_t)b * LQ) * DD + kc * 128;
#pragma unroll
        for (int i = 0; i < 4; i++) {
            int idx = i * 256 + tid, row = idx >> 4, cq = idx & 15;
            cpa16(sa + row * STRB + cq * 16, Ag + (size_t)row * DD + cq * 8);
        }
#pragma unroll
        for (int i = 0; i < 8; i++) {
            int idx = i * 256 + tid, row = idx >> 4, cq = idx & 15;
            cpa16(sb + row * STRB + cq * 16, Bg + (size_t)row * DD + cq * 8);
        }
        CP_COMMIT();
    };

    float acc[2][4][4];
#pragma unroll
    for (int i = 0; i < 2; i++)
#pragma unroll
        for (int j = 0; j < 4; j++)
#pragma unroll
            for (int k = 0; k < 4; k++) acc[i][j][k] = 0.f;

    stage(0, 0);
    stage(1, 1);
#pragma unroll
    for (int kc = 0; kc < 2; kc++) {
        if (kc == 0) CP_WAIT(1); else CP_WAIT(0);
        __syncthreads();
        uint32_t sA = smb + (kc & 1) * K1PAIR, sB = sA + AT64;
#pragma unroll
        for (int ks = 0; ks < 8; ks++) {
            uint32_t ah[2][4], bh[4][2];
            uint32_t aro = (uint32_t)(lane & 15) * STRB + (ks * 16 + (lane >> 4) * 8) * 2;
#pragma unroll
            for (int mf = 0; mf < 2; mf++)
                ldsm4(sA + (uint32_t)(wm * 32 + mf * 16) * STRB + aro, ah[mf]);
            uint32_t bro = (uint32_t)((lane & 7) + ((lane >> 4) * 8)) * STRB +
                           (ks * 16 + ((lane >> 3) & 1) * 8) * 2;
#pragma unroll
            for (int np = 0; np < 2; np++) {
                uint32_t r4[4];
                ldsm4(sB + (uint32_t)(wn * 32 + np * 16) * STRB + bro, r4);
                bh[np * 2][0] = r4[0]; bh[np * 2][1] = r4[1];
                bh[np * 2 + 1][0] = r4[2]; bh[np * 2 + 1][1] = r4[3];
            }
#pragma unroll
            for (int mf = 0; mf < 2; mf++)
#pragma unroll
                for (int nf = 0; nf < 4; nf++) mmah(acc[mf][nf], ah[mf], bh[nf]);
        }
    }

    float rpart[2][2] = {{0.f, 0.f}, {0.f, 0.f}};
    float cpart[4][2] = {{0.f, 0.f}, {0.f, 0.f}, {0.f, 0.f}, {0.f, 0.f}};
#pragma unroll
    for (int mf = 0; mf < 2; mf++) {
        int c = c0 + wm * 32 + mf * 16 + g;
        float cd0 = g_cdot[b * LC + c], cd1 = g_cdot[b * LC + c + 8];
        float cm0 = cmf[c - c0], cm1 = cmf[c - c0 + 8];
        size_t r0 = ((size_t)b * LC + c) * LQ, r1 = r0 + 8 * LQ;
#pragma unroll
        for (int nf = 0; nf < 4; nf++) {
            int q = wn * 32 + nf * 8 + tig * 2;
            float qd0 = g_qdotb[b * LQ + q], qd1 = g_qdotb[b * LQ + q + 1];
            float e00 = expf(acc[mf][nf][0] + cd0 + qd0);
            float e01 = expf(acc[mf][nf][1] + cd0 + qd1);
            float e10 = expf(acc[mf][nf][2] + cd1 + qd0);
            float e11 = expf(acc[mf][nf][3] + cd1 + qd1);
            *(uint32_t*)(g_eh + r0 + q) = h2pk(e00, e01);
            *(uint32_t*)(g_eh + r1 + q) = h2pk(e10, e11);
            float qm0 = qmf[q], qm1 = qmf[q + 1];
            rpart[mf][0] += e00 * qm0 + e01 * qm1;
            rpart[mf][1] += e10 * qm0 + e11 * qm1;
            cpart[nf][0] += e00 * cm0 + e10 * cm1;
            cpart[nf][1] += e01 * cm0 + e11 * cm1;
        }
    }
#pragma unroll
    for (int mf = 0; mf < 2; mf++)
#pragma unroll
        for (int rh = 0; rh < 2; rh++) {
            float v = rpart[mf][rh];
            v += __shfl_xor_sync(0xFFFFFFFFu, v, 1);
            v += __shfl_xor_sync(0xFFFFFFFFu, v, 2);
            if (tig == 0) rs[wn * 64 + wm * 32 + mf * 16 + g + rh * 8] = v;
        }
#pragma unroll
    for (int nf = 0; nf < 4; nf++)
#pragma unroll
        for (int j = 0; j < 2; j++) {
            float v = cpart[nf][j];
            v += __shfl_xor_sync(0xFFFFFFFFu, v, 4);
            v += __shfl_xor_sync(0xFFFFFFFFu, v, 8);
            v += __shfl_xor_sync(0xFFFFFFFFu, v, 16);
            if (lane < 4) cs[wid * 32 + nf * 8 + lane * 2 + j] = v;
        }
    __syncthreads();
    if (tid < 64) {
        float s = rs[tid] + rs[64 + tid] + rs[128 + tid] + rs[192 + tid];
        g_rowinv[b * LC + c0 + tid] = 1.f / s;
    } else if (tid < 192) {
        int q = tid - 64, wnq = q >> 5, ql = q & 31;
        float s = cs[(wnq * 2 + 0) * 32 + ql] + cs[(wnq * 2 + 1) * 32 + ql];
        g_colpart[(b * 16 + ct) * LQ + q] = s;
    }
}

// ---------------- k2: 128q x 64d tiles, 256 thr, 2 CTA/SM; last-block reduce -> g_th ------
__global__ __launch_bounds__(256, 2) void k2_mma(const int* __restrict__ cmask) {
    extern __shared__ char sm[];
    const uint32_t smb = smem_u32(sm);
    __shared__ int isLast;
    const int tid = threadIdx.x, lane = tid & 31, wid = tid >> 5;
    const int wm = wid & 3, wn = wid >> 2;
    const int b = blockIdx.y;
    const int dt = blockIdx.x & 3, ksp = blockIdx.x >> 2;
    const int d0 = dt * 64;
    const int g = lane >> 2, tig = lane & 3;

    auto stage = [&](int kc, int bf) {
        uint32_t sa = smb + bf * K2PAIR, sb = sa + BT128;
        int cb = ksp * 512 + kc * 128;
        const __half* Ag = g_eh + ((size_t)(b * LC + cb)) * LQ;
        const __half* Bg = g_cbh + ((size_t)(b * LC + cb)) * DD + d0;
        const int* cm = cmask + b * LC + cb;
#pragma unroll
        for (int i = 0; i < 8; i++) {
            int idx = i * 256 + tid, row = idx >> 4, cq = idx & 15;
            uint32_t ss = cm[row] ? 16u : 0u;
            cpa16z(sa + row * STRB + cq * 16, Ag + (size_t)row * LQ + cq * 8, ss);
        }
#pragma unroll
        for (int i = 0; i < 4; i++) {
            int idx = i * 256 + tid, row = idx >> 3, cq = idx & 7;
            cpa16(sb + row * STRB2 + cq * 16, Bg + (size_t)row * DD + cq * 8);
        }
        CP_COMMIT();
    };

    float acc[2][4][4];
#pragma unroll
    for (int i = 0; i < 2; i++)
#pragma unroll
        for (int j = 0; j < 4; j++)
#pragma unroll
            for (int k = 0; k < 4; k++) acc[i][j][k] = 0.f;

    stage(0, 0);
    for (int kc = 0; kc < 4; kc++) {
        if (kc + 1 < 4) {
            stage(kc + 1, (kc + 1) & 1);
            CP_WAIT(1);
        } else {
            CP_WAIT(0);
        }
        __syncthreads();
        uint32_t sA = smb + (kc & 1) * K2PAIR, sB = sA + BT128;
#pragma unroll
        for (int ks = 0; ks < 8; ks++) {
            uint32_t ah[2][4], bh[4][2];
            uint32_t aro = (uint32_t)(ks * 16 + ((lane >> 4) * 8) + (lane & 7)) * STRB +
                           (((lane >> 3) & 1) * 8) * 2;
#pragma unroll
            for (int mf = 0; mf < 2; mf++)
                ldsm4t(sA + aro + (uint32_t)(wm * 32 + mf * 16) * 2, ah[mf]);
            uint32_t bro = (uint32_t)(ks * 16 + (lane & 15)) * STRB2 + ((lane >> 4) * 8) * 2;
#pragma unroll
            for (int np = 0; np < 2; np++) {
                uint32_t r4[4];
                ldsm4t(sB + bro + (uint32_t)(wn * 32 + np * 16) * 2, r4);
                bh[np * 2][0] = r4[0]; bh[np * 2][1] = r4[1];
                bh[np * 2 + 1][0] = r4[2]; bh[np * 2 + 1][1] = r4[3];
            }
#pragma unroll
            for (int mf = 0; mf < 2; mf++)
#pragma unroll
                for (int nf = 0; nf < 4; nf++) mmah(acc[mf][nf], ah[mf], bh[nf]);
        }
        __syncthreads();
    }
    float* Tp = g_Tp + ((size_t)(b * 2 + ksp) * LQ) * DD;
#pragma unroll
    for (int mf = 0; mf < 2; mf++) {
        int q = wm * 32 + mf * 16 + g;
#pragma unroll
        for (int nf = 0; nf < 4; nf++) {
            int d = d0 + wn * 32 + nf * 8 + tig * 2;
            *(float2*)(Tp + (size_t)q * DD + d) = make_float2(acc[mf][nf][0], acc[mf][nf][1]);
            *(float2*)(Tp + (size_t)(q + 8) * DD + d) = make_float2(acc[mf][nf][2], acc[mf][nf][3]);
        }
    }

    __threadfence();
    if (tid == 0) {
        int old = atomicAdd(&g_cnt[b * 4 + dt], 1);
        isLast = (old == 1);
    }
    __syncthreads();
    if (isLast) {
        float* civ = (float*)sm;
        if (tid < 128) {
            float s = 0.f;
#pragma unroll
            for (int j = 0; j < 16; j++) s += g_colpart[(b * 16 + j) * LQ + tid];
            civ[tid] = 1.f / s;
        }
        __syncthreads();
        const float* P0 = g_Tp + ((size_t)(b * 2 + 0) * LQ) * DD + d0;
        const float* P1 = g_Tp + ((size_t)(b * 2 + 1) * LQ) * DD + d0;
        __half* To = g_th + (size_t)b * LQ * DD + d0;
        for (int i = tid; i < 128 * 16; i += 256) {
            int q = i >> 4, c4 = (i & 15) * 4;
            float4 x0 = __ldcs((const float4*)(P0 + (size_t)q * DD + c4));
            float4 x1 = __ldcs((const float4*)(P1 + (size_t)q * DD + c4));
            float ci = civ[q];
            uint2 u;
            u.x = h2pk((x0.x + x1.x) * ci, (x0.y + x1.y) * ci);
            u.y = h2pk((x0.z + x1.z) * ci, (x0.w + x1.w) * ci);
            *(uint2*)(To + (size_t)q * DD + c4) = u;
        }
    }
}

// ---------------- k3: B-resident; pipelined E prefetch + C register prefetch ----------------
// grid 256: b = bx>>3, dt = (bx>>2)&1, ctg = bx&3 -> ct in [ctg*4, ctg*4+4)
__global__ __launch_bounds__(256, 2) void k3_mma(const float* __restrict__ Cp,
                                                 const int* __restrict__ qmask,
                                                 float* __restrict__ out) {
    extern __shared__ char sm[];
    const uint32_t smb = smem_u32(sm);
    const uint32_t sBq = smb, sBt = smb + BT128, sE = smb + 2 * BT128;
    char* epA = sm + 2 * BT128;                  // reuses E tile region (fp16 64xEPH)
    char* epB = sm + 2 * BT128 + AT64;           // annex (fp16 64xEPH)
    const int tid = threadIdx.x, lane = tid & 31, wid = tid >> 5;
    const int wm = wid & 1, wn = wid >> 1;
    const int bx = blockIdx.x;
    const int b = bx >> 3, dt = (bx >> 2) & 1, ctg = bx & 3;
    const int d0 = dt * 128;
    const int g = lane >> 2, tig = lane & 3;

    auto stageE = [&](int ct) {
        const __half* Ag = g_eh + ((size_t)(b * LC + ct * 64)) * LQ;
#pragma unroll
        for (int i = 0; i < 4; i++) {
            int idx = i * 256 + tid, row = idx >> 4, cq = idx & 15;
            cpa16(sE + row * STRB + cq * 16, Ag + (size_t)row * LQ + cq * 8);
        }
        CP_COMMIT();
    };

    // stage Bq/Bt once (qmask-zeroed rows) + first E tile
    {
        const __half* Bqg = g_qh + ((size_t)b * LQ) * DD + d0;
        const __half* Btg = g_th + ((size_t)b * LQ) * DD + d0;
        const int* qm = qmask + b * LQ;
#pragma unroll
        for (int i = 0; i < 8; i++) {
            int idx = i * 256 + tid, row = idx >> 4, cq = idx & 15;
            uint32_t ss = qm[row] ? 16u : 0u;
            cpa16z(sBq + row * STRB + cq * 16, Bqg + (size_t)row * DD + cq * 8, ss);
            cpa16z(sBt + row * STRB + cq * 16, Btg + (size_t)row * DD + cq * 8, ss);
        }
        CP_COMMIT();
        stageE(ctg * 4);
    }

    for (int t = 0; t < 4; t++) {
        const int ct = ctg * 4 + t, c0 = ct * 64;
        CP_WAIT(0);
        __syncthreads();

        float accA[2][4][4], accB[2][4][4];
#pragma unroll
        for (int i = 0; i < 2; i++)
#pragma unroll
            for (int j = 0; j < 4; j++)
#pragma unroll
                for (int k = 0; k < 4; k++) { accA[i][j][k] = 0.f; accB[i][j][k] = 0.f; }

#pragma unroll
        for (int ks = 0; ks < 8; ks++) {
            uint32_t ah[2][4], bq[4][2], bt[4][2];
            uint32_t aro = (uint32_t)(lane & 15) * STRB + (ks * 16 + (lane >> 4) * 8) * 2;
#pragma unroll
            for (int mf = 0; mf < 2; mf++)
                ldsm4(sE + (uint32_t)(wm * 32 + mf * 16) * STRB + aro, ah[mf]);
            uint32_t bro = (uint32_t)(ks * 16 + (lane & 15)) * STRB + ((lane >> 4) * 8) * 2;
#pragma unroll
            for (int np = 0; np < 2; np++) {
                uint32_t r4[4];
                ldsm4t(sBq + bro + (uint32_t)(wn * 32 + np * 16) * 2, r4);
                bq[np * 2][0] = r4[0]; bq[np * 2][1] = r4[1];
                bq[np * 2 + 1][0] = r4[2]; bq[np * 2 + 1][1] = r4[3];
                ldsm4t(sBt + bro + (uint32_t)(wn * 32 + np * 16) * 2, r4);
                bt[np * 2][0] = r4[0]; bt[np * 2][1] = r4[1];
                bt[np * 2 + 1][0] = r4[2]; bt[np * 2 + 1][1] = r4[3];
            }
#pragma unroll
            for (int mf = 0; mf < 2; mf++)
#pragma unroll
                for (int nf = 0; nf < 4; nf++) {
                    mmah(accA[mf][nf], ah[mf], bq[nf]);
                    mmah(accB[mf][nf], ah[mf], bt[nf]);
                }
        }

        // stage scaled accumulators (fp16) — epA reuses E region (E reads done)
        __syncthreads();
#pragma unroll
        for (int mf = 0; mf < 2; mf++) {
            int r0 = wm * 32 + mf * 16 + g;
            float ri0 = g_rowinv[b * LC + c0 + r0], ri1 = g_rowinv[b * LC + c0 + r0 + 8];
#pragma unroll
            for (int nf = 0; nf < 4; nf++) {
                int d = wn * 32 + nf * 8 + tig * 2;
                *(uint32_t*)(epA + (r0 * EPH + d) * 2) = h2pk(accA[mf][nf][0] * ri0, accA[mf][nf][1] * ri0);
                *(uint32_t*)(epA + ((r0 + 8) * EPH + d) * 2) = h2pk(accA[mf][nf][2] * ri1, accA[mf][nf][3] * ri1);
                *(uint32_t*)(epB + (r0 * EPH + d) * 2) = h2pk(accB[mf][nf][0] * ri0, accB[mf][nf][1] * ri0);
                *(uint32_t*)(epB + ((r0 + 8) * EPH + d) * 2) = h2pk(accB[mf][nf][2] * ri1, accB[mf][nf][3] * ri1);
            }
        }

        // prefetch C rows for this warp (accumulators are dead; latency hides under sync)
        float4 cpre[8];
#pragma unroll
        for (int it = 0; it < 8; it++) {
            int row = it * 8 + wid;
            cpre[it] = __ldcs((const float4*)(Cp + ((size_t)(b * LC + c0 + row)) * DD + d0 + lane * 4));
        }
        __syncthreads();

        // seg0/1/2 stores (read epA)
#pragma unroll
        for (int it = 0; it < 8; it++) {
            int row = it * 8 + wid;
            int d = lane * 4;
            uint2 ua = *(uint2*)(epA + (row * EPH + d) * 2);
            float2 a01 = __half22float2(*(__half2*)&ua.x);
            float2 a23 = __half22float2(*(__half2*)&ua.y);
            float4 cv = cpre[it];
            float* ob = out + ((size_t)(b * LC + c0 + row)) * (4 * DD) + d0 + d;
            __stcs((float4*)(ob), cv);
            __stcs((float4*)(ob + DD), make_float4(a01.x, a01.y, a23.x, a23.y));
            __stcs((float4*)(ob + 2 * DD),
                   make_float4(cv.x * a01.x, cv.y * a01.y, cv.z * a23.x, cv.w * a23.y));
        }
        __syncthreads();   // epA reads done -> E region free for prefetch

        if (t + 1 < 4) stageE(ct + 1);   // overlap with seg3 stores below

        // seg3 stores (read epB annex — untouched by E prefetch)
#pragma unroll
        for (int it = 0; it < 8; it++) {
            int row = it * 8 + wid;
            int d = lane * 4;
            uint2 ub = *(uint2*)(epB + (row * EPH + d) * 2);
            float2 b01 = __half22float2(*(__half2*)&ub.x);
            float2 b23 = __half22float2(*(__half2*)&ub.y);
            float4 cv = cpre[it];
            float* ob = out + ((size_t)(b * LC + c0 + row)) * (4 * DD) + d0 + d;
            __stcs((float4*)(ob + 3 * DD),
                   make_float4(cv.x * b01.x, cv.y * b01.y, cv.z * b23.x, cv.w * b23.y));
        }
    }
}

extern "C" void kernel_launch(void* const* d_in, const int* in_sizes, int n_in,
                              void* d_out, int out_size) {
    const float* C = (const float*)d_in[0];
    const float* Q = (const float*)d_in[1];
    const int* cmask = (const int*)d_in[2];
    const int* qmask = (const int*)d_in[3];
    const float* Ww = (const float*)d_in[4];
    const float* Wb = (const float*)d_in[5];
    float* out = (float*)d_out;

    static bool attr_set = false;
    if (!attr_set) {
        cudaFuncSetAttribute(k1_mma, cudaFuncAttributeMaxDynamicSharedMemorySize, SM_K1);
        cudaFuncSetAttribute(k2_mma, cudaFuncAttributeMaxDynamicSharedMemorySize, SM_K2);
        cudaFuncSetAttribute(k3_mma, cudaFuncAttributeMaxDynamicSharedMemorySize, SM_K3);
        attr_set = true;
    }

    k_prep<<<4608, 256>>>(C, Q, Ww, Wb);
    k1_mma<<<dim3(16, BB), 256, SM_K1>>>(cmask, qmask);
    k2_mma<<<dim3(8, BB), 256, SM_K2>>>(cmask);
    k3_mma<<<256, 256, SM_K3>>>(C, qmask, out);
}